// round 2
// baseline (speedup 1.0000x reference)
#include <cuda_runtime.h>
#include <cstdint>
#include <cstddef>

typedef unsigned long long ull;

// device scratch (allocs forbidden)
__device__ float g_qh[64 * 1024];
__device__ float g_ws[64 * 1024 * 16];      // [b][d][h]
__device__ float g_scores[64 * 16 * 2048];  // [b][h][s]
__device__ float g_attn[64 * 2048 * 16];    // [b][s][h]
__device__ float g_vbar[64 * 16 * 1024];    // [b][h][d]
__device__ float g_concat[64 * 1024];
__device__ float g_outpre[64 * 1024];

__device__ __forceinline__ ull pk2(float x, float y) {
    ull r; asm("mov.b64 %0, {%1,%2};" : "=l"(r) : "f"(x), "f"(y)); return r;
}
__device__ __forceinline__ void upk2(float& x, float& y, ull v) {
    asm("mov.b64 {%0,%1}, %2;" : "=f"(x), "=f"(y) : "l"(v));
}
__device__ __forceinline__ ull fma2(ull a, ull b, ull c) {
    ull d; asm("fma.rn.f32x2 %0, %1, %2, %3;" : "=l"(d) : "l"(a), "l"(b), "l"(c)); return d;
}

__global__ __launch_bounds__(256) void k_init(const float* __restrict__ bq,
                                              const float* __restrict__ bv,
                                              const float* __restrict__ bo) {
    int i = blockIdx.x * 256 + threadIdx.x;
    int c = i & 1023;
    g_qh[i] = bq[c]; g_concat[i] = bv[c]; g_outpre[i] = bo[c];
}

// C[64,1024] += A[64,1024] @ W[1024,1024]; k-split over blockIdx.y (8x128), 64-col tiles over x.
// mode 0: A=q -> g_qh | mode 1: A=g_vbar head-sliced -> g_concat | mode 2: A=g_concat -> g_outpre
__global__ __launch_bounds__(256) void gemm_ksplit(const float* __restrict__ Ain,
                                                   const float* __restrict__ W, int mode) {
    __shared__ float As[64 * 68];
    __shared__ float Wsm[64 * 64];
    const float* A; float* C; int aRow, aTile;
    if (mode == 0)      { A = Ain;      C = g_qh;     aRow = 1024;  aTile = 0;    }
    else if (mode == 1) { A = g_vbar;   C = g_concat; aRow = 16384; aTile = 1024; }
    else                { A = g_concat; C = g_outpre; aRow = 1024;  aTile = 0;    }
    int bx = blockIdx.x, by = blockIdx.y, tid = threadIdx.x;
    const float* Ap = A + bx * aTile;
    int col0 = bx * 64, d0 = by * 128;
    int tj = tid & 15, tb = tid >> 4;
    float acc[4][4] = {};
    for (int dc = 0; dc < 2; dc++) {
        int db = d0 + dc * 64;
        __syncthreads();
        for (int idx = tid; idx < 4096; idx += 256) {
            int b = idx >> 6, dd = idx & 63;
            As[b * 68 + dd] = Ap[(size_t)b * aRow + db + dd];
        }
        for (int idx = tid; idx < 4096; idx += 256) {
            int dd = idx >> 6, j = idx & 63;
            Wsm[dd * 64 + j] = W[(size_t)(db + dd) * 1024 + col0 + j];
        }
        __syncthreads();
        const float4* Ws4 = (const float4*)Wsm;
        #pragma unroll 8
        for (int dd = 0; dd < 64; dd++) {
            float4 w = Ws4[dd * 16 + tj];
            #pragma unroll
            for (int bb = 0; bb < 4; bb++) {
                float a = As[(tb * 4 + bb) * 68 + dd];
                acc[bb][0] = fmaf(a, w.x, acc[bb][0]);
                acc[bb][1] = fmaf(a, w.y, acc[bb][1]);
                acc[bb][2] = fmaf(a, w.z, acc[bb][2]);
                acc[bb][3] = fmaf(a, w.w, acc[bb][3]);
            }
        }
    }
    #pragma unroll
    for (int bb = 0; bb < 4; bb++)
        #pragma unroll
        for (int jj = 0; jj < 4; jj++)
            atomicAdd(&C[(size_t)(tb * 4 + bb) * 1024 + col0 + tj * 4 + jj], acc[bb][jj]);
}

// g_ws[b][d][h] = 0.125 * sum_j Wk[d, 64h+j] * g_qh[b, 64h+j]
__global__ __launch_bounds__(256) void k_ws(const float* __restrict__ Wk) {
    __shared__ float Wks[64 * 68];
    __shared__ float qhs[8 * 64];
    int dt = blockIdx.x, bt = blockIdx.y, tid = threadIdx.x;
    int td = tid & 63, tg = tid >> 6;
    for (int h = 0; h < 16; h++) {
        __syncthreads();
        for (int idx = tid; idx < 4096; idx += 256) {
            int dd = idx >> 6, j = idx & 63;
            Wks[dd * 68 + j] = Wk[(size_t)(dt * 64 + dd) * 1024 + h * 64 + j];
        }
        for (int idx = tid; idx < 512; idx += 256) {
            int bb = idx >> 6, j = idx & 63;
            qhs[bb * 64 + j] = g_qh[(size_t)(bt * 8 + bb) * 1024 + h * 64 + j];
        }
        __syncthreads();
        float a0 = 0.f, a1 = 0.f;
        #pragma unroll
        for (int j4 = 0; j4 < 16; j4++) {
            float4 w  = *(const float4*)&Wks[td * 68 + j4 * 4];
            float4 qa = *(const float4*)&qhs[(tg * 2 + 0) * 64 + j4 * 4];
            float4 qb = *(const float4*)&qhs[(tg * 2 + 1) * 64 + j4 * 4];
            a0 = fmaf(w.x, qa.x, fmaf(w.y, qa.y, fmaf(w.z, qa.z, fmaf(w.w, qa.w, a0))));
            a1 = fmaf(w.x, qb.x, fmaf(w.y, qb.y, fmaf(w.z, qb.z, fmaf(w.w, qb.w, a1))));
        }
        int d = dt * 64 + td;
        g_ws[((size_t)(bt * 8 + tg * 2 + 0) * 1024 + d) * 16 + h] = a0 * 0.125f;
        g_ws[((size_t)(bt * 8 + tg * 2 + 1) * 1024 + d) * 16 + h] = a1 * 0.125f;
    }
}

// pass 1: stream k -> scores. grid (64,2), dyn smem = (16384 + 64*257)*4
__global__ __launch_bounds__(256) void k_scores(const float* __restrict__ k) {
    extern __shared__ float sm[];
    float* ws_s = sm;            // 16384 f: [d][h] for batch b
    float* k_t  = sm + 16384;    // 64 x 257 transposed tile
    int b = blockIdx.x, sh = blockIdx.y, tid = threadIdx.x;
    {
        const float4* src = (const float4*)(g_ws + (size_t)b * 16384);
        float4* dst = (float4*)ws_s;
        for (int idx = tid; idx < 4096; idx += 256) dst[idx] = src[idx];
    }
    const float4* k4 = (const float4*)k;
    const ulonglong2* wsu2 = (const ulonglong2*)ws_s;
    for (int tile = 0; tile < 4; tile++) {
        int rbase = sh * 1024 + tile * 256;
        ull acc[8];
        #pragma unroll
        for (int p = 0; p < 8; p++) acc[p] = 0ull;
        for (int dc = 0; dc < 16; dc++) {
            __syncthreads();
            for (int idx = tid; idx < 4096; idx += 256) {
                int row = idx >> 4, dq = idx & 15;
                float4 kv = k4[((size_t)b * 2048 + rbase + row) * 256 + dc * 16 + dq];
                int d4 = dq * 4;
                k_t[(d4 + 0) * 257 + row] = kv.x;
                k_t[(d4 + 1) * 257 + row] = kv.y;
                k_t[(d4 + 2) * 257 + row] = kv.z;
                k_t[(d4 + 3) * 257 + row] = kv.w;
            }
            __syncthreads();
            #pragma unroll
            for (int dd = 0; dd < 64; dd++) {
                float kv = k_t[dd * 257 + tid];
                ull k2 = pk2(kv, kv);
                int wb = (dc * 64 + dd) * 4;
                ulonglong2 w0 = wsu2[wb + 0], w1 = wsu2[wb + 1];
                ulonglong2 w2 = wsu2[wb + 2], w3 = wsu2[wb + 3];
                acc[0] = fma2(k2, w0.x, acc[0]); acc[1] = fma2(k2, w0.y, acc[1]);
                acc[2] = fma2(k2, w1.x, acc[2]); acc[3] = fma2(k2, w1.y, acc[3]);
                acc[4] = fma2(k2, w2.x, acc[4]); acc[5] = fma2(k2, w2.y, acc[5]);
                acc[6] = fma2(k2, w3.x, acc[6]); acc[7] = fma2(k2, w3.y, acc[7]);
            }
        }
        int s = rbase + tid;
        #pragma unroll
        for (int p = 0; p < 8; p++) {
            float lo, hi; upk2(lo, hi, acc[p]);
            g_scores[(size_t)(b * 16 + 2 * p) * 2048 + s]     = lo;
            g_scores[(size_t)(b * 16 + 2 * p + 1) * 2048 + s] = hi;
        }
    }
}

// softmax over s per (b,h); write attn[b][s][h]
__global__ __launch_bounds__(256) void k_softmax() {
    int b = blockIdx.x, h = blockIdx.y, tid = threadIdx.x;
    const float* row = g_scores + (size_t)(b * 16 + h) * 2048;
    float x[8], m = -1e30f;
    #pragma unroll
    for (int i = 0; i < 8; i++) { x[i] = row[tid + i * 256]; m = fmaxf(m, x[i]); }
    __shared__ float red[8];
    #pragma unroll
    for (int o = 16; o; o >>= 1) m = fmaxf(m, __shfl_xor_sync(0xffffffffu, m, o));
    if ((tid & 31) == 0) red[tid >> 5] = m;
    __syncthreads();
    float M = red[0];
    #pragma unroll
    for (int i = 1; i < 8; i++) M = fmaxf(M, red[i]);
    __syncthreads();
    float ssum = 0.f;
    #pragma unroll
    for (int i = 0; i < 8; i++) { x[i] = __expf(x[i] - M); ssum += x[i]; }
    #pragma unroll
    for (int o = 16; o; o >>= 1) ssum += __shfl_xor_sync(0xffffffffu, ssum, o);
    if ((tid & 31) == 0) red[tid >> 5] = ssum;
    __syncthreads();
    float T = 0.f;
    #pragma unroll
    for (int i = 0; i < 8; i++) T += red[i];
    float inv = 1.0f / T;
    #pragma unroll
    for (int i = 0; i < 8; i++)
        g_attn[((size_t)b * 2048 + tid + i * 256) * 16 + h] = x[i] * inv;
}

// pass 2: stream v -> vbar[b][h][d]. grid (64,2)
__global__ __launch_bounds__(256) void k_vbar(const float* __restrict__ v) {
    __shared__ __align__(16) ull at2[128 * 16];
    int b = blockIdx.x, dh = blockIdx.y, tid = threadIdx.x;
    int w = tid >> 5, l = tid & 31;
    int d0 = dh * 512 + w * 64 + 2 * l;
    ull acc[16];
    #pragma unroll
    for (int h = 0; h < 16; h++) acc[h] = 0ull;
    const ull* vp = (const ull*)v;
    for (int sc = 0; sc < 16; sc++) {
        __syncthreads();
        for (int idx = tid; idx < 2048; idx += 256) {
            float a = g_attn[((size_t)b * 2048 + sc * 128 + (idx >> 4)) * 16 + (idx & 15)];
            at2[idx] = pk2(a, a);
        }
        __syncthreads();
        const ulonglong2* A2 = (const ulonglong2*)at2;
        #pragma unroll 4
        for (int ss = 0; ss < 128; ss++) {
            ull v2 = vp[(((size_t)b * 2048 + sc * 128 + ss) * 1024 + d0) >> 1];
            ulonglong2 a01 = A2[ss * 8 + 0], a23 = A2[ss * 8 + 1];
            ulonglong2 a45 = A2[ss * 8 + 2], a67 = A2[ss * 8 + 3];
            ulonglong2 a89 = A2[ss * 8 + 4], aAB = A2[ss * 8 + 5];
            ulonglong2 aCD = A2[ss * 8 + 6], aEF = A2[ss * 8 + 7];
            acc[0]  = fma2(v2, a01.x, acc[0]);  acc[1]  = fma2(v2, a01.y, acc[1]);
            acc[2]  = fma2(v2, a23.x, acc[2]);  acc[3]  = fma2(v2, a23.y, acc[3]);
            acc[4]  = fma2(v2, a45.x, acc[4]);  acc[5]  = fma2(v2, a45.y, acc[5]);
            acc[6]  = fma2(v2, a67.x, acc[6]);  acc[7]  = fma2(v2, a67.y, acc[7]);
            acc[8]  = fma2(v2, a89.x, acc[8]);  acc[9]  = fma2(v2, a89.y, acc[9]);
            acc[10] = fma2(v2, aAB.x, acc[10]); acc[11] = fma2(v2, aAB.y, acc[11]);
            acc[12] = fma2(v2, aCD.x, acc[12]); acc[13] = fma2(v2, aCD.y, acc[13]);
            acc[14] = fma2(v2, aEF.x, acc[14]); acc[15] = fma2(v2, aEF.y, acc[15]);
        }
    }
    ull* vb = (ull*)g_vbar;
    #pragma unroll
    for (int h = 0; h < 16; h++)
        vb[(((size_t)(b * 16 + h)) * 1024 + d0) >> 1] = acc[h];
}

__global__ __launch_bounds__(256) void k_relu(float* __restrict__ out) {
    int i = blockIdx.x * 256 + threadIdx.x;
    out[i] = fmaxf(g_outpre[i], 0.0f);
}

extern "C" void kernel_launch(void* const* d_in, const int* in_sizes, int n_in,
                              void* d_out, int out_size) {
    const float* q  = (const float*)d_in[0];
    const float* k  = (const float*)d_in[1];
    const float* v  = (const float*)d_in[2];
    const float* Wq = (const float*)d_in[3];
    const float* bq = (const float*)d_in[4];
    const float* Wk = (const float*)d_in[5];
    // d_in[6] = bk — cancels in softmax, unused
    const float* Wv = (const float*)d_in[7];
    const float* bv = (const float*)d_in[8];
    const float* Wo = (const float*)d_in[9];
    const float* bo = (const float*)d_in[10];

    static bool attr_done = false;
    int smem_scores = (16384 + 64 * 257) * (int)sizeof(float);
    if (!attr_done) {
        cudaFuncSetAttribute(k_scores, cudaFuncAttributeMaxDynamicSharedMemorySize, smem_scores);
        attr_done = true;
    }

    k_init<<<256, 256>>>(bq, bv, bo);
    gemm_ksplit<<<dim3(16, 8), 256>>>(q, Wq, 0);
    k_ws<<<dim3(16, 8), 256>>>(Wk);
    k_scores<<<dim3(64, 2), 256, smem_scores>>>(k);
    k_softmax<<<dim3(64, 16), 256>>>();
    k_vbar<<<dim3(64, 2), 256>>>(v);
    gemm_ksplit<<<dim3(16, 8), 256>>>(nullptr, Wv, 1);
    gemm_ksplit<<<dim3(16, 8), 256>>>(nullptr, Wo, 2);
    k_relu<<<256, 256>>>((float*)d_out);
}

// round 3
// speedup vs baseline: 1.6717x; 1.6717x over previous
#include <cuda_runtime.h>
#include <cstdint>
#include <cstddef>

typedef unsigned long long ull;

// device scratch (allocs forbidden)
__device__ float g_qh[64 * 1024];
__device__ float g_ws[64 * 1024 * 16];                 // [b][d][h]
__device__ float g_scores_part[4][64 * 16 * 2048];     // [dq][b][h][s]  32 MB
__device__ float g_attn[64 * 2048 * 16];               // [b][s][h]
__device__ float g_vbar_part[4][64 * 16 * 1024];       // [sq][b][h][d]  16 MB
__device__ float g_vbar[64 * 16 * 1024];               // [b][h][d]
__device__ float g_concat[64 * 1024];
__device__ float g_outpre[64 * 1024];

__device__ __forceinline__ ull pk2(float x, float y) {
    ull r; asm("mov.b64 %0, {%1,%2};" : "=l"(r) : "f"(x), "f"(y)); return r;
}
__device__ __forceinline__ void upk2(float& x, float& y, ull v) {
    asm("mov.b64 {%0,%1}, %2;" : "=f"(x), "=f"(y) : "l"(v));
}
__device__ __forceinline__ ull fma2(ull a, ull b, ull c) {
    ull d; asm("fma.rn.f32x2 %0, %1, %2, %3;" : "=l"(d) : "l"(a), "l"(b), "l"(c)); return d;
}

__global__ __launch_bounds__(256) void k_init(const float* __restrict__ bq,
                                              const float* __restrict__ bv,
                                              const float* __restrict__ bo) {
    int i = blockIdx.x * 256 + threadIdx.x;
    int c = i & 1023;
    g_qh[i] = bq[c]; g_concat[i] = bv[c]; g_outpre[i] = bo[c];
}

// C[64,1024] += A[64,1024] @ W[1024,1024]; k-split over blockIdx.y (8x128), 64-col tiles over x.
__global__ __launch_bounds__(256) void gemm_ksplit(const float* __restrict__ Ain,
                                                   const float* __restrict__ W, int mode) {
    __shared__ float As[64 * 68];
    __shared__ float Wsm[64 * 64];
    const float* A; float* C; int aRow, aTile;
    if (mode == 0)      { A = Ain;      C = g_qh;     aRow = 1024;  aTile = 0;    }
    else if (mode == 1) { A = g_vbar;   C = g_concat; aRow = 16384; aTile = 1024; }
    else                { A = g_concat; C = g_outpre; aRow = 1024;  aTile = 0;    }
    int bx = blockIdx.x, by = blockIdx.y, tid = threadIdx.x;
    const float* Ap = A + bx * aTile;
    int col0 = bx * 64, d0 = by * 128;
    int tj = tid & 15, tb = tid >> 4;
    float acc[4][4] = {};
    for (int dc = 0; dc < 2; dc++) {
        int db = d0 + dc * 64;
        __syncthreads();
        for (int idx = tid; idx < 4096; idx += 256) {
            int b = idx >> 6, dd = idx & 63;
            As[b * 68 + dd] = Ap[(size_t)b * aRow + db + dd];
        }
        for (int idx = tid; idx < 4096; idx += 256) {
            int dd = idx >> 6, j = idx & 63;
            Wsm[dd * 64 + j] = W[(size_t)(db + dd) * 1024 + col0 + j];
        }
        __syncthreads();
        const float4* Ws4 = (const float4*)Wsm;
        #pragma unroll 8
        for (int dd = 0; dd < 64; dd++) {
            float4 w = Ws4[dd * 16 + tj];
            #pragma unroll
            for (int bb = 0; bb < 4; bb++) {
                float a = As[(tb * 4 + bb) * 68 + dd];
                acc[bb][0] = fmaf(a, w.x, acc[bb][0]);
                acc[bb][1] = fmaf(a, w.y, acc[bb][1]);
                acc[bb][2] = fmaf(a, w.z, acc[bb][2]);
                acc[bb][3] = fmaf(a, w.w, acc[bb][3]);
            }
        }
    }
    #pragma unroll
    for (int bb = 0; bb < 4; bb++)
        #pragma unroll
        for (int jj = 0; jj < 4; jj++)
            atomicAdd(&C[(size_t)(tb * 4 + bb) * 1024 + col0 + tj * 4 + jj], acc[bb][jj]);
}

// g_ws[b][d][h] = 0.125 * sum_j Wk[d, 64h+j] * g_qh[b, 64h+j]
__global__ __launch_bounds__(256) void k_ws(const float* __restrict__ Wk) {
    __shared__ float Wks[64 * 68];
    __shared__ float qhs[8 * 64];
    int dt = blockIdx.x, bt = blockIdx.y, tid = threadIdx.x;
    int td = tid & 63, tg = tid >> 6;
    for (int h = 0; h < 16; h++) {
        __syncthreads();
        for (int idx = tid; idx < 4096; idx += 256) {
            int dd = idx >> 6, j = idx & 63;
            Wks[dd * 68 + j] = Wk[(size_t)(dt * 64 + dd) * 1024 + h * 64 + j];
        }
        for (int idx = tid; idx < 512; idx += 256) {
            int bb = idx >> 6, j = idx & 63;
            qhs[bb * 64 + j] = g_qh[(size_t)(bt * 8 + bb) * 1024 + h * 64 + j];
        }
        __syncthreads();
        float a0 = 0.f, a1 = 0.f;
        #pragma unroll
        for (int j4 = 0; j4 < 16; j4++) {
            float4 w  = *(const float4*)&Wks[td * 68 + j4 * 4];
            float4 qa = *(const float4*)&qhs[(tg * 2 + 0) * 64 + j4 * 4];
            float4 qb = *(const float4*)&qhs[(tg * 2 + 1) * 64 + j4 * 4];
            a0 = fmaf(w.x, qa.x, fmaf(w.y, qa.y, fmaf(w.z, qa.z, fmaf(w.w, qa.w, a0))));
            a1 = fmaf(w.x, qb.x, fmaf(w.y, qb.y, fmaf(w.z, qb.z, fmaf(w.w, qb.w, a1))));
        }
        int d = dt * 64 + td;
        g_ws[((size_t)(bt * 8 + tg * 2 + 0) * 1024 + d) * 16 + h] = a0 * 0.125f;
        g_ws[((size_t)(bt * 8 + tg * 2 + 1) * 1024 + d) * 16 + h] = a1 * 0.125f;
    }
}

// ---------------- pass 1: stream k -> partial scores ----------------
// grid (64 b, 8 st, 4 dq). Each CTA: 256 s-rows, 256-d chunk, 16 chunks of 16 d.
// dyn smem: ws_s[256*16] (16KB) + k_t[2][16*257] (32.9KB)
__global__ __launch_bounds__(256) void k_scores(const float* __restrict__ k) {
    extern __shared__ float sm[];
    float* ws_s = sm;                 // 4096 floats
    float* k_t  = sm + 4096;          // 2 bufs of 16*257
    const int b = blockIdx.x, st = blockIdx.y, dq = blockIdx.z;
    const int tid = threadIdx.x;

    {   // stage ws slice [256 d][16 h] for (b, dq)
        const float4* src = (const float4*)(g_ws + (size_t)b * 16384 + dq * 4096);
        float4* dst = (float4*)ws_s;
        #pragma unroll
        for (int i = 0; i < 4; i++) dst[tid + i * 256] = src[tid + i * 256];
    }

    const float4* k4 = (const float4*)k;
    const size_t rowBase = ((size_t)b * 2048 + st * 256) * 256 + dq * 64; // float4 units
    const int myrow = tid >> 2, myq = tid & 3; // per-thread fixed (row, quad) pattern

    // prologue: load chunk 0 into regs, store to buf 0
    float4 r[4];
    #pragma unroll
    for (int i = 0; i < 4; i++) {
        int idx = tid + i * 256;
        r[i] = k4[rowBase + (size_t)(idx >> 2) * 256 + (idx & 3)];
    }
    #pragma unroll
    for (int i = 0; i < 4; i++) {
        int idx = tid + i * 256;
        int row = idx >> 2, q = idx & 3;
        k_t[(4 * q + 0) * 257 + row] = r[i].x;
        k_t[(4 * q + 1) * 257 + row] = r[i].y;
        k_t[(4 * q + 2) * 257 + row] = r[i].z;
        k_t[(4 * q + 3) * 257 + row] = r[i].w;
    }

    ull acc[8];
    #pragma unroll
    for (int p = 0; p < 8; p++) acc[p] = 0ull;
    const ulonglong2* wsu2 = (const ulonglong2*)ws_s;

    for (int c = 0; c < 16; c++) {
        __syncthreads();
        if (c < 15) {  // issue next chunk's LDGs early (hidden behind compute)
            #pragma unroll
            for (int i = 0; i < 4; i++) {
                int idx = tid + i * 256;
                r[i] = k4[rowBase + (size_t)(idx >> 2) * 256 + (c + 1) * 4 + (idx & 3)];
            }
        }
        const float* kb = k_t + (c & 1) * 4112;
        #pragma unroll
        for (int dd = 0; dd < 16; dd++) {
            float kv = kb[dd * 257 + tid];
            ull k2 = pk2(kv, kv);
            int wb = (c * 16 + dd) * 4;
            ulonglong2 w0 = wsu2[wb + 0], w1 = wsu2[wb + 1];
            ulonglong2 w2 = wsu2[wb + 2], w3 = wsu2[wb + 3];
            acc[0] = fma2(k2, w0.x, acc[0]); acc[1] = fma2(k2, w0.y, acc[1]);
            acc[2] = fma2(k2, w1.x, acc[2]); acc[3] = fma2(k2, w1.y, acc[3]);
            acc[4] = fma2(k2, w2.x, acc[4]); acc[5] = fma2(k2, w2.y, acc[5]);
            acc[6] = fma2(k2, w3.x, acc[6]); acc[7] = fma2(k2, w3.y, acc[7]);
        }
        if (c < 15) {
            float* nb = k_t + ((c + 1) & 1) * 4112;
            #pragma unroll
            for (int i = 0; i < 4; i++) {
                int idx = tid + i * 256;
                int row = idx >> 2, q = idx & 3;
                nb[(4 * q + 0) * 257 + row] = r[i].x;
                nb[(4 * q + 1) * 257 + row] = r[i].y;
                nb[(4 * q + 2) * 257 + row] = r[i].z;
                nb[(4 * q + 3) * 257 + row] = r[i].w;
            }
        }
    }

    int s = st * 256 + tid;
    float* outp = g_scores_part[dq];
    #pragma unroll
    for (int p = 0; p < 8; p++) {
        float lo, hi; upk2(lo, hi, acc[p]);
        outp[(size_t)(b * 16 + 2 * p) * 2048 + s]     = lo;
        outp[(size_t)(b * 16 + 2 * p + 1) * 2048 + s] = hi;
    }
}

// softmax over s per (b,h); sums 4 d-partials; write attn[b][s][h]
__global__ __launch_bounds__(256) void k_softmax() {
    int b = blockIdx.x, h = blockIdx.y, tid = threadIdx.x;
    size_t off = (size_t)(b * 16 + h) * 2048;
    float x[8], m = -1e30f;
    #pragma unroll
    for (int i = 0; i < 8; i++) {
        int s = tid + i * 256;
        float v = g_scores_part[0][off + s] + g_scores_part[1][off + s]
                + g_scores_part[2][off + s] + g_scores_part[3][off + s];
        x[i] = v; m = fmaxf(m, v);
    }
    __shared__ float red[8];
    #pragma unroll
    for (int o = 16; o; o >>= 1) m = fmaxf(m, __shfl_xor_sync(0xffffffffu, m, o));
    if ((tid & 31) == 0) red[tid >> 5] = m;
    __syncthreads();
    float M = red[0];
    #pragma unroll
    for (int i = 1; i < 8; i++) M = fmaxf(M, red[i]);
    __syncthreads();
    float ssum = 0.f;
    #pragma unroll
    for (int i = 0; i < 8; i++) { x[i] = __expf(x[i] - M); ssum += x[i]; }
    #pragma unroll
    for (int o = 16; o; o >>= 1) ssum += __shfl_xor_sync(0xffffffffu, ssum, o);
    if ((tid & 31) == 0) red[tid >> 5] = ssum;
    __syncthreads();
    float T = 0.f;
    #pragma unroll
    for (int i = 0; i < 8; i++) T += red[i];
    float inv = 1.0f / T;
    #pragma unroll
    for (int i = 0; i < 8; i++)
        g_attn[((size_t)b * 2048 + tid + i * 256) * 16 + h] = x[i] * inv;
}

// ---------------- pass 2: stream v -> partial vbar ----------------
// grid (64 b, 2 dh, 4 sq). Each CTA: 512 s (4 sub-chunks of 128), 512 d.
__global__ __launch_bounds__(256) void k_vbar(const float* __restrict__ v) {
    __shared__ __align__(16) ull at2[2][2048];
    const int b = blockIdx.x, dh = blockIdx.y, sq = blockIdx.z;
    const int tid = threadIdx.x;
    const int w = tid >> 5, l = tid & 31;
    const int d0 = dh * 512 + w * 64 + 2 * l;
    const size_t sBase = (size_t)b * 2048 + sq * 512;

    ull acc[16];
    #pragma unroll
    for (int h = 0; h < 16; h++) acc[h] = 0ull;
    const ull* vp = (const ull*)v;

    // prologue: stage attn sub-chunk 0
    ull a2[8];
    #pragma unroll
    for (int i = 0; i < 8; i++) {
        int idx = tid + i * 256;
        float a = g_attn[(sBase + (idx >> 4)) * 16 + (idx & 15)];
        a2[i] = pk2(a, a);
    }
    #pragma unroll
    for (int i = 0; i < 8; i++) at2[0][tid + i * 256] = a2[i];

    for (int sub = 0; sub < 4; sub++) {
        __syncthreads();
        if (sub < 3) {
            #pragma unroll
            for (int i = 0; i < 8; i++) {
                int idx = tid + i * 256;
                float a = g_attn[(sBase + (sub + 1) * 128 + (idx >> 4)) * 16 + (idx & 15)];
                a2[i] = pk2(a, a);
            }
        }
        const ulonglong2* A2 = (const ulonglong2*)at2[sub & 1];
        const size_t vrow0 = (sBase + sub * 128) * 1024 + d0;
        #pragma unroll 4
        for (int ss = 0; ss < 128; ss++) {
            ull v2 = vp[(vrow0 + (size_t)ss * 1024) >> 1];
            ulonglong2 a01 = A2[ss * 8 + 0], a23 = A2[ss * 8 + 1];
            ulonglong2 a45 = A2[ss * 8 + 2], a67 = A2[ss * 8 + 3];
            ulonglong2 a89 = A2[ss * 8 + 4], aAB = A2[ss * 8 + 5];
            ulonglong2 aCD = A2[ss * 8 + 6], aEF = A2[ss * 8 + 7];
            acc[0]  = fma2(v2, a01.x, acc[0]);  acc[1]  = fma2(v2, a01.y, acc[1]);
            acc[2]  = fma2(v2, a23.x, acc[2]);  acc[3]  = fma2(v2, a23.y, acc[3]);
            acc[4]  = fma2(v2, a45.x, acc[4]);  acc[5]  = fma2(v2, a45.y, acc[5]);
            acc[6]  = fma2(v2, a67.x, acc[6]);  acc[7]  = fma2(v2, a67.y, acc[7]);
            acc[8]  = fma2(v2, a89.x, acc[8]);  acc[9]  = fma2(v2, a89.y, acc[9]);
            acc[10] = fma2(v2, aAB.x, acc[10]); acc[11] = fma2(v2, aAB.y, acc[11]);
            acc[12] = fma2(v2, aCD.x, acc[12]); acc[13] = fma2(v2, aCD.y, acc[13]);
            acc[14] = fma2(v2, aEF.x, acc[14]); acc[15] = fma2(v2, aEF.y, acc[15]);
        }
        if (sub < 3) {
            ull* nb = at2[(sub + 1) & 1];
            #pragma unroll
            for (int i = 0; i < 8; i++) nb[tid + i * 256] = a2[i];
        }
    }

    ull* vb = (ull*)g_vbar_part[sq];
    #pragma unroll
    for (int h = 0; h < 16; h++)
        vb[(((size_t)(b * 16 + h)) * 1024 + d0) >> 1] = acc[h];
}

// sum 4 vbar partials
__global__ __launch_bounds__(256) void k_vreduce() {
    int i = blockIdx.x * 256 + threadIdx.x;   // 256K float4
    const float4* p0 = (const float4*)g_vbar_part[0];
    const float4* p1 = (const float4*)g_vbar_part[1];
    const float4* p2 = (const float4*)g_vbar_part[2];
    const float4* p3 = (const float4*)g_vbar_part[3];
    float4 a = p0[i], b = p1[i], c = p2[i], d = p3[i];
    float4 o;
    o.x = (a.x + b.x) + (c.x + d.x);
    o.y = (a.y + b.y) + (c.y + d.y);
    o.z = (a.z + b.z) + (c.z + d.z);
    o.w = (a.w + b.w) + (c.w + d.w);
    ((float4*)g_vbar)[i] = o;
}

__global__ __launch_bounds__(256) void k_relu(float* __restrict__ out) {
    int i = blockIdx.x * 256 + threadIdx.x;
    out[i] = fmaxf(g_outpre[i], 0.0f);
}

extern "C" void kernel_launch(void* const* d_in, const int* in_sizes, int n_in,
                              void* d_out, int out_size) {
    const float* q  = (const float*)d_in[0];
    const float* k  = (const float*)d_in[1];
    const float* v  = (const float*)d_in[2];
    const float* Wq = (const float*)d_in[3];
    const float* bq = (const float*)d_in[4];
    const float* Wk = (const float*)d_in[5];
    // d_in[6] = bk — cancels in softmax
    const float* Wv = (const float*)d_in[7];
    const float* bv = (const float*)d_in[8];
    const float* Wo = (const float*)d_in[9];
    const float* bo = (const float*)d_in[10];

    const int smem_scores = (4096 + 2 * 16 * 257) * (int)sizeof(float); // 49280
    static bool attr_done = false;
    if (!attr_done) {
        cudaFuncSetAttribute(k_scores, cudaFuncAttributeMaxDynamicSharedMemorySize, smem_scores);
        attr_done = true;
    }

    k_init<<<256, 256>>>(bq, bv, bo);
    gemm_ksplit<<<dim3(16, 8), 256>>>(q, Wq, 0);
    k_ws<<<dim3(16, 8), 256>>>(Wk);
    k_scores<<<dim3(64, 8, 4), 256, smem_scores>>>(k);
    k_softmax<<<dim3(64, 16), 256>>>();
    k_vbar<<<dim3(64, 2, 4), 256>>>(v);
    k_vreduce<<<1024, 256>>>();
    gemm_ksplit<<<dim3(16, 8), 256>>>(nullptr, Wv, 1);
    gemm_ksplit<<<dim3(16, 8), 256>>>(nullptr, Wo, 2);
    k_relu<<<256, 256>>>((float*)d_out);
}

// round 4
// speedup vs baseline: 2.0512x; 1.2270x over previous
#include <cuda_runtime.h>
#include <cstdint>
#include <cstddef>

typedef unsigned long long ull;

// device scratch (allocs forbidden)
__device__ float g_qh[64 * 1024];
__device__ float g_ws[64 * 1024 * 16];                 // [b][d][h]
__device__ float g_scores_part[4][64 * 16 * 2048];     // [dq][b][h][s]
__device__ float g_attn[64 * 2048 * 16];               // [b][s][h]
__device__ float g_vbar_part[8][64 * 16 * 1024];       // [sq][b][h][d]
__device__ float g_vbar[64 * 16 * 1024];               // [b][h][d]
__device__ float g_concat[64 * 1024];
__device__ float g_outpre[64 * 1024];

__device__ __forceinline__ ull pk2(float x, float y) {
    ull r; asm("mov.b64 %0, {%1,%2};" : "=l"(r) : "f"(x), "f"(y)); return r;
}
__device__ __forceinline__ void upk2(float& x, float& y, ull v) {
    asm("mov.b64 {%0,%1}, %2;" : "=f"(x), "=f"(y) : "l"(v));
}
__device__ __forceinline__ ull fma2(ull a, ull b, ull c) {
    ull d; asm("fma.rn.f32x2 %0, %1, %2, %3;" : "=l"(d) : "l"(a), "l"(b), "l"(c)); return d;
}
__device__ __forceinline__ ull add2(ull a, ull b) {
    ull c; asm("add.rn.f32x2 %0, %1, %2;" : "=l"(c) : "l"(a), "l"(b)); return c;
}

__global__ __launch_bounds__(256) void k_init(const float* __restrict__ bq,
                                              const float* __restrict__ bv,
                                              const float* __restrict__ bo) {
    int i = blockIdx.x * 256 + threadIdx.x;
    int c = i & 1023;
    g_qh[i] = bq[c]; g_concat[i] = bv[c]; g_outpre[i] = bo[c];
}

// C[64,1024] += A[64,1024] @ W[1024,1024]; k-split over blockIdx.y (8x128), 64-col tiles over x.
__global__ __launch_bounds__(256) void gemm_ksplit(const float* __restrict__ Ain,
                                                   const float* __restrict__ W, int mode) {
    __shared__ float As[64 * 68];
    __shared__ float Wsm[64 * 64];
    const float* A; float* C; int aRow, aTile;
    if (mode == 0)      { A = Ain;      C = g_qh;     aRow = 1024;  aTile = 0;    }
    else if (mode == 1) { A = g_vbar;   C = g_concat; aRow = 16384; aTile = 1024; }
    else                { A = g_concat; C = g_outpre; aRow = 1024;  aTile = 0;    }
    int bx = blockIdx.x, by = blockIdx.y, tid = threadIdx.x;
    const float* Ap = A + bx * aTile;
    int col0 = bx * 64, d0 = by * 128;
    int tj = tid & 15, tb = tid >> 4;
    float acc[4][4] = {};
    for (int dc = 0; dc < 2; dc++) {
        int db = d0 + dc * 64;
        __syncthreads();
        for (int idx = tid; idx < 4096; idx += 256) {
            int b = idx >> 6, dd = idx & 63;
            As[b * 68 + dd] = Ap[(size_t)b * aRow + db + dd];
        }
        for (int idx = tid; idx < 4096; idx += 256) {
            int dd = idx >> 6, j = idx & 63;
            Wsm[dd * 64 + j] = W[(size_t)(db + dd) * 1024 + col0 + j];
        }
        __syncthreads();
        const float4* Ws4 = (const float4*)Wsm;
        #pragma unroll 8
        for (int dd = 0; dd < 64; dd++) {
            float4 w = Ws4[dd * 16 + tj];
            #pragma unroll
            for (int bb = 0; bb < 4; bb++) {
                float a = As[(tb * 4 + bb) * 68 + dd];
                acc[bb][0] = fmaf(a, w.x, acc[bb][0]);
                acc[bb][1] = fmaf(a, w.y, acc[bb][1]);
                acc[bb][2] = fmaf(a, w.z, acc[bb][2]);
                acc[bb][3] = fmaf(a, w.w, acc[bb][3]);
            }
        }
    }
    #pragma unroll
    for (int bb = 0; bb < 4; bb++)
        #pragma unroll
        for (int jj = 0; jj < 4; jj++)
            atomicAdd(&C[(size_t)(tb * 4 + bb) * 1024 + col0 + tj * 4 + jj], acc[bb][jj]);
}

// g_ws[b][d][h] = 0.125 * sum_j Wk[d, 64h+j] * g_qh[b, 64h+j]
__global__ __launch_bounds__(256) void k_ws(const float* __restrict__ Wk) {
    __shared__ float Wks[64 * 68];
    __shared__ float qhs[8 * 64];
    int dt = blockIdx.x, bt = blockIdx.y, tid = threadIdx.x;
    int td = tid & 63, tg = tid >> 6;
    for (int h = 0; h < 16; h++) {
        __syncthreads();
        for (int idx = tid; idx < 4096; idx += 256) {
            int dd = idx >> 6, j = idx & 63;
            Wks[dd * 68 + j] = Wk[(size_t)(dt * 64 + dd) * 1024 + h * 64 + j];
        }
        for (int idx = tid; idx < 512; idx += 256) {
            int bb = idx >> 6, j = idx & 63;
            qhs[bb * 64 + j] = g_qh[(size_t)(bt * 8 + bb) * 1024 + h * 64 + j];
        }
        __syncthreads();
        float a0 = 0.f, a1 = 0.f;
        #pragma unroll
        for (int j4 = 0; j4 < 16; j4++) {
            float4 w  = *(const float4*)&Wks[td * 68 + j4 * 4];
            float4 qa = *(const float4*)&qhs[(tg * 2 + 0) * 64 + j4 * 4];
            float4 qb = *(const float4*)&qhs[(tg * 2 + 1) * 64 + j4 * 4];
            a0 = fmaf(w.x, qa.x, fmaf(w.y, qa.y, fmaf(w.z, qa.z, fmaf(w.w, qa.w, a0))));
            a1 = fmaf(w.x, qb.x, fmaf(w.y, qb.y, fmaf(w.z, qb.z, fmaf(w.w, qb.w, a1))));
        }
        int d = dt * 64 + td;
        g_ws[((size_t)(bt * 8 + tg * 2 + 0) * 1024 + d) * 16 + h] = a0 * 0.125f;
        g_ws[((size_t)(bt * 8 + tg * 2 + 1) * 1024 + d) * 16 + h] = a1 * 0.125f;
    }
}

// ---------------- pass 1: stream k -> partial scores ----------------
// grid (64 b, 8 st, 4 dq). Tile: 256 s x 256 d. Threads: dg=tid>>6 handles 4 of
// 16 dd per chunk; r=tid&63 owns rows {r, r+64, r+128, r+192} (permuted layout
// makes them one LDS.128). Cross-dg reduction via smem at tile end.
// dyn smem: ws_s[4096] + k_t[2][16*260] floats = 49664 B
__global__ __launch_bounds__(256, 2) void k_scores(const float* __restrict__ k) {
    extern __shared__ float sm[];
    float* ws_s = sm;                 // 4096 floats: [256 d][16 h]
    float* k_t  = sm + 4096;          // 2 bufs of 16 dd x 260 (permuted cols)
    const int b = blockIdx.x, st = blockIdx.y, dq = blockIdx.z;
    const int tid = threadIdx.x;
    const int dg = tid >> 6, r = tid & 63;

    {   // stage ws slice [256 d][16 h] for (b, dq)
        const float4* src = (const float4*)(g_ws + (size_t)b * 16384 + dq * 4096);
        float4* dst = (float4*)ws_s;
        #pragma unroll
        for (int i = 0; i < 4; i++) dst[tid + i * 256] = src[tid + i * 256];
    }

    const float4* k4 = (const float4*)k;
    const size_t rowBase = ((size_t)b * 2048 + st * 256) * 256 + dq * 64; // float4 units

    // prologue: chunk 0
    float4 rg[4];
    #pragma unroll
    for (int i = 0; i < 4; i++) {
        int idx = tid + i * 256;
        rg[i] = k4[rowBase + (size_t)(idx >> 2) * 256 + (idx & 3)];
    }
    #pragma unroll
    for (int i = 0; i < 4; i++) {
        int idx = tid + i * 256;
        int row = idx >> 2, q = idx & 3;
        int rp = 4 * (row & 63) + (row >> 6);
        k_t[(4 * q + 0) * 260 + rp] = rg[i].x;
        k_t[(4 * q + 1) * 260 + rp] = rg[i].y;
        k_t[(4 * q + 2) * 260 + rp] = rg[i].z;
        k_t[(4 * q + 3) * 260 + rp] = rg[i].w;
    }

    ull acc[4][8];
    #pragma unroll
    for (int i = 0; i < 4; i++)
        #pragma unroll
        for (int p = 0; p < 8; p++) acc[i][p] = 0ull;
    const ulonglong2* wsu2 = (const ulonglong2*)ws_s;

    for (int c = 0; c < 16; c++) {
        __syncthreads();
        if (c < 15) {
            #pragma unroll
            for (int i = 0; i < 4; i++) {
                int idx = tid + i * 256;
                rg[i] = k4[rowBase + (size_t)(idx >> 2) * 256 + (c + 1) * 4 + (idx & 3)];
            }
        }
        const float* kb = k_t + (c & 1) * 4160;
        #pragma unroll
        for (int t = 0; t < 4; t++) {
            int dd = dg * 4 + t;
            float4 kq = *(const float4*)(kb + dd * 260 + 4 * r);
            ull kk0 = pk2(kq.x, kq.x), kk1 = pk2(kq.y, kq.y);
            ull kk2 = pk2(kq.z, kq.z), kk3 = pk2(kq.w, kq.w);
            int wb = (c * 16 + dd) * 4;
            ulonglong2 w0 = wsu2[wb + 0], w1 = wsu2[wb + 1];
            ulonglong2 w2 = wsu2[wb + 2], w3 = wsu2[wb + 3];
            acc[0][0] = fma2(kk0, w0.x, acc[0][0]); acc[0][1] = fma2(kk0, w0.y, acc[0][1]);
            acc[0][2] = fma2(kk0, w1.x, acc[0][2]); acc[0][3] = fma2(kk0, w1.y, acc[0][3]);
            acc[0][4] = fma2(kk0, w2.x, acc[0][4]); acc[0][5] = fma2(kk0, w2.y, acc[0][5]);
            acc[0][6] = fma2(kk0, w3.x, acc[0][6]); acc[0][7] = fma2(kk0, w3.y, acc[0][7]);
            acc[1][0] = fma2(kk1, w0.x, acc[1][0]); acc[1][1] = fma2(kk1, w0.y, acc[1][1]);
            acc[1][2] = fma2(kk1, w1.x, acc[1][2]); acc[1][3] = fma2(kk1, w1.y, acc[1][3]);
            acc[1][4] = fma2(kk1, w2.x, acc[1][4]); acc[1][5] = fma2(kk1, w2.y, acc[1][5]);
            acc[1][6] = fma2(kk1, w3.x, acc[1][6]); acc[1][7] = fma2(kk1, w3.y, acc[1][7]);
            acc[2][0] = fma2(kk2, w0.x, acc[2][0]); acc[2][1] = fma2(kk2, w0.y, acc[2][1]);
            acc[2][2] = fma2(kk2, w1.x, acc[2][2]); acc[2][3] = fma2(kk2, w1.y, acc[2][3]);
            acc[2][4] = fma2(kk2, w2.x, acc[2][4]); acc[2][5] = fma2(kk2, w2.y, acc[2][5]);
            acc[2][6] = fma2(kk2, w3.x, acc[2][6]); acc[2][7] = fma2(kk2, w3.y, acc[2][7]);
            acc[3][0] = fma2(kk3, w0.x, acc[3][0]); acc[3][1] = fma2(kk3, w0.y, acc[3][1]);
            acc[3][2] = fma2(kk3, w1.x, acc[3][2]); acc[3][3] = fma2(kk3, w1.y, acc[3][3]);
            acc[3][4] = fma2(kk3, w2.x, acc[3][4]); acc[3][5] = fma2(kk3, w2.y, acc[3][5]);
            acc[3][6] = fma2(kk3, w3.x, acc[3][6]); acc[3][7] = fma2(kk3, w3.y, acc[3][7]);
        }
        if (c < 15) {
            float* nb = k_t + ((c + 1) & 1) * 4160;
            #pragma unroll
            for (int i = 0; i < 4; i++) {
                int idx = tid + i * 256;
                int row = idx >> 2, q = idx & 3;
                int rp = 4 * (row & 63) + (row >> 6);
                nb[(4 * q + 0) * 260 + rp] = rg[i].x;
                nb[(4 * q + 1) * 260 + rp] = rg[i].y;
                nb[(4 * q + 2) * 260 + rp] = rg[i].z;
                nb[(4 * q + 3) * 260 + rp] = rg[i].w;
            }
        }
    }

    // cross-dg reduction: 2 waves through smem (reusing k_t region: 4096 ull = 32 KB)
    ull* sred = (ull*)(sm + 4096);
    float* outp = g_scores_part[dq];
    const int s = st * 256 + tid;
    #pragma unroll
    for (int w = 0; w < 2; w++) {
        __syncthreads();
        #pragma unroll
        for (int i = 0; i < 4; i++)
            #pragma unroll
            for (int pp = 0; pp < 4; pp++)
                sred[dg * 1024 + (r + 64 * i) * 4 + pp] = acc[i][4 * w + pp];
        __syncthreads();
        #pragma unroll
        for (int jj = 0; jj < 4; jj++) {
            ull s0 = sred[0 * 1024 + tid * 4 + jj];
            ull s1 = sred[1 * 1024 + tid * 4 + jj];
            ull s2 = sred[2 * 1024 + tid * 4 + jj];
            ull s3 = sred[3 * 1024 + tid * 4 + jj];
            ull tsum = add2(add2(s0, s1), add2(s2, s3));
            float lo, hi; upk2(lo, hi, tsum);
            int h = (4 * w + jj) * 2;
            outp[(size_t)(b * 16 + h) * 2048 + s]     = lo;
            outp[(size_t)(b * 16 + h + 1) * 2048 + s] = hi;
        }
    }
}

// softmax over s per (b,h); sums 4 d-partials; write attn[b][s][h]
__global__ __launch_bounds__(256) void k_softmax() {
    int b = blockIdx.x, h = blockIdx.y, tid = threadIdx.x;
    size_t off = (size_t)(b * 16 + h) * 2048;
    float x[8], m = -1e30f;
    #pragma unroll
    for (int i = 0; i < 8; i++) {
        int s = tid + i * 256;
        float v = g_scores_part[0][off + s] + g_scores_part[1][off + s]
                + g_scores_part[2][off + s] + g_scores_part[3][off + s];
        x[i] = v; m = fmaxf(m, v);
    }
    __shared__ float red[8];
    #pragma unroll
    for (int o = 16; o; o >>= 1) m = fmaxf(m, __shfl_xor_sync(0xffffffffu, m, o));
    if ((tid & 31) == 0) red[tid >> 5] = m;
    __syncthreads();
    float M = red[0];
    #pragma unroll
    for (int i = 1; i < 8; i++) M = fmaxf(M, red[i]);
    __syncthreads();
    float ssum = 0.f;
    #pragma unroll
    for (int i = 0; i < 8; i++) { x[i] = __expf(x[i] - M); ssum += x[i]; }
    #pragma unroll
    for (int o = 16; o; o >>= 1) ssum += __shfl_xor_sync(0xffffffffu, ssum, o);
    if ((tid & 31) == 0) red[tid >> 5] = ssum;
    __syncthreads();
    float T = 0.f;
    #pragma unroll
    for (int i = 0; i < 8; i++) T += red[i];
    float inv = 1.0f / T;
    #pragma unroll
    for (int i = 0; i < 8; i++)
        g_attn[((size_t)b * 2048 + tid + i * 256) * 16 + h] = x[i] * inv;
}

// ---------------- pass 2: stream v -> partial vbar ----------------
// grid (64 b, 8 sq). Each CTA: 256 s (2 subs of 128), all 1024 d.
// Thread owns 4 consecutive d (one LDG.128 of v per s) x 16 heads.
__global__ __launch_bounds__(256, 2) void k_vbar(const float* __restrict__ v) {
    __shared__ __align__(16) ull at2[2][2048];
    const int b = blockIdx.x, sq = blockIdx.y;
    const int tid = threadIdx.x;
    const int d0 = tid * 4;
    const size_t sBase = (size_t)b * 2048 + sq * 256;

    ull acc[16][2];
    #pragma unroll
    for (int h = 0; h < 16; h++) { acc[h][0] = 0ull; acc[h][1] = 0ull; }
    const ulonglong2* vp2 = (const ulonglong2*)v;

    // prologue: stage attn sub 0
    ull a2[8];
    #pragma unroll
    for (int i = 0; i < 8; i++) {
        int idx = tid + i * 256;
        float a = g_attn[(sBase + (idx >> 4)) * 16 + (idx & 15)];
        a2[i] = pk2(a, a);
    }
    #pragma unroll
    for (int i = 0; i < 8; i++) at2[0][tid + i * 256] = a2[i];

    #pragma unroll
    for (int sub = 0; sub < 2; sub++) {
        __syncthreads();
        if (sub < 1) {
            #pragma unroll
            for (int i = 0; i < 8; i++) {
                int idx = tid + i * 256;
                float a = g_attn[(sBase + 128 + (idx >> 4)) * 16 + (idx & 15)];
                a2[i] = pk2(a, a);
            }
        }
        const ulonglong2* A2 = (const ulonglong2*)at2[sub];
        const size_t vrow0 = (sBase + sub * 128) * 1024 + d0;
        #pragma unroll 2
        for (int ss = 0; ss < 128; ss++) {
            ulonglong2 v2 = vp2[(vrow0 + (size_t)ss * 1024) >> 2];
            #pragma unroll
            for (int hp = 0; hp < 8; hp++) {
                ulonglong2 a = A2[ss * 8 + hp];
                acc[2 * hp][0]     = fma2(v2.x, a.x, acc[2 * hp][0]);
                acc[2 * hp][1]     = fma2(v2.y, a.x, acc[2 * hp][1]);
                acc[2 * hp + 1][0] = fma2(v2.x, a.y, acc[2 * hp + 1][0]);
                acc[2 * hp + 1][1] = fma2(v2.y, a.y, acc[2 * hp + 1][1]);
            }
        }
        if (sub < 1) {
            #pragma unroll
            for (int i = 0; i < 8; i++) at2[1][tid + i * 256] = a2[i];
        }
    }

    ulonglong2* vb = (ulonglong2*)g_vbar_part[sq];
    #pragma unroll
    for (int h = 0; h < 16; h++) {
        ulonglong2 o; o.x = acc[h][0]; o.y = acc[h][1];
        vb[(((size_t)(b * 16 + h)) * 1024 + d0) >> 2] = o;
    }
}

// sum 8 vbar partials
__global__ __launch_bounds__(256) void k_vreduce() {
    int i = blockIdx.x * 256 + threadIdx.x;   // 256K float4
    float4 o = ((const float4*)g_vbar_part[0])[i];
    #pragma unroll
    for (int p = 1; p < 8; p++) {
        float4 a = ((const float4*)g_vbar_part[p])[i];
        o.x += a.x; o.y += a.y; o.z += a.z; o.w += a.w;
    }
    ((float4*)g_vbar)[i] = o;
}

__global__ __launch_bounds__(256) void k_relu(float* __restrict__ out) {
    int i = blockIdx.x * 256 + threadIdx.x;
    out[i] = fmaxf(g_outpre[i], 0.0f);
}

extern "C" void kernel_launch(void* const* d_in, const int* in_sizes, int n_in,
                              void* d_out, int out_size) {
    const float* q  = (const float*)d_in[0];
    const float* k  = (const float*)d_in[1];
    const float* v  = (const float*)d_in[2];
    const float* Wq = (const float*)d_in[3];
    const float* bq = (const float*)d_in[4];
    const float* Wk = (const float*)d_in[5];
    // d_in[6] = bk — cancels in softmax
    const float* Wv = (const float*)d_in[7];
    const float* bv = (const float*)d_in[8];
    const float* Wo = (const float*)d_in[9];
    const float* bo = (const float*)d_in[10];

    const int smem_scores = (4096 + 2 * 16 * 260) * (int)sizeof(float); // 49664
    static bool attr_done = false;
    if (!attr_done) {
        cudaFuncSetAttribute(k_scores, cudaFuncAttributeMaxDynamicSharedMemorySize, smem_scores);
        attr_done = true;
    }

    k_init<<<256, 256>>>(bq, bv, bo);
    gemm_ksplit<<<dim3(16, 8), 256>>>(q, Wq, 0);
    k_ws<<<dim3(16, 8), 256>>>(Wk);
    k_scores<<<dim3(64, 8, 4), 256, smem_scores>>>(k);
    k_softmax<<<dim3(64, 16), 256>>>();
    k_vbar<<<dim3(64, 8), 256>>>(v);
    k_vreduce<<<1024, 256>>>();
    gemm_ksplit<<<dim3(16, 8), 256>>>(nullptr, Wv, 1);
    gemm_ksplit<<<dim3(16, 8), 256>>>(nullptr, Wo, 2);
    k_relu<<<256, 256>>>((float*)d_out);
}

// round 5
// speedup vs baseline: 2.5089x; 1.2232x over previous
#include <cuda_runtime.h>
#include <cstdint>
#include <cstddef>

typedef unsigned long long ull;

// device scratch (allocs forbidden)
__device__ float g_qh[64 * 1024];
__device__ float g_ws[64 * 1024 * 16];                 // [b][d][h]
__device__ float g_scores_part[4][64 * 16 * 2048];     // [dq][b][h][s]
__device__ float g_attn[64 * 2048 * 16];               // [b][s][h]
__device__ float g_vbar_part[8][64 * 16 * 1024];       // [sq][b][h][d]
__device__ float g_concat[64 * 1024];
__device__ float g_outpre[64 * 1024];

__device__ __forceinline__ ull pk2(float x, float y) {
    ull r; asm("mov.b64 %0, {%1,%2};" : "=l"(r) : "f"(x), "f"(y)); return r;
}
__device__ __forceinline__ void upk2(float& x, float& y, ull v) {
    asm("mov.b64 {%0,%1}, %2;" : "=f"(x), "=f"(y) : "l"(v));
}
__device__ __forceinline__ ull fma2(ull a, ull b, ull c) {
    ull d; asm("fma.rn.f32x2 %0, %1, %2, %3;" : "=l"(d) : "l"(a), "l"(b), "l"(c)); return d;
}
__device__ __forceinline__ ull add2(ull a, ull b) {
    ull c; asm("add.rn.f32x2 %0, %1, %2;" : "=l"(c) : "l"(a), "l"(b)); return c;
}

__global__ __launch_bounds__(256) void k_init(const float* __restrict__ bq,
                                              const float* __restrict__ bv,
                                              const float* __restrict__ bo) {
    int i = blockIdx.x * 256 + threadIdx.x;
    int c = i & 1023;
    g_qh[i] = bq[c]; g_concat[i] = bv[c]; g_outpre[i] = bo[c];
}

// C[64,1024] += A[64,1024] @ W[1024,1024]; 16-way k-split over by (64 d each),
// 64-col tiles over bx. mode 0: A=q -> g_qh | mode 1: A=sum of vbar partials
// (head-sliced, h=bx) -> g_concat | mode 2: A=g_concat -> g_outpre
__global__ __launch_bounds__(256) void gemm_ksplit(const float* __restrict__ Ain,
                                                   const float* __restrict__ W, int mode) {
    __shared__ float As[64 * 68];
    __shared__ float Wsm[64 * 64];
    int bx = blockIdx.x, by = blockIdx.y, tid = threadIdx.x;
    int col0 = bx * 64, db = by * 64;

    if (mode == 1) {
        for (int idx = tid; idx < 4096; idx += 256) {
            int bb = idx >> 6, dd = idx & 63;
            size_t off = (size_t)bb * 16384 + (size_t)bx * 1024 + db + dd;
            float s = 0.f;
            #pragma unroll
            for (int p = 0; p < 8; p++) s += g_vbar_part[p][off];
            As[bb * 68 + dd] = s;
        }
    } else {
        const float* A = (mode == 0) ? Ain : g_concat;
        for (int idx = tid; idx < 4096; idx += 256) {
            int bb = idx >> 6, dd = idx & 63;
            As[bb * 68 + dd] = A[(size_t)bb * 1024 + db + dd];
        }
    }
    for (int idx = tid; idx < 4096; idx += 256) {
        int dd = idx >> 6, j = idx & 63;
        Wsm[dd * 64 + j] = W[(size_t)(db + dd) * 1024 + col0 + j];
    }
    __syncthreads();

    int tj = tid & 15, tb = tid >> 4;
    float acc[4][4] = {};
    const float4* Ws4 = (const float4*)Wsm;
    #pragma unroll 8
    for (int dd = 0; dd < 64; dd++) {
        float4 w = Ws4[dd * 16 + tj];
        #pragma unroll
        for (int bb = 0; bb < 4; bb++) {
            float a = As[(tb * 4 + bb) * 68 + dd];
            acc[bb][0] = fmaf(a, w.x, acc[bb][0]);
            acc[bb][1] = fmaf(a, w.y, acc[bb][1]);
            acc[bb][2] = fmaf(a, w.z, acc[bb][2]);
            acc[bb][3] = fmaf(a, w.w, acc[bb][3]);
        }
    }
    float* C = (mode == 0) ? g_qh : (mode == 1) ? g_concat : g_outpre;
    #pragma unroll
    for (int bb = 0; bb < 4; bb++)
        #pragma unroll
        for (int jj = 0; jj < 4; jj++)
            atomicAdd(&C[(size_t)(tb * 4 + bb) * 1024 + col0 + tj * 4 + jj], acc[bb][jj]);
}

// g_ws[b][d][h] = 0.125 * sum_j Wk[d, 64h+j] * g_qh[b, 64h+j]; grid (16 dt, 8 bt, 4 hz)
__global__ __launch_bounds__(256) void k_ws(const float* __restrict__ Wk) {
    __shared__ float Wks[64 * 68];
    __shared__ float qhs[8 * 64];
    int dt = blockIdx.x, bt = blockIdx.y, hz = blockIdx.z, tid = threadIdx.x;
    int td = tid & 63, tg = tid >> 6;
    for (int hi = 0; hi < 4; hi++) {
        int h = hz * 4 + hi;
        __syncthreads();
        for (int idx = tid; idx < 4096; idx += 256) {
            int dd = idx >> 6, j = idx & 63;
            Wks[dd * 68 + j] = Wk[(size_t)(dt * 64 + dd) * 1024 + h * 64 + j];
        }
        for (int idx = tid; idx < 512; idx += 256) {
            int bb = idx >> 6, j = idx & 63;
            qhs[bb * 64 + j] = g_qh[(size_t)(bt * 8 + bb) * 1024 + h * 64 + j];
        }
        __syncthreads();
        float a0 = 0.f, a1 = 0.f;
        #pragma unroll
        for (int j4 = 0; j4 < 16; j4++) {
            float4 w  = *(const float4*)&Wks[td * 68 + j4 * 4];
            float4 qa = *(const float4*)&qhs[(tg * 2 + 0) * 64 + j4 * 4];
            float4 qb = *(const float4*)&qhs[(tg * 2 + 1) * 64 + j4 * 4];
            a0 = fmaf(w.x, qa.x, fmaf(w.y, qa.y, fmaf(w.z, qa.z, fmaf(w.w, qa.w, a0))));
            a1 = fmaf(w.x, qb.x, fmaf(w.y, qb.y, fmaf(w.z, qb.z, fmaf(w.w, qb.w, a1))));
        }
        int d = dt * 64 + td;
        g_ws[((size_t)(bt * 8 + tg * 2 + 0) * 1024 + d) * 16 + h] = a0 * 0.125f;
        g_ws[((size_t)(bt * 8 + tg * 2 + 1) * 1024 + d) * 16 + h] = a1 * 0.125f;
    }
}

// ---------------- pass 1: stream k -> partial scores ----------------
// grid (64 b, 8 st, 4 dq). Thread (dg=tid>>6, r=tid&63): rows {r,r+64,r+128,r+192},
// d-range = dq*256 + dg*64 (16 chunks of 4 d). k stays in registers (direct LDG,
// L1-reuses each 128B line across 8 chunks). w read as broadcast LDS.128.
// dyn smem: ws_s[4096 f] + sred[4096 ull] = 49152 B.
__global__ __launch_bounds__(256, 2) void k_scores(const float* __restrict__ k) {
    extern __shared__ float sm[];
    float* ws_s = sm;                       // [256 d][16 h] slice for (b, dq)
    ull* sred = (ull*)(sm + 4096);          // reduction buffer
    const int b = blockIdx.x, st = blockIdx.y, dq = blockIdx.z;
    const int tid = threadIdx.x;
    const int dg = tid >> 6, r = tid & 63;

    {
        const float4* src = (const float4*)(g_ws + (size_t)b * 16384 + dq * 4096);
        float4* dst = (float4*)ws_s;
        #pragma unroll
        for (int i = 0; i < 4; i++) dst[tid + i * 256] = src[tid + i * 256];
    }

    const float4* k4 = (const float4*)k;
    // float4 units: row stride 256; this thread's d-offset in f4 = dq*64 + dg*16
    const size_t base = ((size_t)b * 2048 + st * 256) * 256 + dq * 64 + dg * 16;

    float4 cur[4], nxt[4];
    #pragma unroll
    for (int i = 0; i < 4; i++)
        cur[i] = k4[base + (size_t)(r + 64 * i) * 256];

    ull acc[4][8];
    #pragma unroll
    for (int i = 0; i < 4; i++)
        #pragma unroll
        for (int p = 0; p < 8; p++) acc[i][p] = 0ull;

    __syncthreads();
    const ulonglong2* wq = (const ulonglong2*)ws_s;  // [d][4 x ulonglong2]

    for (int c = 0; c < 16; c++) {
        if (c < 15) {
            #pragma unroll
            for (int i = 0; i < 4; i++)
                nxt[i] = k4[base + (size_t)(r + 64 * i) * 256 + c + 1];
        }
        #pragma unroll
        for (int j = 0; j < 4; j++) {
            const int dd = dg * 64 + c * 4 + j;
            ulonglong2 p0 = wq[dd * 4 + 0], p1 = wq[dd * 4 + 1];
            ulonglong2 p2 = wq[dd * 4 + 2], p3 = wq[dd * 4 + 3];
            #pragma unroll
            for (int i = 0; i < 4; i++) {
                float kv = ((const float*)&cur[i])[j];
                ull kk = pk2(kv, kv);
                acc[i][0] = fma2(kk, p0.x, acc[i][0]);
                acc[i][1] = fma2(kk, p0.y, acc[i][1]);
                acc[i][2] = fma2(kk, p1.x, acc[i][2]);
                acc[i][3] = fma2(kk, p1.y, acc[i][3]);
                acc[i][4] = fma2(kk, p2.x, acc[i][4]);
                acc[i][5] = fma2(kk, p2.y, acc[i][5]);
                acc[i][6] = fma2(kk, p3.x, acc[i][6]);
                acc[i][7] = fma2(kk, p3.y, acc[i][7]);
            }
        }
        #pragma unroll
        for (int i = 0; i < 4; i++) cur[i] = nxt[i];
    }

    // reduce over the 4 dg groups: 2 smem waves of 4 h-pairs
    float* outp = g_scores_part[dq];
    const int s = st * 256 + tid;
    #pragma unroll
    for (int w = 0; w < 2; w++) {
        __syncthreads();
        #pragma unroll
        for (int i = 0; i < 4; i++)
            #pragma unroll
            for (int pp = 0; pp < 4; pp++)
                sred[dg * 1024 + (r + 64 * i) * 4 + pp] = acc[i][4 * w + pp];
        __syncthreads();
        #pragma unroll
        for (int jj = 0; jj < 4; jj++) {
            ull s0 = sred[0 * 1024 + tid * 4 + jj];
            ull s1 = sred[1 * 1024 + tid * 4 + jj];
            ull s2 = sred[2 * 1024 + tid * 4 + jj];
            ull s3 = sred[3 * 1024 + tid * 4 + jj];
            ull tsum = add2(add2(s0, s1), add2(s2, s3));
            float lo, hi; upk2(lo, hi, tsum);
            int h = (4 * w + jj) * 2;
            outp[(size_t)(b * 16 + h) * 2048 + s]     = lo;
            outp[(size_t)(b * 16 + h + 1) * 2048 + s] = hi;
        }
    }
}

// softmax over s per (b,h); sums 4 d-partials; write attn[b][s][h]
__global__ __launch_bounds__(256) void k_softmax() {
    int b = blockIdx.x, h = blockIdx.y, tid = threadIdx.x;
    size_t off = (size_t)(b * 16 + h) * 2048;
    float x[8], m = -1e30f;
    #pragma unroll
    for (int i = 0; i < 8; i++) {
        int s = tid + i * 256;
        float v = g_scores_part[0][off + s] + g_scores_part[1][off + s]
                + g_scores_part[2][off + s] + g_scores_part[3][off + s];
        x[i] = v; m = fmaxf(m, v);
    }
    __shared__ float red[8];
    #pragma unroll
    for (int o = 16; o; o >>= 1) m = fmaxf(m, __shfl_xor_sync(0xffffffffu, m, o));
    if ((tid & 31) == 0) red[tid >> 5] = m;
    __syncthreads();
    float M = red[0];
    #pragma unroll
    for (int i = 1; i < 8; i++) M = fmaxf(M, red[i]);
    __syncthreads();
    float ssum = 0.f;
    #pragma unroll
    for (int i = 0; i < 8; i++) { x[i] = __expf(x[i] - M); ssum += x[i]; }
    #pragma unroll
    for (int o = 16; o; o >>= 1) ssum += __shfl_xor_sync(0xffffffffu, ssum, o);
    if ((tid & 31) == 0) red[tid >> 5] = ssum;
    __syncthreads();
    float T = 0.f;
    #pragma unroll
    for (int i = 0; i < 8; i++) T += red[i];
    float inv = 1.0f / T;
    #pragma unroll
    for (int i = 0; i < 8; i++)
        g_attn[((size_t)b * 2048 + tid + i * 256) * 16 + h] = x[i] * inv;
}

// ---------------- pass 2: stream v -> partial vbar ----------------
// grid (64 b, 8 sq). CTA: 256 s (4 blocks of 64), all 1024 d. Thread owns 4
// consecutive d. h-PAIRED: fma2((a_h0,a_h1),(v,v)) -> attn read raw (no dup),
// 4 broadcast LDS.128 per s. v via coalesced LDG.128 with 4-deep reg prefetch.
__global__ __launch_bounds__(256, 2) void k_vbar(const float* __restrict__ v) {
    __shared__ __align__(16) float abuf[2][1024];   // 64 s x 16 h, raw
    const int b = blockIdx.x, sq = blockIdx.y;
    const int tid = threadIdx.x;
    const int d0 = tid * 4;
    const size_t sBase = (size_t)b * 2048 + sq * 256;

    ull acc[4][8];
    #pragma unroll
    for (int d = 0; d < 4; d++)
        #pragma unroll
        for (int hp = 0; hp < 8; hp++) acc[d][hp] = 0ull;

    const float4* v4 = (const float4*)v;
    const float4* attn4 = (const float4*)g_attn;
    const size_t vbase = sBase * 256 + tid;   // float4 units

    // stage attn block 0; preload v group 0 (s = 0..3)
    ((float4*)abuf[0])[tid] = attn4[sBase * 4 + tid];
    float4 cur[4], nxt[4];
    #pragma unroll
    for (int i = 0; i < 4; i++) cur[i] = v4[vbase + (size_t)i * 256];
    __syncthreads();

    for (int blk = 0; blk < 4; blk++) {
        if (blk < 3)
            ((float4*)abuf[(blk + 1) & 1])[tid] = attn4[(sBase + (blk + 1) * 64) * 4 + tid];
        const float* ab = abuf[blk & 1];
        for (int g = 0; g < 16; g++) {
            if (!(blk == 3 && g == 15)) {
                int snext = blk * 64 + g * 4 + 4;
                #pragma unroll
                for (int i = 0; i < 4; i++)
                    nxt[i] = v4[vbase + (size_t)(snext + i) * 256];
            }
            #pragma unroll
            for (int i = 0; i < 4; i++) {
                int s = g * 4 + i;
                ulonglong2 a01 = *(const ulonglong2*)&ab[s * 16 + 0];
                ulonglong2 a23 = *(const ulonglong2*)&ab[s * 16 + 4];
                ulonglong2 a45 = *(const ulonglong2*)&ab[s * 16 + 8];
                ulonglong2 a67 = *(const ulonglong2*)&ab[s * 16 + 12];
                float4 vv = cur[i];
                ull v0 = pk2(vv.x, vv.x), v1 = pk2(vv.y, vv.y);
                ull v2 = pk2(vv.z, vv.z), v3 = pk2(vv.w, vv.w);
                acc[0][0] = fma2(a01.x, v0, acc[0][0]); acc[1][0] = fma2(a01.x, v1, acc[1][0]);
                acc[2][0] = fma2(a01.x, v2, acc[2][0]); acc[3][0] = fma2(a01.x, v3, acc[3][0]);
                acc[0][1] = fma2(a01.y, v0, acc[0][1]); acc[1][1] = fma2(a01.y, v1, acc[1][1]);
                acc[2][1] = fma2(a01.y, v2, acc[2][1]); acc[3][1] = fma2(a01.y, v3, acc[3][1]);
                acc[0][2] = fma2(a23.x, v0, acc[0][2]); acc[1][2] = fma2(a23.x, v1, acc[1][2]);
                acc[2][2] = fma2(a23.x, v2, acc[2][2]); acc[3][2] = fma2(a23.x, v3, acc[3][2]);
                acc[0][3] = fma2(a23.y, v0, acc[0][3]); acc[1][3] = fma2(a23.y, v1, acc[1][3]);
                acc[2][3] = fma2(a23.y, v2, acc[2][3]); acc[3][3] = fma2(a23.y, v3, acc[3][3]);
                acc[0][4] = fma2(a45.x, v0, acc[0][4]); acc[1][4] = fma2(a45.x, v1, acc[1][4]);
                acc[2][4] = fma2(a45.x, v2, acc[2][4]); acc[3][4] = fma2(a45.x, v3, acc[3][4]);
                acc[0][5] = fma2(a45.y, v0, acc[0][5]); acc[1][5] = fma2(a45.y, v1, acc[1][5]);
                acc[2][5] = fma2(a45.y, v2, acc[2][5]); acc[3][5] = fma2(a45.y, v3, acc[3][5]);
                acc[0][6] = fma2(a67.x, v0, acc[0][6]); acc[1][6] = fma2(a67.x, v1, acc[1][6]);
                acc[2][6] = fma2(a67.x, v2, acc[2][6]); acc[3][6] = fma2(a67.x, v3, acc[3][6]);
                acc[0][7] = fma2(a67.y, v0, acc[0][7]); acc[1][7] = fma2(a67.y, v1, acc[1][7]);
                acc[2][7] = fma2(a67.y, v2, acc[2][7]); acc[3][7] = fma2(a67.y, v3, acc[3][7]);
            }
            #pragma unroll
            for (int i = 0; i < 4; i++) cur[i] = nxt[i];
        }
        __syncthreads();
    }

    float* outp = g_vbar_part[sq] + (size_t)b * 16384;
    #pragma unroll
    for (int hp = 0; hp < 8; hp++) {
        float lo0, hi0, lo1, hi1, lo2, hi2, lo3, hi3;
        upk2(lo0, hi0, acc[0][hp]); upk2(lo1, hi1, acc[1][hp]);
        upk2(lo2, hi2, acc[2][hp]); upk2(lo3, hi3, acc[3][hp]);
        float4 e; e.x = lo0; e.y = lo1; e.z = lo2; e.w = lo3;
        float4 o; o.x = hi0; o.y = hi1; o.z = hi2; o.w = hi3;
        *(float4*)&outp[(size_t)(2 * hp) * 1024 + d0]     = e;
        *(float4*)&outp[(size_t)(2 * hp + 1) * 1024 + d0] = o;
    }
}

__global__ __launch_bounds__(256) void k_relu(float* __restrict__ out) {
    int i = blockIdx.x * 256 + threadIdx.x;
    out[i] = fmaxf(g_outpre[i], 0.0f);
}

extern "C" void kernel_launch(void* const* d_in, const int* in_sizes, int n_in,
                              void* d_out, int out_size) {
    const float* q  = (const float*)d_in[0];
    const float* k  = (const float*)d_in[1];
    const float* v  = (const float*)d_in[2];
    const float* Wq = (const float*)d_in[3];
    const float* bq = (const float*)d_in[4];
    const float* Wk = (const float*)d_in[5];
    // d_in[6] = bk — cancels in softmax
    const float* Wv = (const float*)d_in[7];
    const float* bv = (const float*)d_in[8];
    const float* Wo = (const float*)d_in[9];
    const float* bo = (const float*)d_in[10];

    const int smem_scores = 4096 * 4 + 4096 * 8;  // 49152
    static bool attr_done = false;
    if (!attr_done) {
        cudaFuncSetAttribute(k_scores, cudaFuncAttributeMaxDynamicSharedMemorySize, smem_scores);
        attr_done = true;
    }

    k_init<<<256, 256>>>(bq, bv, bo);
    gemm_ksplit<<<dim3(16, 16), 256>>>(q, Wq, 0);
    k_ws<<<dim3(16, 8, 4), 256>>>(Wk);
    k_scores<<<dim3(64, 8, 4), 256, smem_scores>>>(k);
    k_softmax<<<dim3(64, 16), 256>>>();
    k_vbar<<<dim3(64, 8), 256>>>(v);
    gemm_ksplit<<<dim3(16, 16), 256>>>(nullptr, Wv, 1);
    gemm_ksplit<<<dim3(16, 16), 256>>>(nullptr, Wo, 2);
    k_relu<<<256, 256>>>((float*)d_out);
}

// round 6
// speedup vs baseline: 2.5700x; 1.0243x over previous
#include <cuda_runtime.h>
#include <cstdint>
#include <cstddef>

typedef unsigned long long ull;

// device scratch (allocs forbidden)
__device__ float g_qh[64 * 1024];
__device__ float g_ws[64 * 1024 * 16];                 // [b][d][h]
__device__ float g_scores_part[4][64 * 16 * 2048];     // [dq][b][h][s]
__device__ float g_attn[64 * 2048 * 16];               // [b][s][h]
__device__ float g_vbar_part[16][64 * 16 * 1024];      // [sq][b][h][d]
__device__ float g_concat[64 * 1024];
__device__ float g_outpre[64 * 1024];

__device__ __forceinline__ ull pk2(float x, float y) {
    ull r; asm("mov.b64 %0, {%1,%2};" : "=l"(r) : "f"(x), "f"(y)); return r;
}
__device__ __forceinline__ void upk2(float& x, float& y, ull v) {
    asm("mov.b64 {%0,%1}, %2;" : "=f"(x), "=f"(y) : "l"(v));
}
__device__ __forceinline__ ull fma2(ull a, ull b, ull c) {
    ull d; asm("fma.rn.f32x2 %0, %1, %2, %3;" : "=l"(d) : "l"(a), "l"(b), "l"(c)); return d;
}
__device__ __forceinline__ ull add2(ull a, ull b) {
    ull c; asm("add.rn.f32x2 %0, %1, %2;" : "=l"(c) : "l"(a), "l"(b)); return c;
}

__global__ __launch_bounds__(256) void k_init(const float* __restrict__ bq,
                                              const float* __restrict__ bv,
                                              const float* __restrict__ bo) {
    int i = blockIdx.x * 256 + threadIdx.x;
    int c = i & 1023;
    g_qh[i] = bq[c]; g_concat[i] = bv[c]; g_outpre[i] = bo[c];
}

// C[64,1024] += A[64,1024] @ W[1024,1024]; 16-way k-split over by (64 d each),
// 64-col tiles over bx. mode 0: A=q -> g_qh | mode 1: A=sum of 16 vbar partials
// (head-sliced, h=bx) -> g_concat | mode 2: A=g_concat -> g_outpre
__global__ __launch_bounds__(256) void gemm_ksplit(const float* __restrict__ Ain,
                                                   const float* __restrict__ W, int mode) {
    __shared__ float As[64 * 68];
    __shared__ float Wsm[64 * 64];
    int bx = blockIdx.x, by = blockIdx.y, tid = threadIdx.x;
    int col0 = bx * 64, db = by * 64;

    if (mode == 1) {
        for (int idx = tid; idx < 4096; idx += 256) {
            int bb = idx >> 6, dd = idx & 63;
            size_t off = (size_t)bb * 16384 + (size_t)bx * 1024 + db + dd;
            float s = 0.f;
            #pragma unroll
            for (int p = 0; p < 16; p++) s += g_vbar_part[p][off];
            As[bb * 68 + dd] = s;
        }
    } else {
        const float* A = (mode == 0) ? Ain : g_concat;
        for (int idx = tid; idx < 4096; idx += 256) {
            int bb = idx >> 6, dd = idx & 63;
            As[bb * 68 + dd] = A[(size_t)bb * 1024 + db + dd];
        }
    }
    for (int idx = tid; idx < 4096; idx += 256) {
        int dd = idx >> 6, j = idx & 63;
        Wsm[dd * 64 + j] = W[(size_t)(db + dd) * 1024 + col0 + j];
    }
    __syncthreads();

    int tj = tid & 15, tb = tid >> 4;
    float acc[4][4] = {};
    const float4* Ws4 = (const float4*)Wsm;
    #pragma unroll 8
    for (int dd = 0; dd < 64; dd++) {
        float4 w = Ws4[dd * 16 + tj];
        #pragma unroll
        for (int bb = 0; bb < 4; bb++) {
            float a = As[(tb * 4 + bb) * 68 + dd];
            acc[bb][0] = fmaf(a, w.x, acc[bb][0]);
            acc[bb][1] = fmaf(a, w.y, acc[bb][1]);
            acc[bb][2] = fmaf(a, w.z, acc[bb][2]);
            acc[bb][3] = fmaf(a, w.w, acc[bb][3]);
        }
    }
    float* C = (mode == 0) ? g_qh : (mode == 1) ? g_concat : g_outpre;
    #pragma unroll
    for (int bb = 0; bb < 4; bb++)
        #pragma unroll
        for (int jj = 0; jj < 4; jj++)
            atomicAdd(&C[(size_t)(tb * 4 + bb) * 1024 + col0 + tj * 4 + jj], acc[bb][jj]);
}

// g_ws[b][d][h] = 0.125 * sum_j Wk[d, 64h+j] * g_qh[b, 64h+j]; grid (16 dt, 8 bt, 4 hz)
__global__ __launch_bounds__(256) void k_ws(const float* __restrict__ Wk) {
    __shared__ float Wks[64 * 68];
    __shared__ float qhs[8 * 64];
    int dt = blockIdx.x, bt = blockIdx.y, hz = blockIdx.z, tid = threadIdx.x;
    int td = tid & 63, tg = tid >> 6;
    for (int hi = 0; hi < 4; hi++) {
        int h = hz * 4 + hi;
        __syncthreads();
        for (int idx = tid; idx < 4096; idx += 256) {
            int dd = idx >> 6, j = idx & 63;
            Wks[dd * 68 + j] = Wk[(size_t)(dt * 64 + dd) * 1024 + h * 64 + j];
        }
        for (int idx = tid; idx < 512; idx += 256) {
            int bb = idx >> 6, j = idx & 63;
            qhs[bb * 64 + j] = g_qh[(size_t)(bt * 8 + bb) * 1024 + h * 64 + j];
        }
        __syncthreads();
        float a0 = 0.f, a1 = 0.f;
        #pragma unroll
        for (int j4 = 0; j4 < 16; j4++) {
            float4 w  = *(const float4*)&Wks[td * 68 + j4 * 4];
            float4 qa = *(const float4*)&qhs[(tg * 2 + 0) * 64 + j4 * 4];
            float4 qb = *(const float4*)&qhs[(tg * 2 + 1) * 64 + j4 * 4];
            a0 = fmaf(w.x, qa.x, fmaf(w.y, qa.y, fmaf(w.z, qa.z, fmaf(w.w, qa.w, a0))));
            a1 = fmaf(w.x, qb.x, fmaf(w.y, qb.y, fmaf(w.z, qb.z, fmaf(w.w, qb.w, a1))));
        }
        int d = dt * 64 + td;
        g_ws[((size_t)(bt * 8 + tg * 2 + 0) * 1024 + d) * 16 + h] = a0 * 0.125f;
        g_ws[((size_t)(bt * 8 + tg * 2 + 1) * 1024 + d) * 16 + h] = a1 * 0.125f;
    }
}

// ---------------- pass 1: stream k -> partial scores ----------------
// grid (64 b, 16 st, 4 dq). CTA tile: 128 s x 256 d, 4 chunks of 64 d.
// k staged in smem natural layout [row][17 f4] (pad -> conflict-free LDS),
// loaded fully coalesced (each 128B line read exactly once). Thread
// (dg=tid>>5, r=tid&31): rows {r,r+32,r+64,r+96}, d-slice dg*8..dg*8+7/chunk.
// dyn smem: ws_s[4096 f] (16KB) + k_s[2][128][17 f4] (69632 B) = 86016 B.
__global__ __launch_bounds__(256, 2) void k_scores(const float* __restrict__ k) {
    extern __shared__ float sm[];
    float* ws_s = sm;                          // [256 d][16 h] slice for (b, dq)
    float4* k_s = (float4*)(sm + 4096);        // 2 bufs x 128 rows x 17 f4
    const int b = blockIdx.x, st = blockIdx.y, dq = blockIdx.z;
    const int tid = threadIdx.x;
    const int dg = tid >> 5, r = tid & 31;

    {   // stage ws slice (coalesced)
        const float4* src = (const float4*)(g_ws + (size_t)b * 16384 + dq * 4096);
        float4* dst = (float4*)ws_s;
        #pragma unroll
        for (int i = 0; i < 4; i++) dst[tid + i * 256] = src[tid + i * 256];
    }

    const float4* k4 = (const float4*)k;
    // element idx -> row = idx>>4, col = idx&15 (16 f4 per 64-d chunk row)
    const size_t gbase = ((size_t)b * 2048 + st * 128) * 256 + dq * 64;

    float4 stg[8];
    #pragma unroll
    for (int i = 0; i < 8; i++) {
        int idx = tid + i * 256;
        stg[i] = k4[gbase + (size_t)(idx >> 4) * 256 + (idx & 15)];
    }
    #pragma unroll
    for (int i = 0; i < 8; i++) {
        int idx = tid + i * 256;
        k_s[(idx >> 4) * 17 + (idx & 15)] = stg[i];
    }

    ull acc[4][8];
    #pragma unroll
    for (int i = 0; i < 4; i++)
        #pragma unroll
        for (int p = 0; p < 8; p++) acc[i][p] = 0ull;

    __syncthreads();
    const ulonglong2* wq = (const ulonglong2*)ws_s;   // [d][4 ulonglong2]

    for (int c = 0; c < 4; c++) {
        if (c < 3) {
            #pragma unroll
            for (int i = 0; i < 8; i++) {
                int idx = tid + i * 256;
                stg[i] = k4[gbase + (size_t)(idx >> 4) * 256 + (c + 1) * 16 + (idx & 15)];
            }
        }
        const float4* kb = k_s + (c & 1) * (128 * 17);
        #pragma unroll
        for (int jj = 0; jj < 2; jj++) {
            float4 kv[4];
            #pragma unroll
            for (int i = 0; i < 4; i++)
                kv[i] = kb[(r + 32 * i) * 17 + dg * 2 + jj];
            #pragma unroll
            for (int dl = 0; dl < 4; dl++) {
                const int dd = c * 64 + dg * 8 + jj * 4 + dl;
                ulonglong2 p0 = wq[dd * 4 + 0], p1 = wq[dd * 4 + 1];
                ulonglong2 p2 = wq[dd * 4 + 2], p3 = wq[dd * 4 + 3];
                #pragma unroll
                for (int i = 0; i < 4; i++) {
                    float kf = ((const float*)&kv[i])[dl];
                    ull kk = pk2(kf, kf);
                    acc[i][0] = fma2(kk, p0.x, acc[i][0]);
                    acc[i][1] = fma2(kk, p0.y, acc[i][1]);
                    acc[i][2] = fma2(kk, p1.x, acc[i][2]);
                    acc[i][3] = fma2(kk, p1.y, acc[i][3]);
                    acc[i][4] = fma2(kk, p2.x, acc[i][4]);
                    acc[i][5] = fma2(kk, p2.y, acc[i][5]);
                    acc[i][6] = fma2(kk, p3.x, acc[i][6]);
                    acc[i][7] = fma2(kk, p3.y, acc[i][7]);
                }
            }
        }
        if (c < 3) {
            float4* nb = k_s + ((c + 1) & 1) * (128 * 17);
            #pragma unroll
            for (int i = 0; i < 8; i++) {
                int idx = tid + i * 256;
                nb[(idx >> 4) * 17 + (idx & 15)] = stg[i];
            }
        }
        __syncthreads();
    }

    // reduce over 8 dg groups: 2 smem waves of 4 h-pairs (reuse k_s region)
    ull* sred = (ull*)(sm + 4096);     // 4096 ull = 32 KB
    float* outp = g_scores_part[dq];
    #pragma unroll
    for (int w = 0; w < 2; w++) {
        __syncthreads();
        #pragma unroll
        for (int i = 0; i < 4; i++)
            #pragma unroll
            for (int pp = 0; pp < 4; pp++)
                sred[dg * 512 + (r + 32 * i) * 4 + pp] = acc[i][4 * w + pp];
        __syncthreads();
        const int row = tid >> 1, pb = (tid & 1) * 2;
        const int s = st * 128 + row;
        #pragma unroll
        for (int jj = 0; jj < 2; jj++) {
            int pp = pb + jj;
            ull t0 = add2(sred[0 * 512 + row * 4 + pp], sred[1 * 512 + row * 4 + pp]);
            ull t1 = add2(sred[2 * 512 + row * 4 + pp], sred[3 * 512 + row * 4 + pp]);
            ull t2 = add2(sred[4 * 512 + row * 4 + pp], sred[5 * 512 + row * 4 + pp]);
            ull t3 = add2(sred[6 * 512 + row * 4 + pp], sred[7 * 512 + row * 4 + pp]);
            ull t = add2(add2(t0, t1), add2(t2, t3));
            float lo, hi; upk2(lo, hi, t);
            int h = (4 * w + pp) * 2;
            outp[(size_t)(b * 16 + h) * 2048 + s]     = lo;
            outp[(size_t)(b * 16 + h + 1) * 2048 + s] = hi;
        }
    }
}

// softmax over s per (b,h); sums 4 d-partials; write attn[b][s][h]
__global__ __launch_bounds__(256) void k_softmax() {
    int b = blockIdx.x, h = blockIdx.y, tid = threadIdx.x;
    size_t off = (size_t)(b * 16 + h) * 2048;
    float x[8], m = -1e30f;
    #pragma unroll
    for (int i = 0; i < 8; i++) {
        int s = tid + i * 256;
        float v = g_scores_part[0][off + s] + g_scores_part[1][off + s]
                + g_scores_part[2][off + s] + g_scores_part[3][off + s];
        x[i] = v; m = fmaxf(m, v);
    }
    __shared__ float red[8];
    #pragma unroll
    for (int o = 16; o; o >>= 1) m = fmaxf(m, __shfl_xor_sync(0xffffffffu, m, o));
    if ((tid & 31) == 0) red[tid >> 5] = m;
    __syncthreads();
    float M = red[0];
    #pragma unroll
    for (int i = 1; i < 8; i++) M = fmaxf(M, red[i]);
    __syncthreads();
    float ssum = 0.f;
    #pragma unroll
    for (int i = 0; i < 8; i++) { x[i] = __expf(x[i] - M); ssum += x[i]; }
    #pragma unroll
    for (int o = 16; o; o >>= 1) ssum += __shfl_xor_sync(0xffffffffu, ssum, o);
    if ((tid & 31) == 0) red[tid >> 5] = ssum;
    __syncthreads();
    float T = 0.f;
    #pragma unroll
    for (int i = 0; i < 8; i++) T += red[i];
    float inv = 1.0f / T;
    #pragma unroll
    for (int i = 0; i < 8; i++)
        g_attn[((size_t)b * 2048 + tid + i * 256) * 16 + h] = x[i] * inv;
}

// ---------------- pass 2: stream v -> partial vbar ----------------
// grid (64 b, 16 sq). CTA: 128 s (2 blocks of 64), all 1024 d. Thread owns 4
// consecutive d; h-paired fma2 with raw broadcast attn LDS; coalesced v LDG
// with 4-deep register prefetch.
__global__ __launch_bounds__(256, 2) void k_vbar(const float* __restrict__ v) {
    __shared__ __align__(16) float abuf[2][1024];   // 64 s x 16 h
    const int b = blockIdx.x, sq = blockIdx.y;
    const int tid = threadIdx.x;
    const int d0 = tid * 4;
    const size_t sBase = (size_t)b * 2048 + sq * 128;

    ull acc[4][8];
    #pragma unroll
    for (int d = 0; d < 4; d++)
        #pragma unroll
        for (int hp = 0; hp < 8; hp++) acc[d][hp] = 0ull;

    const float4* v4 = (const float4*)v;
    const float4* attn4 = (const float4*)g_attn;
    const size_t vbase = sBase * 256 + tid;   // float4 units

    ((float4*)abuf[0])[tid] = attn4[sBase * 4 + tid];
    float4 cur[4], nxt[4];
    #pragma unroll
    for (int i = 0; i < 4; i++) cur[i] = v4[vbase + (size_t)i * 256];
    __syncthreads();

    for (int blk = 0; blk < 2; blk++) {
        if (blk < 1)
            ((float4*)abuf[1])[tid] = attn4[(sBase + 64) * 4 + tid];
        const float* ab = abuf[blk];
        for (int g = 0; g < 16; g++) {
            if (!(blk == 1 && g == 15)) {
                int snext = blk * 64 + g * 4 + 4;
                #pragma unroll
                for (int i = 0; i < 4; i++)
                    nxt[i] = v4[vbase + (size_t)(snext + i) * 256];
            }
            #pragma unroll
            for (int i = 0; i < 4; i++) {
                int s = g * 4 + i;
                ulonglong2 a01 = *(const ulonglong2*)&ab[s * 16 + 0];
                ulonglong2 a23 = *(const ulonglong2*)&ab[s * 16 + 4];
                ulonglong2 a45 = *(const ulonglong2*)&ab[s * 16 + 8];
                ulonglong2 a67 = *(const ulonglong2*)&ab[s * 16 + 12];
                float4 vv = cur[i];
                ull v0 = pk2(vv.x, vv.x), v1 = pk2(vv.y, vv.y);
                ull v2 = pk2(vv.z, vv.z), v3 = pk2(vv.w, vv.w);
                acc[0][0] = fma2(a01.x, v0, acc[0][0]); acc[1][0] = fma2(a01.x, v1, acc[1][0]);
                acc[2][0] = fma2(a01.x, v2, acc[2][0]); acc[3][0] = fma2(a01.x, v3, acc[3][0]);
                acc[0][1] = fma2(a01.y, v0, acc[0][1]); acc[1][1] = fma2(a01.y, v1, acc[1][1]);
                acc[2][1] = fma2(a01.y, v2, acc[2][1]); acc[3][1] = fma2(a01.y, v3, acc[3][1]);
                acc[0][2] = fma2(a23.x, v0, acc[0][2]); acc[1][2] = fma2(a23.x, v1, acc[1][2]);
                acc[2][2] = fma2(a23.x, v2, acc[2][2]); acc[3][2] = fma2(a23.x, v3, acc[3][2]);
                acc[0][3] = fma2(a23.y, v0, acc[0][3]); acc[1][3] = fma2(a23.y, v1, acc[1][3]);
                acc[2][3] = fma2(a23.y, v2, acc[2][3]); acc[3][3] = fma2(a23.y, v3, acc[3][3]);
                acc[0][4] = fma2(a45.x, v0, acc[0][4]); acc[1][4] = fma2(a45.x, v1, acc[1][4]);
                acc[2][4] = fma2(a45.x, v2, acc[2][4]); acc[3][4] = fma2(a45.x, v3, acc[3][4]);
                acc[0][5] = fma2(a45.y, v0, acc[0][5]); acc[1][5] = fma2(a45.y, v1, acc[1][5]);
                acc[2][5] = fma2(a45.y, v2, acc[2][5]); acc[3][5] = fma2(a45.y, v3, acc[3][5]);
                acc[0][6] = fma2(a67.x, v0, acc[0][6]); acc[1][6] = fma2(a67.x, v1, acc[1][6]);
                acc[2][6] = fma2(a67.x, v2, acc[2][6]); acc[3][6] = fma2(a67.x, v3, acc[3][6]);
                acc[0][7] = fma2(a67.y, v0, acc[0][7]); acc[1][7] = fma2(a67.y, v1, acc[1][7]);
                acc[2][7] = fma2(a67.y, v2, acc[2][7]); acc[3][7] = fma2(a67.y, v3, acc[3][7]);
            }
            #pragma unroll
            for (int i = 0; i < 4; i++) cur[i] = nxt[i];
        }
        __syncthreads();
    }

    float* outp = g_vbar_part[sq] + (size_t)b * 16384;
    #pragma unroll
    for (int hp = 0; hp < 8; hp++) {
        float lo0, hi0, lo1, hi1, lo2, hi2, lo3, hi3;
        upk2(lo0, hi0, acc[0][hp]); upk2(lo1, hi1, acc[1][hp]);
        upk2(lo2, hi2, acc[2][hp]); upk2(lo3, hi3, acc[3][hp]);
        float4 e; e.x = lo0; e.y = lo1; e.z = lo2; e.w = lo3;
        float4 o; o.x = hi0; o.y = hi1; o.z = hi2; o.w = hi3;
        *(float4*)&outp[(size_t)(2 * hp) * 1024 + d0]     = e;
        *(float4*)&outp[(size_t)(2 * hp + 1) * 1024 + d0] = o;
    }
}

__global__ __launch_bounds__(256) void k_relu(float* __restrict__ out) {
    int i = blockIdx.x * 256 + threadIdx.x;
    out[i] = fmaxf(g_outpre[i], 0.0f);
}

extern "C" void kernel_launch(void* const* d_in, const int* in_sizes, int n_in,
                              void* d_out, int out_size) {
    const float* q  = (const float*)d_in[0];
    const float* k  = (const float*)d_in[1];
    const float* v  = (const float*)d_in[2];
    const float* Wq = (const float*)d_in[3];
    const float* bq = (const float*)d_in[4];
    const float* Wk = (const float*)d_in[5];
    // d_in[6] = bk — cancels in softmax
    const float* Wv = (const float*)d_in[7];
    const float* bv = (const float*)d_in[8];
    const float* Wo = (const float*)d_in[9];
    const float* bo = (const float*)d_in[10];

    const int smem_scores = 4096 * 4 + 2 * 128 * 17 * 16;  // 86016
    static bool attr_done = false;
    if (!attr_done) {
        cudaFuncSetAttribute(k_scores, cudaFuncAttributeMaxDynamicSharedMemorySize, smem_scores);
        attr_done = true;
    }

    k_init<<<256, 256>>>(bq, bv, bo);
    gemm_ksplit<<<dim3(16, 16), 256>>>(q, Wq, 0);
    k_ws<<<dim3(16, 8, 4), 256>>>(Wk);
    k_scores<<<dim3(64, 16, 4), 256, smem_scores>>>(k);
    k_softmax<<<dim3(64, 16), 256>>>();
    k_vbar<<<dim3(64, 16), 256>>>(v);
    gemm_ksplit<<<dim3(16, 16), 256>>>(nullptr, Wv, 1);
    gemm_ksplit<<<dim3(16, 16), 256>>>(nullptr, Wo, 2);
    k_relu<<<256, 256>>>((float*)d_out);
}

// round 7
// speedup vs baseline: 3.0463x; 1.1854x over previous
#include <cuda_runtime.h>
#include <cstdint>
#include <cstddef>

typedef unsigned long long ull;

// device scratch (allocs forbidden)
__device__ float g_qh[64 * 1024];
__device__ float g_ws[64 * 1024 * 16];                 // [b][d][h]
__device__ float g_scores_part[4][64 * 16 * 2048];     // [dq][b][h][s]
__device__ float g_attn[64 * 2048 * 16];               // [b][s][h]
__device__ float g_vbar_part[16][64 * 16 * 1024];      // [part][b][h][d]
__device__ float g_concat[64 * 1024];
__device__ float g_outpre[64 * 1024];

__device__ __forceinline__ ull pk2(float x, float y) {
    ull r; asm("mov.b64 %0, {%1,%2};" : "=l"(r) : "f"(x), "f"(y)); return r;
}
__device__ __forceinline__ void upk2(float& x, float& y, ull v) {
    asm("mov.b64 {%0,%1}, %2;" : "=f"(x), "=f"(y) : "l"(v));
}
__device__ __forceinline__ ull fma2(ull a, ull b, ull c) {
    ull d; asm("fma.rn.f32x2 %0, %1, %2, %3;" : "=l"(d) : "l"(a), "l"(b), "l"(c)); return d;
}
__device__ __forceinline__ ull add2(ull a, ull b) {
    ull c; asm("add.rn.f32x2 %0, %1, %2;" : "=l"(c) : "l"(a), "l"(b)); return c;
}
__device__ __forceinline__ unsigned smem_u32(const void* p) {
    return (unsigned)__cvta_generic_to_shared(p);
}
__device__ __forceinline__ void cpa16(unsigned s, const void* g) {
    asm volatile("cp.async.cg.shared.global [%0], [%1], 16;" :: "r"(s), "l"(g));
}
__device__ __forceinline__ void cpa_commit() {
    asm volatile("cp.async.commit_group;" ::: "memory");
}
template <int N> __device__ __forceinline__ void cpa_wait() {
    asm volatile("cp.async.wait_group %0;" :: "n"(N) : "memory");
}

__global__ __launch_bounds__(256) void k_init(const float* __restrict__ bq,
                                              const float* __restrict__ bv,
                                              const float* __restrict__ bo) {
    int i = blockIdx.x * 256 + threadIdx.x;
    int c = i & 1023;
    g_qh[i] = bq[c]; g_concat[i] = bv[c]; g_outpre[i] = bo[c];
}

// C[64,1024] += A[64,1024] @ W[1024,1024]; 16-way k-split over by, 64-col tiles over bx.
// mode 0: A=q -> g_qh | mode 1: A=sum of 16 vbar partials (head h=bx) -> g_concat
// mode 2: A=g_concat -> g_outpre
__global__ __launch_bounds__(256) void gemm_ksplit(const float* __restrict__ Ain,
                                                   const float* __restrict__ W, int mode) {
    __shared__ float As[64 * 68];
    __shared__ float Wsm[64 * 64];
    int bx = blockIdx.x, by = blockIdx.y, tid = threadIdx.x;
    int col0 = bx * 64, db = by * 64;

    if (mode == 1) {
        for (int idx = tid; idx < 4096; idx += 256) {
            int bb = idx >> 6, dd = idx & 63;
            size_t off = (size_t)bb * 16384 + (size_t)bx * 1024 + db + dd;
            float s = 0.f;
            #pragma unroll
            for (int p = 0; p < 16; p++) s += g_vbar_part[p][off];
            As[bb * 68 + dd] = s;
        }
    } else {
        const float* A = (mode == 0) ? Ain : g_concat;
        for (int idx = tid; idx < 4096; idx += 256) {
            int bb = idx >> 6, dd = idx & 63;
            As[bb * 68 + dd] = A[(size_t)bb * 1024 + db + dd];
        }
    }
    for (int idx = tid; idx < 4096; idx += 256) {
        int dd = idx >> 6, j = idx & 63;
        Wsm[dd * 64 + j] = W[(size_t)(db + dd) * 1024 + col0 + j];
    }
    __syncthreads();

    int tj = tid & 15, tb = tid >> 4;
    float acc[4][4] = {};
    const float4* Ws4 = (const float4*)Wsm;
    #pragma unroll 8
    for (int dd = 0; dd < 64; dd++) {
        float4 w = Ws4[dd * 16 + tj];
        #pragma unroll
        for (int bb = 0; bb < 4; bb++) {
            float a = As[(tb * 4 + bb) * 68 + dd];
            acc[bb][0] = fmaf(a, w.x, acc[bb][0]);
            acc[bb][1] = fmaf(a, w.y, acc[bb][1]);
            acc[bb][2] = fmaf(a, w.z, acc[bb][2]);
            acc[bb][3] = fmaf(a, w.w, acc[bb][3]);
        }
    }
    float* C = (mode == 0) ? g_qh : (mode == 1) ? g_concat : g_outpre;
    #pragma unroll
    for (int bb = 0; bb < 4; bb++)
        #pragma unroll
        for (int jj = 0; jj < 4; jj++)
            atomicAdd(&C[(size_t)(tb * 4 + bb) * 1024 + col0 + tj * 4 + jj], acc[bb][jj]);
}

// g_ws[b][d][h] = 0.125 * sum_j Wk[d, 64h+j] * g_qh[b, 64h+j]; grid (16 dt, 8 bt, 4 hz)
__global__ __launch_bounds__(256) void k_ws(const float* __restrict__ Wk) {
    __shared__ float Wks[64 * 68];
    __shared__ float qhs[8 * 64];
    int dt = blockIdx.x, bt = blockIdx.y, hz = blockIdx.z, tid = threadIdx.x;
    int td = tid & 63, tg = tid >> 6;
    for (int hi = 0; hi < 4; hi++) {
        int h = hz * 4 + hi;
        __syncthreads();
        for (int idx = tid; idx < 4096; idx += 256) {
            int dd = idx >> 6, j = idx & 63;
            Wks[dd * 68 + j] = Wk[(size_t)(dt * 64 + dd) * 1024 + h * 64 + j];
        }
        for (int idx = tid; idx < 512; idx += 256) {
            int bb = idx >> 6, j = idx & 63;
            qhs[bb * 64 + j] = g_qh[(size_t)(bt * 8 + bb) * 1024 + h * 64 + j];
        }
        __syncthreads();
        float a0 = 0.f, a1 = 0.f;
        #pragma unroll
        for (int j4 = 0; j4 < 16; j4++) {
            float4 w  = *(const float4*)&Wks[td * 68 + j4 * 4];
            float4 qa = *(const float4*)&qhs[(tg * 2 + 0) * 64 + j4 * 4];
            float4 qb = *(const float4*)&qhs[(tg * 2 + 1) * 64 + j4 * 4];
            a0 = fmaf(w.x, qa.x, fmaf(w.y, qa.y, fmaf(w.z, qa.z, fmaf(w.w, qa.w, a0))));
            a1 = fmaf(w.x, qb.x, fmaf(w.y, qb.y, fmaf(w.z, qb.z, fmaf(w.w, qb.w, a1))));
        }
        int d = dt * 64 + td;
        g_ws[((size_t)(bt * 8 + tg * 2 + 0) * 1024 + d) * 16 + h] = a0 * 0.125f;
        g_ws[((size_t)(bt * 8 + tg * 2 + 1) * 1024 + d) * 16 + h] = a1 * 0.125f;
    }
}

// ---------------- pass 1: stream k -> partial scores ----------------
// grid (64 b, 16 st, 4 dq). CTA tile: 128 s x 256 d, 16 chunks of 16 d.
// 6-stage cp.async ring; stage = [128 rows][5 f4] (col 4 pad, odd stride ->
// conflict-free LDS.128). Thread (dg=tid>>6, r=tid&63): rows {r, r+64},
// f4-col dg of each chunk (4 d). dyn smem = 16KB ws + 60KB ring = 77824 B.
__global__ __launch_bounds__(256, 2) void k_scores(const float* __restrict__ k) {
    extern __shared__ float sm[];
    float* ws_s = sm;                          // 4096 f: [256 d][16 h]
    float4* pipe = (float4*)(sm + 4096);       // 6 stages x 640 f4
    const int b = blockIdx.x, st = blockIdx.y, dq = blockIdx.z;
    const int tid = threadIdx.x;
    const int dg = tid >> 6, r = tid & 63;

    {   // stage ws slice (coalesced)
        const float4* src = (const float4*)(g_ws + (size_t)b * 16384 + dq * 4096);
        float4* dst = (float4*)ws_s;
        #pragma unroll
        for (int i = 0; i < 4; i++) dst[tid + i * 256] = src[tid + i * 256];
    }

    const float4* k4 = (const float4*)k;
    const size_t gbase = ((size_t)b * 2048 + st * 128) * 256 + dq * 64;   // f4 units
    const int row0 = tid >> 2, colx = tid & 3;
    const int row1 = (tid + 256) >> 2;
    const unsigned sbase = smem_u32(pipe);
    const unsigned soff0 = (unsigned)(row0 * 5 + colx) * 16u;
    const unsigned soff1 = (unsigned)(row1 * 5 + colx) * 16u;

#define KS_ISSUE(c) do { \
    unsigned sb = sbase + (unsigned)(((c) % 6) * 640) * 16u; \
    cpa16(sb + soff0, k4 + gbase + (size_t)row0 * 256 + (c) * 4 + colx); \
    cpa16(sb + soff1, k4 + gbase + (size_t)row1 * 256 + (c) * 4 + colx); \
} while (0)

    #pragma unroll
    for (int c = 0; c < 5; c++) { KS_ISSUE(c); cpa_commit(); }

    ull acc[2][8];
    #pragma unroll
    for (int i = 0; i < 2; i++)
        #pragma unroll
        for (int p = 0; p < 8; p++) acc[i][p] = 0ull;

    const ulonglong2* wq = (const ulonglong2*)ws_s;   // [d][4 x ulonglong2]

    for (int c = 0; c < 16; c++) {
        cpa_wait<4>();
        __syncthreads();
        if (c + 5 < 16) KS_ISSUE(c + 5);
        cpa_commit();

        const float4* kb = pipe + (c % 6) * 640;
        float4 kv0 = kb[r * 5 + dg];
        float4 kv1 = kb[(r + 64) * 5 + dg];
        #pragma unroll
        for (int dl = 0; dl < 4; dl++) {
            const int dd = c * 16 + dg * 4 + dl;
            ulonglong2 p0 = wq[dd * 4 + 0], p1 = wq[dd * 4 + 1];
            ulonglong2 p2 = wq[dd * 4 + 2], p3 = wq[dd * 4 + 3];
            float kf0 = ((const float*)&kv0)[dl];
            float kf1 = ((const float*)&kv1)[dl];
            ull kk0 = pk2(kf0, kf0), kk1 = pk2(kf1, kf1);
            acc[0][0] = fma2(kk0, p0.x, acc[0][0]); acc[0][1] = fma2(kk0, p0.y, acc[0][1]);
            acc[0][2] = fma2(kk0, p1.x, acc[0][2]); acc[0][3] = fma2(kk0, p1.y, acc[0][3]);
            acc[0][4] = fma2(kk0, p2.x, acc[0][4]); acc[0][5] = fma2(kk0, p2.y, acc[0][5]);
            acc[0][6] = fma2(kk0, p3.x, acc[0][6]); acc[0][7] = fma2(kk0, p3.y, acc[0][7]);
            acc[1][0] = fma2(kk1, p0.x, acc[1][0]); acc[1][1] = fma2(kk1, p0.y, acc[1][1]);
            acc[1][2] = fma2(kk1, p1.x, acc[1][2]); acc[1][3] = fma2(kk1, p1.y, acc[1][3]);
            acc[1][4] = fma2(kk1, p2.x, acc[1][4]); acc[1][5] = fma2(kk1, p2.y, acc[1][5]);
            acc[1][6] = fma2(kk1, p3.x, acc[1][6]); acc[1][7] = fma2(kk1, p3.y, acc[1][7]);
        }
    }
#undef KS_ISSUE

    // reduce the 4 dg partials via smem (reuse ring region; stride 9 avoids conflicts)
    __syncthreads();
    ull* sred = (ull*)(sm + 4096);        // 4 * 1200 ull = 38400 B <= 60 KB
    #pragma unroll
    for (int i = 0; i < 2; i++)
        #pragma unroll
        for (int p = 0; p < 8; p++)
            sred[dg * 1200 + (r + 64 * i) * 9 + p] = acc[i][p];
    __syncthreads();

    const int row = tid >> 1, pb = (tid & 1) * 4;
    const int s = st * 128 + row;
    float* outp = g_scores_part[dq];
    #pragma unroll
    for (int j = 0; j < 4; j++) {
        int p = pb + j;
        ull t = add2(add2(sred[row * 9 + p],        sred[1200 + row * 9 + p]),
                     add2(sred[2400 + row * 9 + p], sred[3600 + row * 9 + p]));
        float lo, hi; upk2(lo, hi, t);
        outp[(size_t)(b * 16 + 2 * p) * 2048 + s]     = lo;
        outp[(size_t)(b * 16 + 2 * p + 1) * 2048 + s] = hi;
    }
}

// softmax over s per (b,h); sums 4 d-partials; write attn[b][s][h]
__global__ __launch_bounds__(256) void k_softmax() {
    int b = blockIdx.x, h = blockIdx.y, tid = threadIdx.x;
    size_t off = (size_t)(b * 16 + h) * 2048;
    float x[8], m = -1e30f;
    #pragma unroll
    for (int i = 0; i < 8; i++) {
        int s = tid + i * 256;
        float v = g_scores_part[0][off + s] + g_scores_part[1][off + s]
                + g_scores_part[2][off + s] + g_scores_part[3][off + s];
        x[i] = v; m = fmaxf(m, v);
    }
    __shared__ float red[8];
    #pragma unroll
    for (int o = 16; o; o >>= 1) m = fmaxf(m, __shfl_xor_sync(0xffffffffu, m, o));
    if ((tid & 31) == 0) red[tid >> 5] = m;
    __syncthreads();
    float M = red[0];
    #pragma unroll
    for (int i = 1; i < 8; i++) M = fmaxf(M, red[i]);
    __syncthreads();
    float ssum = 0.f;
    #pragma unroll
    for (int i = 0; i < 8; i++) { x[i] = __expf(x[i] - M); ssum += x[i]; }
    #pragma unroll
    for (int o = 16; o; o >>= 1) ssum += __shfl_xor_sync(0xffffffffu, ssum, o);
    if ((tid & 31) == 0) red[tid >> 5] = ssum;
    __syncthreads();
    float T = 0.f;
    #pragma unroll
    for (int i = 0; i < 8; i++) T += red[i];
    float inv = 1.0f / T;
    #pragma unroll
    for (int i = 0; i < 8; i++)
        g_attn[((size_t)b * 2048 + tid + i * 256) * 16 + h] = x[i] * inv;
}

// ---------------- pass 2: stream v -> partial vbar ----------------
// grid (64 b, 2 dh, 8 sq). CTA: 256 s x 512 d, 32 stages of 8 s via a 4-stage
// cp.async ring (v 16KB + attn 512B per stage). Thread (sg=tid>>7, dt=tid&127):
// d0 = dh*512 + dt*4, s parity sg within each stage. Partial -> slot sq*2+sg.
__global__ __launch_bounds__(256, 2) void k_vbar(const float* __restrict__ v) {
    extern __shared__ float vsm[];             // 4 stages x 4224 floats (16896 B)
    const int b = blockIdx.x, dh = blockIdx.y, sq = blockIdx.z;
    const int tid = threadIdx.x;
    const int sg = tid >> 7, dt = tid & 127;
    const size_t sBase = (size_t)b * 2048 + sq * 256;
    const float4* vg = (const float4*)v;
    const float4* ag = (const float4*)g_attn;
    const unsigned smb = smem_u32(vsm);

#define VB_ISSUE(c) do { \
    unsigned sb = smb + (unsigned)(((c) % 4) * 16896); \
    int s0 = (c) * 8; \
    _Pragma("unroll") \
    for (int i2 = 0; i2 < 4; i2++) { \
        int idx = tid + i2 * 256; int sl = idx >> 7, col = idx & 127; \
        cpa16(sb + (unsigned)idx * 16u, \
              vg + (sBase + s0 + sl) * 256 + dh * 128 + col); \
    } \
    if (tid < 32) cpa16(sb + 16384u + (unsigned)tid * 16u, ag + (sBase + s0) * 4 + tid); \
} while (0)

    #pragma unroll
    for (int c = 0; c < 3; c++) { VB_ISSUE(c); cpa_commit(); }

    ull acc[4][8];
    #pragma unroll
    for (int d = 0; d < 4; d++)
        #pragma unroll
        for (int hp = 0; hp < 8; hp++) acc[d][hp] = 0ull;

    for (int c = 0; c < 32; c++) {
        cpa_wait<2>();
        __syncthreads();
        if (c + 3 < 32) VB_ISSUE(c + 3);
        cpa_commit();

        const float* stg = vsm + (c % 4) * 4224;
        const float4* vb4 = (const float4*)stg;       // [8 s][128 f4]
        const float* ab = stg + 4096;                 // [8 s][16 h]
        #pragma unroll
        for (int j = 0; j < 4; j++) {
            int sl = sg + 2 * j;
            float4 vv = vb4[sl * 128 + dt];
            ulonglong2 a01 = *(const ulonglong2*)(ab + sl * 16 + 0);
            ulonglong2 a23 = *(const ulonglong2*)(ab + sl * 16 + 4);
            ulonglong2 a45 = *(const ulonglong2*)(ab + sl * 16 + 8);
            ulonglong2 a67 = *(const ulonglong2*)(ab + sl * 16 + 12);
            ull v0 = pk2(vv.x, vv.x), v1 = pk2(vv.y, vv.y);
            ull v2 = pk2(vv.z, vv.z), v3 = pk2(vv.w, vv.w);
            acc[0][0] = fma2(a01.x, v0, acc[0][0]); acc[1][0] = fma2(a01.x, v1, acc[1][0]);
            acc[2][0] = fma2(a01.x, v2, acc[2][0]); acc[3][0] = fma2(a01.x, v3, acc[3][0]);
            acc[0][1] = fma2(a01.y, v0, acc[0][1]); acc[1][1] = fma2(a01.y, v1, acc[1][1]);
            acc[2][1] = fma2(a01.y, v2, acc[2][1]); acc[3][1] = fma2(a01.y, v3, acc[3][1]);
            acc[0][2] = fma2(a23.x, v0, acc[0][2]); acc[1][2] = fma2(a23.x, v1, acc[1][2]);
            acc[2][2] = fma2(a23.x, v2, acc[2][2]); acc[3][2] = fma2(a23.x, v3, acc[3][2]);
            acc[0][3] = fma2(a23.y, v0, acc[0][3]); acc[1][3] = fma2(a23.y, v1, acc[1][3]);
            acc[2][3] = fma2(a23.y, v2, acc[2][3]); acc[3][3] = fma2(a23.y, v3, acc[3][3]);
            acc[0][4] = fma2(a45.x, v0, acc[0][4]); acc[1][4] = fma2(a45.x, v1, acc[1][4]);
            acc[2][4] = fma2(a45.x, v2, acc[2][4]); acc[3][4] = fma2(a45.x, v3, acc[3][4]);
            acc[0][5] = fma2(a45.y, v0, acc[0][5]); acc[1][5] = fma2(a45.y, v1, acc[1][5]);
            acc[2][5] = fma2(a45.y, v2, acc[2][5]); acc[3][5] = fma2(a45.y, v3, acc[3][5]);
            acc[0][6] = fma2(a67.x, v0, acc[0][6]); acc[1][6] = fma2(a67.x, v1, acc[1][6]);
            acc[2][6] = fma2(a67.x, v2, acc[2][6]); acc[3][6] = fma2(a67.x, v3, acc[3][6]);
            acc[0][7] = fma2(a67.y, v0, acc[0][7]); acc[1][7] = fma2(a67.y, v1, acc[1][7]);
            acc[2][7] = fma2(a67.y, v2, acc[2][7]); acc[3][7] = fma2(a67.y, v3, acc[3][7]);
        }
    }
#undef VB_ISSUE

    float* outp = g_vbar_part[sq * 2 + sg] + (size_t)b * 16384;
    const int d0 = dh * 512 + dt * 4;
    #pragma unroll
    for (int hp = 0; hp < 8; hp++) {
        float lo0, hi0, lo1, hi1, lo2, hi2, lo3, hi3;
        upk2(lo0, hi0, acc[0][hp]); upk2(lo1, hi1, acc[1][hp]);
        upk2(lo2, hi2, acc[2][hp]); upk2(lo3, hi3, acc[3][hp]);
        float4 e; e.x = lo0; e.y = lo1; e.z = lo2; e.w = lo3;
        float4 o; o.x = hi0; o.y = hi1; o.z = hi2; o.w = hi3;
        *(float4*)&outp[(size_t)(2 * hp) * 1024 + d0]     = e;
        *(float4*)&outp[(size_t)(2 * hp + 1) * 1024 + d0] = o;
    }
}

__global__ __launch_bounds__(256) void k_relu(float* __restrict__ out) {
    int i = blockIdx.x * 256 + threadIdx.x;
    out[i] = fmaxf(g_outpre[i], 0.0f);
}

extern "C" void kernel_launch(void* const* d_in, const int* in_sizes, int n_in,
                              void* d_out, int out_size) {
    const float* q  = (const float*)d_in[0];
    const float* k  = (const float*)d_in[1];
    const float* v  = (const float*)d_in[2];
    const float* Wq = (const float*)d_in[3];
    const float* bq = (const float*)d_in[4];
    const float* Wk = (const float*)d_in[5];
    // d_in[6] = bk — cancels in softmax
    const float* Wv = (const float*)d_in[7];
    const float* bv = (const float*)d_in[8];
    const float* Wo = (const float*)d_in[9];
    const float* bo = (const float*)d_in[10];

    const int smem_scores = 4096 * 4 + 6 * 640 * 16;   // 16384 + 61440 = 77824
    const int smem_vbar   = 4 * 16896;                 // 67584
    static bool attr_done = false;
    if (!attr_done) {
        cudaFuncSetAttribute(k_scores, cudaFuncAttributeMaxDynamicSharedMemorySize, smem_scores);
        cudaFuncSetAttribute(k_vbar,   cudaFuncAttributeMaxDynamicSharedMemorySize, smem_vbar);
        attr_done = true;
    }

    k_init<<<256, 256>>>(bq, bv, bo);
    gemm_ksplit<<<dim3(16, 16), 256>>>(q, Wq, 0);
    k_ws<<<dim3(16, 8, 4), 256>>>(Wk);
    k_scores<<<dim3(64, 16, 4), 256, smem_scores>>>(k);
    k_softmax<<<dim3(64, 16), 256>>>();
    k_vbar<<<dim3(64, 2, 8), 256, smem_vbar>>>(v);
    gemm_ksplit<<<dim3(16, 16), 256>>>(nullptr, Wv, 1);
    gemm_ksplit<<<dim3(16, 16), 256>>>(nullptr, Wo, 2);
    k_relu<<<256, 256>>>((float*)d_out);
}

// round 8
// speedup vs baseline: 3.2460x; 1.0655x over previous
#include <cuda_runtime.h>
#include <cstdint>
#include <cstddef>

typedef unsigned long long ull;

// device scratch (allocs forbidden)
__device__ float g_qh[64 * 1024];
__device__ float g_ws[64 * 1024 * 16];                 // [b][d][h]
__device__ float g_scores_part[4][64 * 16 * 2048];     // [dq][b][h][s]
__device__ float g_attn[64 * 2048 * 16];               // [b][s][h]
__device__ float g_vbar_part[8][64 * 16 * 1024];       // [sq][b][h][d]
__device__ float g_concat[64 * 1024];
__device__ float g_outpre[64 * 1024];

__device__ __forceinline__ ull pk2(float x, float y) {
    ull r; asm("mov.b64 %0, {%1,%2};" : "=l"(r) : "f"(x), "f"(y)); return r;
}
__device__ __forceinline__ void upk2(float& x, float& y, ull v) {
    asm("mov.b64 {%0,%1}, %2;" : "=f"(x), "=f"(y) : "l"(v));
}
__device__ __forceinline__ ull fma2(ull a, ull b, ull c) {
    ull d; asm("fma.rn.f32x2 %0, %1, %2, %3;" : "=l"(d) : "l"(a), "l"(b), "l"(c)); return d;
}
__device__ __forceinline__ ull add2(ull a, ull b) {
    ull c; asm("add.rn.f32x2 %0, %1, %2;" : "=l"(c) : "l"(a), "l"(b)); return c;
}
__device__ __forceinline__ unsigned smem_u32(const void* p) {
    return (unsigned)__cvta_generic_to_shared(p);
}
__device__ __forceinline__ void cpa16(unsigned s, const void* g) {
    asm volatile("cp.async.cg.shared.global [%0], [%1], 16;" :: "r"(s), "l"(g));
}
__device__ __forceinline__ void cpa_commit() {
    asm volatile("cp.async.commit_group;" ::: "memory");
}
template <int N> __device__ __forceinline__ void cpa_wait() {
    asm volatile("cp.async.wait_group %0;" :: "n"(N) : "memory");
}

__global__ __launch_bounds__(256) void k_init(const float* __restrict__ bq,
                                              const float* __restrict__ bv,
                                              const float* __restrict__ bo) {
    int i = blockIdx.x * 256 + threadIdx.x;
    int c = i & 1023;
    g_qh[i] = bq[c]; g_concat[i] = bv[c]; g_outpre[i] = bo[c];
}

// C[64,1024] += A[64,1024] @ W[1024,1024]; 16-way k-split over by, 64-col tiles over bx.
// mode 0: A=q -> g_qh | mode 1: A=sum of 8 vbar partials (head h=bx) -> g_concat
// mode 2: A=g_concat -> g_outpre
__global__ __launch_bounds__(256) void gemm_ksplit(const float* __restrict__ Ain,
                                                   const float* __restrict__ W, int mode) {
    __shared__ float As[64 * 68];
    __shared__ float Wsm[64 * 64];
    int bx = blockIdx.x, by = blockIdx.y, tid = threadIdx.x;
    int col0 = bx * 64, db = by * 64;

    if (mode == 1) {
        for (int idx = tid; idx < 4096; idx += 256) {
            int bb = idx >> 6, dd = idx & 63;
            size_t off = (size_t)bb * 16384 + (size_t)bx * 1024 + db + dd;
            float s = 0.f;
            #pragma unroll
            for (int p = 0; p < 8; p++) s += g_vbar_part[p][off];
            As[bb * 68 + dd] = s;
        }
    } else {
        const float* A = (mode == 0) ? Ain : g_concat;
        for (int idx = tid; idx < 4096; idx += 256) {
            int bb = idx >> 6, dd = idx & 63;
            As[bb * 68 + dd] = A[(size_t)bb * 1024 + db + dd];
        }
    }
    for (int idx = tid; idx < 4096; idx += 256) {
        int dd = idx >> 6, j = idx & 63;
        Wsm[dd * 64 + j] = W[(size_t)(db + dd) * 1024 + col0 + j];
    }
    __syncthreads();

    int tj = tid & 15, tb = tid >> 4;
    float acc[4][4] = {};
    const float4* Ws4 = (const float4*)Wsm;
    #pragma unroll 8
    for (int dd = 0; dd < 64; dd++) {
        float4 w = Ws4[dd * 16 + tj];
        #pragma unroll
        for (int bb = 0; bb < 4; bb++) {
            float a = As[(tb * 4 + bb) * 68 + dd];
            acc[bb][0] = fmaf(a, w.x, acc[bb][0]);
            acc[bb][1] = fmaf(a, w.y, acc[bb][1]);
            acc[bb][2] = fmaf(a, w.z, acc[bb][2]);
            acc[bb][3] = fmaf(a, w.w, acc[bb][3]);
        }
    }
    float* C = (mode == 0) ? g_qh : (mode == 1) ? g_concat : g_outpre;
    #pragma unroll
    for (int bb = 0; bb < 4; bb++)
        #pragma unroll
        for (int jj = 0; jj < 4; jj++)
            atomicAdd(&C[(size_t)(tb * 4 + bb) * 1024 + col0 + tj * 4 + jj], acc[bb][jj]);
}

// g_ws[b][d][h] = 0.125 * sum_j Wk[d, 64h+j] * g_qh[b, 64h+j]; grid (16 dt, 8 bt, 4 hz)
__global__ __launch_bounds__(256) void k_ws(const float* __restrict__ Wk) {
    __shared__ float Wks[64 * 68];
    __shared__ float qhs[8 * 64];
    int dt = blockIdx.x, bt = blockIdx.y, hz = blockIdx.z, tid = threadIdx.x;
    int td = tid & 63, tg = tid >> 6;
    for (int hi = 0; hi < 4; hi++) {
        int h = hz * 4 + hi;
        __syncthreads();
        for (int idx = tid; idx < 4096; idx += 256) {
            int dd = idx >> 6, j = idx & 63;
            Wks[dd * 68 + j] = Wk[(size_t)(dt * 64 + dd) * 1024 + h * 64 + j];
        }
        for (int idx = tid; idx < 512; idx += 256) {
            int bb = idx >> 6, j = idx & 63;
            qhs[bb * 64 + j] = g_qh[(size_t)(bt * 8 + bb) * 1024 + h * 64 + j];
        }
        __syncthreads();
        float a0 = 0.f, a1 = 0.f;
        #pragma unroll
        for (int j4 = 0; j4 < 16; j4++) {
            float4 w  = *(const float4*)&Wks[td * 68 + j4 * 4];
            float4 qa = *(const float4*)&qhs[(tg * 2 + 0) * 64 + j4 * 4];
            float4 qb = *(const float4*)&qhs[(tg * 2 + 1) * 64 + j4 * 4];
            a0 = fmaf(w.x, qa.x, fmaf(w.y, qa.y, fmaf(w.z, qa.z, fmaf(w.w, qa.w, a0))));
            a1 = fmaf(w.x, qb.x, fmaf(w.y, qb.y, fmaf(w.z, qb.z, fmaf(w.w, qb.w, a1))));
        }
        int d = dt * 64 + td;
        g_ws[((size_t)(bt * 8 + tg * 2 + 0) * 1024 + d) * 16 + h] = a0 * 0.125f;
        g_ws[((size_t)(bt * 8 + tg * 2 + 1) * 1024 + d) * 16 + h] = a1 * 0.125f;
    }
}

// ---------------- pass 1: stream k -> partial scores ----------------
// grid (64 b, 16 st, 4 dq). CTA tile: 128 s x 256 d, 16 chunks of 16 d.
// 5-stage cp.async ring; stage = [128 rows][5 f4] (pad col -> conflict-free
// LDS.128). Thread (dg=tid>>6, r=tid&63): rows {r, r+64}, f4-col dg per chunk.
// dyn smem = 16KB ws + 50KB ring = 67584 B -> 3 CTAs/SM (regs capped at 85).
__global__ __launch_bounds__(256, 3) void k_scores(const float* __restrict__ k) {
    extern __shared__ float sm[];
    float* ws_s = sm;                          // 4096 f: [256 d][16 h]
    float4* pipe = (float4*)(sm + 4096);       // 5 stages x 640 f4
    const int b = blockIdx.x, st = blockIdx.y, dq = blockIdx.z;
    const int tid = threadIdx.x;
    const int dg = tid >> 6, r = tid & 63;

    {   // stage ws slice (coalesced)
        const float4* src = (const float4*)(g_ws + (size_t)b * 16384 + dq * 4096);
        float4* dst = (float4*)ws_s;
        #pragma unroll
        for (int i = 0; i < 4; i++) dst[tid + i * 256] = src[tid + i * 256];
    }

    const float4* k4 = (const float4*)k;
    const size_t gbase = ((size_t)b * 2048 + st * 128) * 256 + dq * 64;   // f4 units
    const int row0 = tid >> 2, colx = tid & 3;
    const int row1 = (tid + 256) >> 2;
    const unsigned sbase = smem_u32(pipe);
    const unsigned soff0 = (unsigned)(row0 * 5 + colx) * 16u;
    const unsigned soff1 = (unsigned)(row1 * 5 + colx) * 16u;

#define KS_ISSUE(c) do { \
    unsigned sb = sbase + (unsigned)(((c) % 5) * 640) * 16u; \
    cpa16(sb + soff0, k4 + gbase + (size_t)row0 * 256 + (c) * 4 + colx); \
    cpa16(sb + soff1, k4 + gbase + (size_t)row1 * 256 + (c) * 4 + colx); \
} while (0)

    #pragma unroll
    for (int c = 0; c < 4; c++) { KS_ISSUE(c); cpa_commit(); }

    ull acc[2][8];
    #pragma unroll
    for (int i = 0; i < 2; i++)
        #pragma unroll
        for (int p = 0; p < 8; p++) acc[i][p] = 0ull;

    const ulonglong2* wq = (const ulonglong2*)ws_s;   // [d][4 x ulonglong2]

    for (int c = 0; c < 16; c++) {
        cpa_wait<3>();
        __syncthreads();
        if (c + 4 < 16) KS_ISSUE(c + 4);
        cpa_commit();

        const float4* kb = pipe + (c % 5) * 640;
        float4 kv0 = kb[r * 5 + dg];
        float4 kv1 = kb[(r + 64) * 5 + dg];
        #pragma unroll
        for (int dl = 0; dl < 4; dl++) {
            const int dd = c * 16 + dg * 4 + dl;
            ulonglong2 p0 = wq[dd * 4 + 0], p1 = wq[dd * 4 + 1];
            ulonglong2 p2 = wq[dd * 4 + 2], p3 = wq[dd * 4 + 3];
            float kf0 = ((const float*)&kv0)[dl];
            float kf1 = ((const float*)&kv1)[dl];
            ull kk0 = pk2(kf0, kf0), kk1 = pk2(kf1, kf1);
            acc[0][0] = fma2(kk0, p0.x, acc[0][0]); acc[0][1] = fma2(kk0, p0.y, acc[0][1]);
            acc[0][2] = fma2(kk0, p1.x, acc[0][2]); acc[0][3] = fma2(kk0, p1.y, acc[0][3]);
            acc[0][4] = fma2(kk0, p2.x, acc[0][4]); acc[0][5] = fma2(kk0, p2.y, acc[0][5]);
            acc[0][6] = fma2(kk0, p3.x, acc[0][6]); acc[0][7] = fma2(kk0, p3.y, acc[0][7]);
            acc[1][0] = fma2(kk1, p0.x, acc[1][0]); acc[1][1] = fma2(kk1, p0.y, acc[1][1]);
            acc[1][2] = fma2(kk1, p1.x, acc[1][2]); acc[1][3] = fma2(kk1, p1.y, acc[1][3]);
            acc[1][4] = fma2(kk1, p2.x, acc[1][4]); acc[1][5] = fma2(kk1, p2.y, acc[1][5]);
            acc[1][6] = fma2(kk1, p3.x, acc[1][6]); acc[1][7] = fma2(kk1, p3.y, acc[1][7]);
        }
    }
#undef KS_ISSUE

    // reduce the 4 dg partials via smem (reuse ring region; stride 9 avoids conflicts)
    __syncthreads();
    ull* sred = (ull*)(sm + 4096);        // 4 * 1200 ull = 38400 B <= 50 KB
    #pragma unroll
    for (int i = 0; i < 2; i++)
        #pragma unroll
        for (int p = 0; p < 8; p++)
            sred[dg * 1200 + (r + 64 * i) * 9 + p] = acc[i][p];
    __syncthreads();

    const int row = tid >> 1, pb = (tid & 1) * 4;
    const int s = st * 128 + row;
    float* outp = g_scores_part[dq];
    #pragma unroll
    for (int j = 0; j < 4; j++) {
        int p = pb + j;
        ull t = add2(add2(sred[row * 9 + p],        sred[1200 + row * 9 + p]),
                     add2(sred[2400 + row * 9 + p], sred[3600 + row * 9 + p]));
        float lo, hi; upk2(lo, hi, t);
        outp[(size_t)(b * 16 + 2 * p) * 2048 + s]     = lo;
        outp[(size_t)(b * 16 + 2 * p + 1) * 2048 + s] = hi;
    }
}

// softmax over s per (b,h); sums 4 d-partials; write attn[b][s][h]
__global__ __launch_bounds__(256) void k_softmax() {
    int b = blockIdx.x, h = blockIdx.y, tid = threadIdx.x;
    size_t off = (size_t)(b * 16 + h) * 2048;
    float x[8], m = -1e30f;
    #pragma unroll
    for (int i = 0; i < 8; i++) {
        int s = tid + i * 256;
        float v = g_scores_part[0][off + s] + g_scores_part[1][off + s]
                + g_scores_part[2][off + s] + g_scores_part[3][off + s];
        x[i] = v; m = fmaxf(m, v);
    }
    __shared__ float red[8];
    #pragma unroll
    for (int o = 16; o; o >>= 1) m = fmaxf(m, __shfl_xor_sync(0xffffffffu, m, o));
    if ((tid & 31) == 0) red[tid >> 5] = m;
    __syncthreads();
    float M = red[0];
    #pragma unroll
    for (int i = 1; i < 8; i++) M = fmaxf(M, red[i]);
    __syncthreads();
    float ssum = 0.f;
    #pragma unroll
    for (int i = 0; i < 8; i++) { x[i] = __expf(x[i] - M); ssum += x[i]; }
    #pragma unroll
    for (int o = 16; o; o >>= 1) ssum += __shfl_xor_sync(0xffffffffu, ssum, o);
    if ((tid & 31) == 0) red[tid >> 5] = ssum;
    __syncthreads();
    float T = 0.f;
    #pragma unroll
    for (int i = 0; i < 8; i++) T += red[i];
    float inv = 1.0f / T;
    #pragma unroll
    for (int i = 0; i < 8; i++)
        g_attn[((size_t)b * 2048 + tid + i * 256) * 16 + h] = x[i] * inv;
}

// ---------------- pass 2: stream v -> partial vbar ----------------
// grid (64 b, 2 dh, 8 sq). CTA: 256 s x 512 d x 16 h; 32 stages of 8 s via
// 3-stage cp.async ring (v 16KB + attn 512B per stage). Thread (hg=tid>>7,
// dt=tid&127): 4 d (one f4) x 8 heads x all 8 s per stage. acc = 16 ull.
// Partial slot = sq (hg/dh are disjoint head/d ranges). 3 CTAs/SM.
__global__ __launch_bounds__(256, 3) void k_vbar(const float* __restrict__ v) {
    extern __shared__ float vsm[];             // 3 stages x 4224 floats (16896 B)
    const int b = blockIdx.x, dh = blockIdx.y, sq = blockIdx.z;
    const int tid = threadIdx.x;
    const int hg = tid >> 7, dt = tid & 127;
    const size_t sBase = (size_t)b * 2048 + sq * 256;
    const float4* vg = (const float4*)v;
    const float4* ag = (const float4*)g_attn;
    const unsigned smb = smem_u32(vsm);

#define VB_ISSUE(c) do { \
    unsigned sb = smb + (unsigned)(((c) % 3) * 16896); \
    int s0 = (c) * 8; \
    _Pragma("unroll") \
    for (int i2 = 0; i2 < 4; i2++) { \
        int idx = tid + i2 * 256; int sl = idx >> 7, col = idx & 127; \
        cpa16(sb + (unsigned)idx * 16u, \
              vg + (sBase + s0 + sl) * 256 + dh * 128 + col); \
    } \
    if (tid < 32) cpa16(sb + 16384u + (unsigned)tid * 16u, ag + (sBase + s0) * 4 + tid); \
} while (0)

    #pragma unroll
    for (int c = 0; c < 2; c++) { VB_ISSUE(c); cpa_commit(); }

    ull acc[4][4];
    #pragma unroll
    for (int d = 0; d < 4; d++)
        #pragma unroll
        for (int hp = 0; hp < 4; hp++) acc[d][hp] = 0ull;

    for (int c = 0; c < 32; c++) {
        cpa_wait<1>();
        __syncthreads();
        if (c + 2 < 32) VB_ISSUE(c + 2);
        cpa_commit();

        const float* stg = vsm + (c % 3) * 4224;
        const float4* vb4 = (const float4*)stg;       // [8 s][128 f4]
        const float* ab = stg + 4096;                 // [8 s][16 h]
        #pragma unroll
        for (int sl = 0; sl < 8; sl++) {
            float4 vv = vb4[sl * 128 + dt];
            ulonglong2 a01 = *(const ulonglong2*)(ab + sl * 16 + hg * 8);
            ulonglong2 a23 = *(const ulonglong2*)(ab + sl * 16 + hg * 8 + 4);
            ull v0 = pk2(vv.x, vv.x), v1 = pk2(vv.y, vv.y);
            ull v2 = pk2(vv.z, vv.z), v3 = pk2(vv.w, vv.w);
            acc[0][0] = fma2(a01.x, v0, acc[0][0]); acc[1][0] = fma2(a01.x, v1, acc[1][0]);
            acc[2][0] = fma2(a01.x, v2, acc[2][0]); acc[3][0] = fma2(a01.x, v3, acc[3][0]);
            acc[0][1] = fma2(a01.y, v0, acc[0][1]); acc[1][1] = fma2(a01.y, v1, acc[1][1]);
            acc[2][1] = fma2(a01.y, v2, acc[2][1]); acc[3][1] = fma2(a01.y, v3, acc[3][1]);
            acc[0][2] = fma2(a23.x, v0, acc[0][2]); acc[1][2] = fma2(a23.x, v1, acc[1][2]);
            acc[2][2] = fma2(a23.x, v2, acc[2][2]); acc[3][2] = fma2(a23.x, v3, acc[3][2]);
            acc[0][3] = fma2(a23.y, v0, acc[0][3]); acc[1][3] = fma2(a23.y, v1, acc[1][3]);
            acc[2][3] = fma2(a23.y, v2, acc[2][3]); acc[3][3] = fma2(a23.y, v3, acc[3][3]);
        }
    }
#undef VB_ISSUE

    float* outp = g_vbar_part[sq] + (size_t)b * 16384;
    const int d0 = dh * 512 + dt * 4;
    #pragma unroll
    for (int hp = 0; hp < 4; hp++) {
        float lo0, hi0, lo1, hi1, lo2, hi2, lo3, hi3;
        upk2(lo0, hi0, acc[0][hp]); upk2(lo1, hi1, acc[1][hp]);
        upk2(lo2, hi2, acc[2][hp]); upk2(lo3, hi3, acc[3][hp]);
        float4 e; e.x = lo0; e.y = lo1; e.z = lo2; e.w = lo3;
        float4 o; o.x = hi0; o.y = hi1; o.z = hi2; o.w = hi3;
        int h0 = hg * 8 + 2 * hp;
        *(float4*)&outp[(size_t)h0 * 1024 + d0]       = e;
        *(float4*)&outp[(size_t)(h0 + 1) * 1024 + d0] = o;
    }
}

__global__ __launch_bounds__(256) void k_relu(float* __restrict__ out) {
    int i = blockIdx.x * 256 + threadIdx.x;
    out[i] = fmaxf(g_outpre[i], 0.0f);
}

extern "C" void kernel_launch(void* const* d_in, const int* in_sizes, int n_in,
                              void* d_out, int out_size) {
    const float* q  = (const float*)d_in[0];
    const float* k  = (const float*)d_in[1];
    const float* v  = (const float*)d_in[2];
    const float* Wq = (const float*)d_in[3];
    const float* bq = (const float*)d_in[4];
    const float* Wk = (const float*)d_in[5];
    // d_in[6] = bk — cancels in softmax
    const float* Wv = (const float*)d_in[7];
    const float* bv = (const float*)d_in[8];
    const float* Wo = (const float*)d_in[9];
    const float* bo = (const float*)d_in[10];

    const int smem_scores = 4096 * 4 + 5 * 640 * 16;   // 16384 + 51200 = 67584
    const int smem_vbar   = 3 * 16896;                 // 50688
    static bool attr_done = false;
    if (!attr_done) {
        cudaFuncSetAttribute(k_scores, cudaFuncAttributeMaxDynamicSharedMemorySize, smem_scores);
        cudaFuncSetAttribute(k_vbar,   cudaFuncAttributeMaxDynamicSharedMemorySize, smem_vbar);
        attr_done = true;
    }

    k_init<<<256, 256>>>(bq, bv, bo);
    gemm_ksplit<<<dim3(16, 16), 256>>>(q, Wq, 0);
    k_ws<<<dim3(16, 8, 4), 256>>>(Wk);
    k_scores<<<dim3(64, 16, 4), 256, smem_scores>>>(k);
    k_softmax<<<dim3(64, 16), 256>>>();
    k_vbar<<<dim3(64, 2, 8), 256, smem_vbar>>>(v);
    gemm_ksplit<<<dim3(16, 16), 256>>>(nullptr, Wv, 1);
    gemm_ksplit<<<dim3(16, 16), 256>>>(nullptr, Wo, 2);
    k_relu<<<256, 256>>>((float*)d_out);
}

// round 9
// speedup vs baseline: 3.3246x; 1.0242x over previous
#include <cuda_runtime.h>
#include <cstdint>
#include <cstddef>

typedef unsigned long long ull;

// device scratch (allocs forbidden)
__device__ float g_qh[64 * 1024];
__device__ float g_ws[64 * 1024 * 16];                 // [b][d][h]
__device__ float g_scores_part[4][64 * 16 * 2048];     // [dq][b][h][s]
__device__ float g_attn[64 * 2048 * 16];               // [b][s][h]
__device__ float g_vbar_part[8][64 * 16 * 1024];       // [sq][b][h][d]
__device__ float g_concat[64 * 1024];
__device__ float g_outpre[64 * 1024];

__device__ __forceinline__ ull pk2(float x, float y) {
    ull r; asm("mov.b64 %0, {%1,%2};" : "=l"(r) : "f"(x), "f"(y)); return r;
}
__device__ __forceinline__ void upk2(float& x, float& y, ull v) {
    asm("mov.b64 {%0,%1}, %2;" : "=f"(x), "=f"(y) : "l"(v));
}
__device__ __forceinline__ ull fma2(ull a, ull b, ull c) {
    ull d; asm("fma.rn.f32x2 %0, %1, %2, %3;" : "=l"(d) : "l"(a), "l"(b), "l"(c)); return d;
}
__device__ __forceinline__ ull add2(ull a, ull b) {
    ull c; asm("add.rn.f32x2 %0, %1, %2;" : "=l"(c) : "l"(a), "l"(b)); return c;
}
__device__ __forceinline__ unsigned smem_u32(const void* p) {
    return (unsigned)__cvta_generic_to_shared(p);
}
__device__ __forceinline__ void cpa16(unsigned s, const void* g) {
    asm volatile("cp.async.cg.shared.global [%0], [%1], 16;" :: "r"(s), "l"(g));
}
__device__ __forceinline__ void cpa_commit() {
    asm volatile("cp.async.commit_group;" ::: "memory");
}
template <int N> __device__ __forceinline__ void cpa_wait() {
    asm volatile("cp.async.wait_group %0;" :: "n"(N) : "memory");
}

__global__ __launch_bounds__(256) void k_init(const float* __restrict__ bq,
                                              const float* __restrict__ bv,
                                              const float* __restrict__ bo) {
    int i = blockIdx.x * 256 + threadIdx.x;
    int c = i & 1023;
    g_qh[i] = bq[c]; g_concat[i] = bv[c]; g_outpre[i] = bo[c];
}

// C[64,1024] += A[64,1024] @ W[1024,1024]; 16-way k-split over by, 64-col tiles over bx.
// mode 0: A=q -> g_qh | mode 1: A=sum of 8 vbar partials (head h=bx) -> g_concat
// mode 2: A=g_concat -> g_outpre
__global__ __launch_bounds__(256) void gemm_ksplit(const float* __restrict__ Ain,
                                                   const float* __restrict__ W, int mode) {
    __shared__ float As[64 * 68];
    __shared__ float Wsm[64 * 64];
    int bx = blockIdx.x, by = blockIdx.y, tid = threadIdx.x;
    int col0 = bx * 64, db = by * 64;

    if (mode == 1) {
        for (int idx = tid; idx < 4096; idx += 256) {
            int bb = idx >> 6, dd = idx & 63;
            size_t off = (size_t)bb * 16384 + (size_t)bx * 1024 + db + dd;
            float s = 0.f;
            #pragma unroll
            for (int p = 0; p < 8; p++) s += g_vbar_part[p][off];
            As[bb * 68 + dd] = s;
        }
    } else {
        const float* A = (mode == 0) ? Ain : g_concat;
        for (int idx = tid; idx < 4096; idx += 256) {
            int bb = idx >> 6, dd = idx & 63;
            As[bb * 68 + dd] = A[(size_t)bb * 1024 + db + dd];
        }
    }
    for (int idx = tid; idx < 4096; idx += 256) {
        int dd = idx >> 6, j = idx & 63;
        Wsm[dd * 64 + j] = W[(size_t)(db + dd) * 1024 + col0 + j];
    }
    __syncthreads();

    int tj = tid & 15, tb = tid >> 4;
    float acc[4][4] = {};
    const float4* Ws4 = (const float4*)Wsm;
    #pragma unroll 8
    for (int dd = 0; dd < 64; dd++) {
        float4 w = Ws4[dd * 16 + tj];
        #pragma unroll
        for (int bb = 0; bb < 4; bb++) {
            float a = As[(tb * 4 + bb) * 68 + dd];
            acc[bb][0] = fmaf(a, w.x, acc[bb][0]);
            acc[bb][1] = fmaf(a, w.y, acc[bb][1]);
            acc[bb][2] = fmaf(a, w.z, acc[bb][2]);
            acc[bb][3] = fmaf(a, w.w, acc[bb][3]);
        }
    }
    float* C = (mode == 0) ? g_qh : (mode == 1) ? g_concat : g_outpre;
    #pragma unroll
    for (int bb = 0; bb < 4; bb++)
        #pragma unroll
        for (int jj = 0; jj < 4; jj++)
            atomicAdd(&C[(size_t)(tb * 4 + bb) * 1024 + col0 + tj * 4 + jj], acc[bb][jj]);
}

// g_ws[b][d][h] = 0.125 * sum_j Wk[d, 64h+j] * g_qh[b, 64h+j]; grid (16 dt, 8 bt, 4 hz)
__global__ __launch_bounds__(256) void k_ws(const float* __restrict__ Wk) {
    __shared__ float Wks[64 * 68];
    __shared__ float qhs[8 * 64];
    int dt = blockIdx.x, bt = blockIdx.y, hz = blockIdx.z, tid = threadIdx.x;
    int td = tid & 63, tg = tid >> 6;
    for (int hi = 0; hi < 4; hi++) {
        int h = hz * 4 + hi;
        __syncthreads();
        for (int idx = tid; idx < 4096; idx += 256) {
            int dd = idx >> 6, j = idx & 63;
            Wks[dd * 68 + j] = Wk[(size_t)(dt * 64 + dd) * 1024 + h * 64 + j];
        }
        for (int idx = tid; idx < 512; idx += 256) {
            int bb = idx >> 6, j = idx & 63;
            qhs[bb * 64 + j] = g_qh[(size_t)(bt * 8 + bb) * 1024 + h * 64 + j];
        }
        __syncthreads();
        float a0 = 0.f, a1 = 0.f;
        #pragma unroll
        for (int j4 = 0; j4 < 16; j4++) {
            float4 w  = *(const float4*)&Wks[td * 68 + j4 * 4];
            float4 qa = *(const float4*)&qhs[(tg * 2 + 0) * 64 + j4 * 4];
            float4 qb = *(const float4*)&qhs[(tg * 2 + 1) * 64 + j4 * 4];
            a0 = fmaf(w.x, qa.x, fmaf(w.y, qa.y, fmaf(w.z, qa.z, fmaf(w.w, qa.w, a0))));
            a1 = fmaf(w.x, qb.x, fmaf(w.y, qb.y, fmaf(w.z, qb.z, fmaf(w.w, qb.w, a1))));
        }
        int d = dt * 64 + td;
        g_ws[((size_t)(bt * 8 + tg * 2 + 0) * 1024 + d) * 16 + h] = a0 * 0.125f;
        g_ws[((size_t)(bt * 8 + tg * 2 + 1) * 1024 + d) * 16 + h] = a1 * 0.125f;
    }
}

// ---------------- pass 1: stream k -> partial scores ----------------
// grid (64 b, 16 st, 4 dq). CTA tile: 128 s x 256 d, 16 chunks of 16 d.
// 6-stage cp.async ring; c-loop FULLY UNROLLED so stage offsets / LDS indices /
// cp.async source offsets are compile-time immediates (no ring modulo, no
// per-iter IMAD). Thread (dg=tid>>6, r=tid&63): rows {r, r+64}, f4-col dg.
// dyn smem = 16KB ws + 60KB ring = 77824 B; 3 CTAs need <= 75.7KB... use
// 6 stages = 61440 + 16384 = 77824 -> 2? NO: 228KB/3 = 76KB. Use 5.75? ->
// keep 6 stages but shave ws into ring? Simpler: 6 stages of 624 f4? See note.
// We keep 5-stage semantics impossible w/ const idx; so: 6-stage ring with
// stage stride 624 f4 (rows packed [128][4.875]?) -- NO. Final: 6 stages x
// 640 f4 = 60KB + ws 16KB = 76KB > 75.7KB by 0.3KB -> drop ws pad: ws is
// exactly 16KB, ring 59.5KB needed. Use stage = [128 rows][5 f4] minus pad on
// last: keep 640 but only 5 stages in flight; ring array of 6 would overflow.
// => Use 6 stages x 608 f4 (stage = [128 rows][4.75]) invalid. Resolution:
// ring stages use stride 636 f4 (row stride 4.96) invalid too. We instead use
// 6 stages x 640 f4 and REDUCE ws to 15.5KB? ws is 4096 floats fixed.
// -> Use 74.5KB total: 6 stages x 596? Not expressible. Final choice:
// FULL UNROLL with 5-stage ring (c%5 still becomes a compile-time constant
// under full unroll!) -- modulo of a constant is free. smem = 67584, 3 CTAs.
__global__ __launch_bounds__(256, 3) void k_scores(const float* __restrict__ k) {
    extern __shared__ float sm[];
    float* ws_s = sm;                          // 4096 f: [256 d][16 h]
    float4* pipe = (float4*)(sm + 4096);       // 5 stages x 640 f4
    const int b = blockIdx.x, st = blockIdx.y, dq = blockIdx.z;
    const int tid = threadIdx.x;
    const int dg = tid >> 6, r = tid & 63;

    {   // stage ws slice (coalesced)
        const float4* src = (const float4*)(g_ws + (size_t)b * 16384 + dq * 4096);
        float4* dst = (float4*)ws_s;
        #pragma unroll
        for (int i = 0; i < 4; i++) dst[tid + i * 256] = src[tid + i * 256];
    }

    const float4* k4 = (const float4*)k;
    const size_t gbase = ((size_t)b * 2048 + st * 128) * 256 + dq * 64;   // f4 units
    const int row0 = tid >> 2, colx = tid & 3;
    const int row1 = (tid + 256) >> 2;
    const float4* kg0 = k4 + gbase + (size_t)row0 * 256 + colx;  // bump +4/chunk (const)
    const float4* kg1 = k4 + gbase + (size_t)row1 * 256 + colx;
    const unsigned sbase = smem_u32(pipe);
    const unsigned s0off = sbase + (unsigned)(row0 * 5 + colx) * 16u;
    const unsigned s1off = sbase + (unsigned)(row1 * 5 + colx) * 16u;

#define KS_ISSUE(c) do { \
    cpa16(s0off + (unsigned)(((c) % 5) * 640) * 16u, kg0 + (c) * 4); \
    cpa16(s1off + (unsigned)(((c) % 5) * 640) * 16u, kg1 + (c) * 4); \
} while (0)

    #pragma unroll
    for (int c = 0; c < 4; c++) { KS_ISSUE(c); cpa_commit(); }

    ull acc[2][8];
    #pragma unroll
    for (int i = 0; i < 2; i++)
        #pragma unroll
        for (int p = 0; p < 8; p++) acc[i][p] = 0ull;

    const ulonglong2* wq = (const ulonglong2*)ws_s + dg * 16;  // [chunk-const + dl*4 + i]
    const int kidx0 = r * 5 + dg, kidx1 = (r + 64) * 5 + dg;

    #pragma unroll
    for (int c = 0; c < 16; c++) {
        cpa_wait<3>();
        __syncthreads();
        if (c + 4 < 16) KS_ISSUE(c + 4);
        cpa_commit();

        const float4* kb = pipe + (c % 5) * 640;       // constant under unroll
        float4 kv0 = kb[kidx0];
        float4 kv1 = kb[kidx1];
        const ulonglong2* wp = wq + c * 64;            // constant offset
        #pragma unroll
        for (int dl = 0; dl < 4; dl++) {
            ulonglong2 p0 = wp[dl * 4 + 0], p1 = wp[dl * 4 + 1];
            ulonglong2 p2 = wp[dl * 4 + 2], p3 = wp[dl * 4 + 3];
            float kf0 = ((const float*)&kv0)[dl];
            float kf1 = ((const float*)&kv1)[dl];
            ull kk0 = pk2(kf0, kf0), kk1 = pk2(kf1, kf1);
            acc[0][0] = fma2(kk0, p0.x, acc[0][0]); acc[0][1] = fma2(kk0, p0.y, acc[0][1]);
            acc[0][2] = fma2(kk0, p1.x, acc[0][2]); acc[0][3] = fma2(kk0, p1.y, acc[0][3]);
            acc[0][4] = fma2(kk0, p2.x, acc[0][4]); acc[0][5] = fma2(kk0, p2.y, acc[0][5]);
            acc[0][6] = fma2(kk0, p3.x, acc[0][6]); acc[0][7] = fma2(kk0, p3.y, acc[0][7]);
            acc[1][0] = fma2(kk1, p0.x, acc[1][0]); acc[1][1] = fma2(kk1, p0.y, acc[1][1]);
            acc[1][2] = fma2(kk1, p1.x, acc[1][2]); acc[1][3] = fma2(kk1, p1.y, acc[1][3]);
            acc[1][4] = fma2(kk1, p2.x, acc[1][4]); acc[1][5] = fma2(kk1, p2.y, acc[1][5]);
            acc[1][6] = fma2(kk1, p3.x, acc[1][6]); acc[1][7] = fma2(kk1, p3.y, acc[1][7]);
        }
    }
#undef KS_ISSUE

    // reduce the 4 dg partials via smem (reuse ring region; stride 9 avoids conflicts)
    __syncthreads();
    ull* sred = (ull*)(sm + 4096);        // 4 * 1200 ull = 38400 B <= 50 KB
    #pragma unroll
    for (int i = 0; i < 2; i++)
        #pragma unroll
        for (int p = 0; p < 8; p++)
            sred[dg * 1200 + (r + 64 * i) * 9 + p] = acc[i][p];
    __syncthreads();

    const int row = tid >> 1, pb = (tid & 1) * 4;
    const int s = st * 128 + row;
    float* outp = g_scores_part[dq];
    #pragma unroll
    for (int j = 0; j < 4; j++) {
        int p = pb + j;
        ull t = add2(add2(sred[row * 9 + p],        sred[1200 + row * 9 + p]),
                     add2(sred[2400 + row * 9 + p], sred[3600 + row * 9 + p]));
        float lo, hi; upk2(lo, hi, t);
        outp[(size_t)(b * 16 + 2 * p) * 2048 + s]     = lo;
        outp[(size_t)(b * 16 + 2 * p + 1) * 2048 + s] = hi;
    }
}

// softmax over s per (b,h); sums 4 d-partials; write attn[b][s][h]
__global__ __launch_bounds__(256) void k_softmax() {
    int b = blockIdx.x, h = blockIdx.y, tid = threadIdx.x;
    size_t off = (size_t)(b * 16 + h) * 2048;
    float x[8], m = -1e30f;
    #pragma unroll
    for (int i = 0; i < 8; i++) {
        int s = tid + i * 256;
        float v = g_scores_part[0][off + s] + g_scores_part[1][off + s]
                + g_scores_part[2][off + s] + g_scores_part[3][off + s];
        x[i] = v; m = fmaxf(m, v);
    }
    __shared__ float red[8];
    #pragma unroll
    for (int o = 16; o; o >>= 1) m = fmaxf(m, __shfl_xor_sync(0xffffffffu, m, o));
    if ((tid & 31) == 0) red[tid >> 5] = m;
    __syncthreads();
    float M = red[0];
    #pragma unroll
    for (int i = 1; i < 8; i++) M = fmaxf(M, red[i]);
    __syncthreads();
    float ssum = 0.f;
    #pragma unroll
    for (int i = 0; i < 8; i++) { x[i] = __expf(x[i] - M); ssum += x[i]; }
    #pragma unroll
    for (int o = 16; o; o >>= 1) ssum += __shfl_xor_sync(0xffffffffu, ssum, o);
    if ((tid & 31) == 0) red[tid >> 5] = ssum;
    __syncthreads();
    float T = 0.f;
    #pragma unroll
    for (int i = 0; i < 8; i++) T += red[i];
    float inv = 1.0f / T;
    #pragma unroll
    for (int i = 0; i < 8; i++)
        g_attn[((size_t)b * 2048 + tid + i * 256) * 16 + h] = x[i] * inv;
}

// ---------------- pass 2: stream v -> partial vbar ----------------
// grid (64 b, 2 dh, 8 sq). CTA: 256 s x 512 d x 16 h; 32 stages of 8 s via
// 4-stage cp.async ring (c&3, constants under x4 unroll). Thread (hg=tid>>7,
// dt=tid&127): 4 d x 8 heads x 8 s per stage. 67584 B smem, 3 CTAs/SM.
__global__ __launch_bounds__(256, 3) void k_vbar(const float* __restrict__ v) {
    extern __shared__ float vsm[];             // 4 stages x 4224 floats
    const int b = blockIdx.x, dh = blockIdx.y, sq = blockIdx.z;
    const int tid = threadIdx.x;
    const int hg = tid >> 7, dt = tid & 127;
    const size_t sBase = (size_t)b * 2048 + sq * 256;
    const float4* vg = (const float4*)v;
    const float4* ag = (const float4*)g_attn;
    const unsigned smb = smem_u32(vsm);

    // precomputed per-thread cp.async endpoints (constants + c*2048 f4 bump)
    const int sl0 = tid >> 7, col0v = tid & 127;
    const float4* vg0 = vg + (sBase + sl0) * 256 + dh * 128 + col0v;   // + i2*2*256
    const float4* agp = ag + sBase * 4 + tid;                           // tid<32 only
    const unsigned vs_off = (unsigned)tid * 16u;

#define VB_ISSUE(c, stg) do { \
    unsigned sb = smb + (unsigned)((stg) * 16896); \
    _Pragma("unroll") \
    for (int i2 = 0; i2 < 4; i2++) \
        cpa16(sb + vs_off + (unsigned)i2 * 4096u, \
              vg0 + ((size_t)(c) * 8 + i2 * 2) * 256); \
    if (tid < 32) cpa16(sb + 16384u + (unsigned)tid * 16u, agp + (c) * 32); \
} while (0)

    VB_ISSUE(0, 0); cpa_commit();
    VB_ISSUE(1, 1); cpa_commit();
    VB_ISSUE(2, 2); cpa_commit();

    ull acc[4][4];
    #pragma unroll
    for (int d = 0; d < 4; d++)
        #pragma unroll
        for (int hp = 0; hp < 4; hp++) acc[d][hp] = 0ull;

    const int abase = hg * 8;
    for (int cc = 0; cc < 8; cc++) {
        #pragma unroll
        for (int u = 0; u < 4; u++) {
            const int c = cc * 4 + u;
            cpa_wait<2>();
            __syncthreads();
            if (c + 3 < 32) VB_ISSUE(c + 3, (u + 3) & 3);
            cpa_commit();

            const float* stg = vsm + u * 4224;            // constant stage
            const float4* vb4 = (const float4*)stg + dt;  // [8 s][128 f4]
            const float* ab = stg + 4096 + abase;         // [8 s][16 h]
            #pragma unroll
            for (int sl = 0; sl < 8; sl++) {
                float4 vv = vb4[sl * 128];
                ulonglong2 a01 = *(const ulonglong2*)(ab + sl * 16);
                ulonglong2 a23 = *(const ulonglong2*)(ab + sl * 16 + 4);
                ull v0 = pk2(vv.x, vv.x), v1 = pk2(vv.y, vv.y);
                ull v2 = pk2(vv.z, vv.z), v3 = pk2(vv.w, vv.w);
                acc[0][0] = fma2(a01.x, v0, acc[0][0]); acc[1][0] = fma2(a01.x, v1, acc[1][0]);
                acc[2][0] = fma2(a01.x, v2, acc[2][0]); acc[3][0] = fma2(a01.x, v3, acc[3][0]);
                acc[0][1] = fma2(a01.y, v0, acc[0][1]); acc[1][1] = fma2(a01.y, v1, acc[1][1]);
                acc[2][1] = fma2(a01.y, v2, acc[2][1]); acc[3][1] = fma2(a01.y, v3, acc[3][1]);
                acc[0][2] = fma2(a23.x, v0, acc[0][2]); acc[1][2] = fma2(a23.x, v1, acc[1][2]);
                acc[2][2] = fma2(a23.x, v2, acc[2][2]); acc[3][2] = fma2(a23.x, v3, acc[3][2]);
                acc[0][3] = fma2(a23.y, v0, acc[0][3]); acc[1][3] = fma2(a23.y, v1, acc[1][3]);
                acc[2][3] = fma2(a23.y, v2, acc[2][3]); acc[3][3] = fma2(a23.y, v3, acc[3][3]);
            }
        }
    }
#undef VB_ISSUE

    float* outp = g_vbar_part[sq] + (size_t)b * 16384;
    const int d0 = dh * 512 + dt * 4;
    #pragma unroll
    for (int hp = 0; hp < 4; hp++) {
        float lo0, hi0, lo1, hi1, lo2, hi2, lo3, hi3;
        upk2(lo0, hi0, acc[0][hp]); upk2(lo1, hi1, acc[1][hp]);
        upk2(lo2, hi2, acc[2][hp]); upk2(lo3, hi3, acc[3][hp]);
        float4 e; e.x = lo0; e.y = lo1; e.z = lo2; e.w = lo3;
        float4 o; o.x = hi0; o.y = hi1; o.z = hi2; o.w = hi3;
        int h0 = hg * 8 + 2 * hp;
        *(float4*)&outp[(size_t)h0 * 1024 + d0]       = e;
        *(float4*)&outp[(size_t)(h0 + 1) * 1024 + d0] = o;
    }
}

__global__ __launch_bounds__(256) void k_relu(float* __restrict__ out) {
    int i = blockIdx.x * 256 + threadIdx.x;
    out[i] = fmaxf(g_outpre[i], 0.0f);
}

extern "C" void kernel_launch(void* const* d_in, const int* in_sizes, int n_in,
                              void* d_out, int out_size) {
    const float* q  = (const float*)d_in[0];
    const float* k  = (const float*)d_in[1];
    const float* v  = (const float*)d_in[2];
    const float* Wq = (const float*)d_in[3];
    const float* bq = (const float*)d_in[4];
    const float* Wk = (const float*)d_in[5];
    // d_in[6] = bk — cancels in softmax
    const float* Wv = (const float*)d_in[7];
    const float* bv = (const float*)d_in[8];
    const float* Wo = (const float*)d_in[9];
    const float* bo = (const float*)d_in[10];

    const int smem_scores = 4096 * 4 + 5 * 640 * 16;   // 67584
    const int smem_vbar   = 4 * 16896;                 // 67584
    static bool attr_done = false;
    if (!attr_done) {
        cudaFuncSetAttribute(k_scores, cudaFuncAttributeMaxDynamicSharedMemorySize, smem_scores);
        cudaFuncSetAttribute(k_vbar,   cudaFuncAttributeMaxDynamicSharedMemorySize, smem_vbar);
        attr_done = true;
    }

    k_init<<<256, 256>>>(bq, bv, bo);
    gemm_ksplit<<<dim3(16, 16), 256>>>(q, Wq, 0);
    k_ws<<<dim3(16, 8, 4), 256>>>(Wk);
    k_scores<<<dim3(64, 16, 4), 256, smem_scores>>>(k);
    k_softmax<<<dim3(64, 16), 256>>>();
    k_vbar<<<dim3(64, 2, 8), 256, smem_vbar>>>(v);
    gemm_ksplit<<<dim3(16, 16), 256>>>(nullptr, Wv, 1);
    gemm_ksplit<<<dim3(16, 16), 256>>>(nullptr, Wo, 2);
    k_relu<<<256, 256>>>((float*)d_out);
}

// round 10
// speedup vs baseline: 3.4347x; 1.0331x over previous
#include <cuda_runtime.h>
#include <cstdint>
#include <cstddef>

typedef unsigned long long ull;

// device scratch (allocs forbidden)
__device__ float g_qh[64 * 1024];
__device__ float g_ws[64 * 1024 * 16];                 // [b][d][h]
__device__ float g_scores_part[4][64 * 16 * 2048];     // [dq][b][h][s]
__device__ float g_attn[64 * 2048 * 16];               // [b][s][h]
__device__ float g_vbar_part[8][64 * 16 * 1024];       // [sq][b][h][d]
__device__ float g_concat[64 * 1024];
__device__ float g_outpre[64 * 1024];

__device__ __forceinline__ ull pk2(float x, float y) {
    ull r; asm("mov.b64 %0, {%1,%2};" : "=l"(r) : "f"(x), "f"(y)); return r;
}
__device__ __forceinline__ void upk2(float& x, float& y, ull v) {
    asm("mov.b64 {%0,%1}, %2;" : "=f"(x), "=f"(y) : "l"(v));
}
__device__ __forceinline__ ull fma2(ull a, ull b, ull c) {
    ull d; asm("fma.rn.f32x2 %0, %1, %2, %3;" : "=l"(d) : "l"(a), "l"(b), "l"(c)); return d;
}
__device__ __forceinline__ ull add2(ull a, ull b) {
    ull c; asm("add.rn.f32x2 %0, %1, %2;" : "=l"(c) : "l"(a), "l"(b)); return c;
}
__device__ __forceinline__ unsigned smem_u32(const void* p) {
    return (unsigned)__cvta_generic_to_shared(p);
}
__device__ __forceinline__ void cpa16(unsigned s, const void* g) {
    asm volatile("cp.async.cg.shared.global [%0], [%1], 16;" :: "r"(s), "l"(g));
}
__device__ __forceinline__ void cpa_commit() {
    asm volatile("cp.async.commit_group;" ::: "memory");
}
template <int N> __device__ __forceinline__ void cpa_wait() {
    asm volatile("cp.async.wait_group %0;" :: "n"(N) : "memory");
}

__global__ __launch_bounds__(256) void k_init(const float* __restrict__ bq,
                                              const float* __restrict__ bv,
                                              const float* __restrict__ bo) {
    int i = blockIdx.x * 256 + threadIdx.x;
    int c = i & 1023;
    g_qh[i] = bq[c]; g_concat[i] = bv[c]; g_outpre[i] = bo[c];
}

// C[64,1024] += A[64,1024] @ W[1024,1024]; 16-way k-split over by, 64-col tiles over bx.
// mode 0: A=q -> g_qh | mode 1: A=sum of 8 vbar partials (head h=bx) -> g_concat
// mode 2: A=g_concat -> g_outpre
__global__ __launch_bounds__(256) void gemm_ksplit(const float* __restrict__ Ain,
                                                   const float* __restrict__ W, int mode) {
    __shared__ float As[64 * 68];
    __shared__ float Wsm[64 * 64];
    int bx = blockIdx.x, by = blockIdx.y, tid = threadIdx.x;
    int col0 = bx * 64, db = by * 64;

    if (mode == 1) {
        for (int idx = tid; idx < 4096; idx += 256) {
            int bb = idx >> 6, dd = idx & 63;
            size_t off = (size_t)bb * 16384 + (size_t)bx * 1024 + db + dd;
            float s = 0.f;
            #pragma unroll
            for (int p = 0; p < 8; p++) s += g_vbar_part[p][off];
            As[bb * 68 + dd] = s;
        }
    } else {
        const float* A = (mode == 0) ? Ain : g_concat;
        for (int idx = tid; idx < 4096; idx += 256) {
            int bb = idx >> 6, dd = idx & 63;
            As[bb * 68 + dd] = A[(size_t)bb * 1024 + db + dd];
        }
    }
    for (int idx = tid; idx < 4096; idx += 256) {
        int dd = idx >> 6, j = idx & 63;
        Wsm[dd * 64 + j] = W[(size_t)(db + dd) * 1024 + col0 + j];
    }
    __syncthreads();

    int tj = tid & 15, tb = tid >> 4;
    float acc[4][4] = {};
    const float4* Ws4 = (const float4*)Wsm;
    #pragma unroll 8
    for (int dd = 0; dd < 64; dd++) {
        float4 w = Ws4[dd * 16 + tj];
        #pragma unroll
        for (int bb = 0; bb < 4; bb++) {
            float a = As[(tb * 4 + bb) * 68 + dd];
            acc[bb][0] = fmaf(a, w.x, acc[bb][0]);
            acc[bb][1] = fmaf(a, w.y, acc[bb][1]);
            acc[bb][2] = fmaf(a, w.z, acc[bb][2]);
            acc[bb][3] = fmaf(a, w.w, acc[bb][3]);
        }
    }
    float* C = (mode == 0) ? g_qh : (mode == 1) ? g_concat : g_outpre;
    #pragma unroll
    for (int bb = 0; bb < 4; bb++)
        #pragma unroll
        for (int jj = 0; jj < 4; jj++)
            atomicAdd(&C[(size_t)(tb * 4 + bb) * 1024 + col0 + tj * 4 + jj], acc[bb][jj]);
}

// g_ws[b][d][h] = 0.125 * sum_j Wk[d, 64h+j] * g_qh[b, 64h+j]; grid (16 dt, 8 bt, 4 hz)
__global__ __launch_bounds__(256) void k_ws(const float* __restrict__ Wk) {
    __shared__ float Wks[64 * 68];
    __shared__ float qhs[8 * 64];
    int dt = blockIdx.x, bt = blockIdx.y, hz = blockIdx.z, tid = threadIdx.x;
    int td = tid & 63, tg = tid >> 6;
    for (int hi = 0; hi < 4; hi++) {
        int h = hz * 4 + hi;
        __syncthreads();
        for (int idx = tid; idx < 4096; idx += 256) {
            int dd = idx >> 6, j = idx & 63;
            Wks[dd * 68 + j] = Wk[(size_t)(dt * 64 + dd) * 1024 + h * 64 + j];
        }
        for (int idx = tid; idx < 512; idx += 256) {
            int bb = idx >> 6, j = idx & 63;
            qhs[bb * 64 + j] = g_qh[(size_t)(bt * 8 + bb) * 1024 + h * 64 + j];
        }
        __syncthreads();
        float a0 = 0.f, a1 = 0.f;
        #pragma unroll
        for (int j4 = 0; j4 < 16; j4++) {
            float4 w  = *(const float4*)&Wks[td * 68 + j4 * 4];
            float4 qa = *(const float4*)&qhs[(tg * 2 + 0) * 64 + j4 * 4];
            float4 qb = *(const float4*)&qhs[(tg * 2 + 1) * 64 + j4 * 4];
            a0 = fmaf(w.x, qa.x, fmaf(w.y, qa.y, fmaf(w.z, qa.z, fmaf(w.w, qa.w, a0))));
            a1 = fmaf(w.x, qb.x, fmaf(w.y, qb.y, fmaf(w.z, qb.z, fmaf(w.w, qb.w, a1))));
        }
        int d = dt * 64 + td;
        g_ws[((size_t)(bt * 8 + tg * 2 + 0) * 1024 + d) * 16 + h] = a0 * 0.125f;
        g_ws[((size_t)(bt * 8 + tg * 2 + 1) * 1024 + d) * 16 + h] = a1 * 0.125f;
    }
}

// ---------------- pass 1: stream k -> partial scores ----------------
// grid (64 b, 16 st, 4 dq). CTA tile: 128 s x 256 d, 16 chunks of 16 d.
// 5-stage cp.async ring, fully unrolled (all indices immediate).
// Thread (hg=tid>>7, dg=(tid>>5)&3, r=tid&31): 4 rows {r,r+32,r+64,r+96},
// 8 heads (hg half), 4 d per chunk (f4-col dg). Per chunk: 4 k-LDS +
// 8 broadcast w-LDS + 64 fma2, 16 independent acc chains.
// dyn smem = 16KB ws + 50KB ring = 67584 B; 3 CTAs/SM.
__global__ __launch_bounds__(256, 3) void k_scores(const float* __restrict__ k) {
    extern __shared__ float sm[];
    float* ws_s = sm;                          // 4096 f: [256 d][16 h]
    float4* pipe = (float4*)(sm + 4096);       // 5 stages x 640 f4
    const int b = blockIdx.x, st = blockIdx.y, dq = blockIdx.z;
    const int tid = threadIdx.x;
    const int r = tid & 31;
    const int dg = (tid >> 5) & 3;
    const int hg = tid >> 7;

    {   // stage ws slice (coalesced)
        const float4* src = (const float4*)(g_ws + (size_t)b * 16384 + dq * 4096);
        float4* dst = (float4*)ws_s;
        #pragma unroll
        for (int i = 0; i < 4; i++) dst[tid + i * 256] = src[tid + i * 256];
    }

    const float4* k4 = (const float4*)k;
    const size_t gbase = ((size_t)b * 2048 + st * 128) * 256 + dq * 64;   // f4 units
    const int row0 = tid >> 2, colx = tid & 3;
    const int row1 = (tid + 256) >> 2;
    const float4* kg0 = k4 + gbase + (size_t)row0 * 256 + colx;
    const float4* kg1 = k4 + gbase + (size_t)row1 * 256 + colx;
    const unsigned sbase = smem_u32(pipe);
    const unsigned s0off = sbase + (unsigned)(row0 * 5 + colx) * 16u;
    const unsigned s1off = sbase + (unsigned)(row1 * 5 + colx) * 16u;

#define KS_ISSUE(c) do { \
    cpa16(s0off + (unsigned)(((c) % 5) * 640) * 16u, kg0 + (c) * 4); \
    cpa16(s1off + (unsigned)(((c) % 5) * 640) * 16u, kg1 + (c) * 4); \
} while (0)

    #pragma unroll
    for (int c = 0; c < 4; c++) { KS_ISSUE(c); cpa_commit(); }

    ull acc[4][4];   // [row i][h-pair p within hg]
    #pragma unroll
    for (int i = 0; i < 4; i++)
        #pragma unroll
        for (int p = 0; p < 4; p++) acc[i][p] = 0ull;

    const ulonglong2* wq = (const ulonglong2*)ws_s;   // [d][4 x ulonglong2]
    const int kidx0 = r * 5 + dg, kidx1 = (r + 32) * 5 + dg;
    const int kidx2 = (r + 64) * 5 + dg, kidx3 = (r + 96) * 5 + dg;
    const int wbase = hg * 2;

    #pragma unroll
    for (int c = 0; c < 16; c++) {
        cpa_wait<3>();
        __syncthreads();
        if (c + 4 < 16) KS_ISSUE(c + 4);
        cpa_commit();

        const float4* kb = pipe + (c % 5) * 640;       // constant under unroll
        float4 kv0 = kb[kidx0];
        float4 kv1 = kb[kidx1];
        float4 kv2 = kb[kidx2];
        float4 kv3 = kb[kidx3];
        #pragma unroll
        for (int dl = 0; dl < 4; dl++) {
            const int dd = c * 16 + dg * 4 + dl;       // constant offsets
            ulonglong2 w0 = wq[dd * 4 + wbase];
            ulonglong2 w1 = wq[dd * 4 + wbase + 1];
            float kf0 = ((const float*)&kv0)[dl];
            float kf1 = ((const float*)&kv1)[dl];
            float kf2 = ((const float*)&kv2)[dl];
            float kf3 = ((const float*)&kv3)[dl];
            ull kk0 = pk2(kf0, kf0), kk1 = pk2(kf1, kf1);
            ull kk2 = pk2(kf2, kf2), kk3 = pk2(kf3, kf3);
            acc[0][0] = fma2(kk0, w0.x, acc[0][0]); acc[0][1] = fma2(kk0, w0.y, acc[0][1]);
            acc[0][2] = fma2(kk0, w1.x, acc[0][2]); acc[0][3] = fma2(kk0, w1.y, acc[0][3]);
            acc[1][0] = fma2(kk1, w0.x, acc[1][0]); acc[1][1] = fma2(kk1, w0.y, acc[1][1]);
            acc[1][2] = fma2(kk1, w1.x, acc[1][2]); acc[1][3] = fma2(kk1, w1.y, acc[1][3]);
            acc[2][0] = fma2(kk2, w0.x, acc[2][0]); acc[2][1] = fma2(kk2, w0.y, acc[2][1]);
            acc[2][2] = fma2(kk2, w1.x, acc[2][2]); acc[2][3] = fma2(kk2, w1.y, acc[2][3]);
            acc[3][0] = fma2(kk3, w0.x, acc[3][0]); acc[3][1] = fma2(kk3, w0.y, acc[3][1]);
            acc[3][2] = fma2(kk3, w1.x, acc[3][2]); acc[3][3] = fma2(kk3, w1.y, acc[3][3]);
        }
    }
#undef KS_ISSUE

    // reduce the 4 dg partials via smem (reuse ring region; stride 9 pad)
    __syncthreads();
    ull* sred = (ull*)(sm + 4096);        // 4 * 1152 ull = 36864 B <= 50 KB
    #pragma unroll
    for (int i = 0; i < 4; i++)
        #pragma unroll
        for (int p = 0; p < 4; p++)
            sred[dg * 1152 + (r + 32 * i) * 9 + hg * 4 + p] = acc[i][p];
    __syncthreads();

    const int row = tid >> 1, pb = (tid & 1) * 4;
    const int s = st * 128 + row;
    float* outp = g_scores_part[dq];
    #pragma unroll
    for (int j = 0; j < 4; j++) {
        int p = pb + j;
        ull t = add2(add2(sred[row * 9 + p],        sred[1152 + row * 9 + p]),
                     add2(sred[2304 + row * 9 + p], sred[3456 + row * 9 + p]));
        float lo, hi; upk2(lo, hi, t);
        outp[(size_t)(b * 16 + 2 * p) * 2048 + s]     = lo;
        outp[(size_t)(b * 16 + 2 * p + 1) * 2048 + s] = hi;
    }
}

// softmax over s per (b,h); sums 4 d-partials; write attn[b][s][h]
__global__ __launch_bounds__(256) void k_softmax() {
    int b = blockIdx.x, h = blockIdx.y, tid = threadIdx.x;
    size_t off = (size_t)(b * 16 + h) * 2048;
    float x[8], m = -1e30f;
    #pragma unroll
    for (int i = 0; i < 8; i++) {
        int s = tid + i * 256;
        float v = g_scores_part[0][off + s] + g_scores_part[1][off + s]
                + g_scores_part[2][off + s] + g_scores_part[3][off + s];
        x[i] = v; m = fmaxf(m, v);
    }
    __shared__ float red[8];
    #pragma unroll
    for (int o = 16; o; o >>= 1) m = fmaxf(m, __shfl_xor_sync(0xffffffffu, m, o));
    if ((tid & 31) == 0) red[tid >> 5] = m;
    __syncthreads();
    float M = red[0];
    #pragma unroll
    for (int i = 1; i < 8; i++) M = fmaxf(M, red[i]);
    __syncthreads();
    float ssum = 0.f;
    #pragma unroll
    for (int i = 0; i < 8; i++) { x[i] = __expf(x[i] - M); ssum += x[i]; }
    #pragma unroll
    for (int o = 16; o; o >>= 1) ssum += __shfl_xor_sync(0xffffffffu, ssum, o);
    if ((tid & 31) == 0) red[tid >> 5] = ssum;
    __syncthreads();
    float T = 0.f;
    #pragma unroll
    for (int i = 0; i < 8; i++) T += red[i];
    float inv = 1.0f / T;
    #pragma unroll
    for (int i = 0; i < 8; i++)
        g_attn[((size_t)b * 2048 + tid + i * 256) * 16 + h] = x[i] * inv;
}

// ---------------- pass 2: stream v -> partial vbar ----------------
// grid (64 b, 2 dh, 8 sq). CTA: 256 s x 512 d x 16 h; 32 stages of 8 s via
// 4-stage cp.async ring (constants under x4 unroll). Thread (hg=tid>>7,
// dt=tid&127): 4 d x 8 heads x 8 s per stage. 67584 B smem, 3 CTAs/SM.
__global__ __launch_bounds__(256, 3) void k_vbar(const float* __restrict__ v) {
    extern __shared__ float vsm[];             // 4 stages x 4224 floats
    const int b = blockIdx.x, dh = blockIdx.y, sq = blockIdx.z;
    const int tid = threadIdx.x;
    const int hg = tid >> 7, dt = tid & 127;
    const size_t sBase = (size_t)b * 2048 + sq * 256;
    const float4* vg = (const float4*)v;
    const float4* ag = (const float4*)g_attn;
    const unsigned smb = smem_u32(vsm);

    const int sl0 = tid >> 7;
    const float4* vg0 = vg + (sBase + sl0) * 256 + dh * 128 + (tid & 127);
    const float4* agp = ag + sBase * 4 + tid;
    const unsigned vs_off = (unsigned)tid * 16u;

#define VB_ISSUE(c, stg) do { \
    unsigned sb = smb + (unsigned)((stg) * 16896); \
    _Pragma("unroll") \
    for (int i2 = 0; i2 < 4; i2++) \
        cpa16(sb + vs_off + (unsigned)i2 * 4096u, \
              vg0 + ((size_t)(c) * 8 + i2 * 2) * 256); \
    if (tid < 32) cpa16(sb + 16384u + (unsigned)tid * 16u, agp + (c) * 32); \
} while (0)

    VB_ISSUE(0, 0); cpa_commit();
    VB_ISSUE(1, 1); cpa_commit();
    VB_ISSUE(2, 2); cpa_commit();

    ull acc[4][4];
    #pragma unroll
    for (int d = 0; d < 4; d++)
        #pragma unroll
        for (int hp = 0; hp < 4; hp++) acc[d][hp] = 0ull;

    const int abase = hg * 8;
    for (int cc = 0; cc < 8; cc++) {
        #pragma unroll
        for (int u = 0; u < 4; u++) {
            const int c = cc * 4 + u;
            cpa_wait<2>();
            __syncthreads();
            if (c + 3 < 32) VB_ISSUE(c + 3, (u + 3) & 3);
            cpa_commit();

            const float* stg = vsm + u * 4224;
            const float4* vb4 = (const float4*)stg + dt;
            const float* ab = stg + 4096 + abase;
            #pragma unroll
            for (int sl = 0; sl < 8; sl++) {
                float4 vv = vb4[sl * 128];
                ulonglong2 a01 = *(const ulonglong2*)(ab + sl * 16);
                ulonglong2 a23 = *(const ulonglong2*)(ab + sl * 16 + 4);
                ull v0 = pk2(vv.x, vv.x), v1 = pk2(vv.y, vv.y);
                ull v2 = pk2(vv.z, vv.z), v3 = pk2(vv.w, vv.w);
                acc[0][0] = fma2(a01.x, v0, acc[0][0]); acc[1][0] = fma2(a01.x, v1, acc[1][0]);
                acc[2][0] = fma2(a01.x, v2, acc[2][0]); acc[3][0] = fma2(a01.x, v3, acc[3][0]);
                acc[0][1] = fma2(a01.y, v0, acc[0][1]); acc[1][1] = fma2(a01.y, v1, acc[1][1]);
                acc[2][1] = fma2(a01.y, v2, acc[2][1]); acc[3][1] = fma2(a01.y, v3, acc[3][1]);
                acc[0][2] = fma2(a23.x, v0, acc[0][2]); acc[1][2] = fma2(a23.x, v1, acc[1][2]);
                acc[2][2] = fma2(a23.x, v2, acc[2][2]); acc[3][2] = fma2(a23.x, v3, acc[3][2]);
                acc[0][3] = fma2(a23.y, v0, acc[0][3]); acc[1][3] = fma2(a23.y, v1, acc[1][3]);
                acc[2][3] = fma2(a23.y, v2, acc[2][3]); acc[3][3] = fma2(a23.y, v3, acc[3][3]);
            }
        }
    }
#undef VB_ISSUE

    float* outp = g_vbar_part[sq] + (size_t)b * 16384;
    const int d0 = dh * 512 + dt * 4;
    #pragma unroll
    for (int hp = 0; hp < 4; hp++) {
        float lo0, hi0, lo1, hi1, lo2, hi2, lo3, hi3;
        upk2(lo0, hi0, acc[0][hp]); upk2(lo1, hi1, acc[1][hp]);
        upk2(lo2, hi2, acc[2][hp]); upk2(lo3, hi3, acc[3][hp]);
        float4 e; e.x = lo0; e.y = lo1; e.z = lo2; e.w = lo3;
        float4 o; o.x = hi0; o.y = hi1; o.z = hi2; o.w = hi3;
        int h0 = hg * 8 + 2 * hp;
        *(float4*)&outp[(size_t)h0 * 1024 + d0]       = e;
        *(float4*)&outp[(size_t)(h0 + 1) * 1024 + d0] = o;
    }
}

__global__ __launch_bounds__(256) void k_relu(float* __restrict__ out) {
    int i = blockIdx.x * 256 + threadIdx.x;
    out[i] = fmaxf(g_outpre[i], 0.0f);
}

extern "C" void kernel_launch(void* const* d_in, const int* in_sizes, int n_in,
                              void* d_out, int out_size) {
    const float* q  = (const float*)d_in[0];
    const float* k  = (const float*)d_in[1];
    const float* v  = (const float*)d_in[2];
    const float* Wq = (const float*)d_in[3];
    const float* bq = (const float*)d_in[4];
    const float* Wk = (const float*)d_in[5];
    // d_in[6] = bk — cancels in softmax
    const float* Wv = (const float*)d_in[7];
    const float* bv = (const float*)d_in[8];
    const float* Wo = (const float*)d_in[9];
    const float* bo = (const float*)d_in[10];

    const int smem_scores = 4096 * 4 + 5 * 640 * 16;   // 67584
    const int smem_vbar   = 4 * 16896;                 // 67584
    static bool attr_done = false;
    if (!attr_done) {
        cudaFuncSetAttribute(k_scores, cudaFuncAttributeMaxDynamicSharedMemorySize, smem_scores);
        cudaFuncSetAttribute(k_vbar,   cudaFuncAttributeMaxDynamicSharedMemorySize, smem_vbar);
        attr_done = true;
    }

    k_init<<<256, 256>>>(bq, bv, bo);
    gemm_ksplit<<<dim3(16, 16), 256>>>(q, Wq, 0);
    k_ws<<<dim3(16, 8, 4), 256>>>(Wk);
    k_scores<<<dim3(64, 16, 4), 256, smem_scores>>>(k);
    k_softmax<<<dim3(64, 16), 256>>>();
    k_vbar<<<dim3(64, 2, 8), 256, smem_vbar>>>(v);
    gemm_ksplit<<<dim3(16, 16), 256>>>(nullptr, Wv, 1);
    gemm_ksplit<<<dim3(16, 16), 256>>>(nullptr, Wo, 2);
    k_relu<<<256, 256>>>((float*)d_out);
}

// round 11
// speedup vs baseline: 3.4465x; 1.0034x over previous
#include <cuda_runtime.h>
#include <cstdint>
#include <cstddef>

typedef unsigned long long ull;

// device scratch (allocs forbidden)
__device__ float g_qh[64 * 1024];
__device__ float g_ws[64 * 1024 * 16];                 // [b][d][h]
__device__ float g_scores_part[4][64 * 16 * 2048];     // [dq][b][h][s]
__device__ float g_attn[64 * 2048 * 16];               // [b][s][h]
__device__ float g_vbar_part[16][64 * 16 * 1024];      // [sq][b][h][d]
__device__ float g_concat[64 * 1024];
__device__ float g_outpre[64 * 1024];

__device__ __forceinline__ ull pk2(float x, float y) {
    ull r; asm("mov.b64 %0, {%1,%2};" : "=l"(r) : "f"(x), "f"(y)); return r;
}
__device__ __forceinline__ void upk2(float& x, float& y, ull v) {
    asm("mov.b64 {%0,%1}, %2;" : "=f"(x), "=f"(y) : "l"(v));
}
__device__ __forceinline__ ull fma2(ull a, ull b, ull c) {
    ull d; asm("fma.rn.f32x2 %0, %1, %2, %3;" : "=l"(d) : "l"(a), "l"(b), "l"(c)); return d;
}
__device__ __forceinline__ ull add2(ull a, ull b) {
    ull c; asm("add.rn.f32x2 %0, %1, %2;" : "=l"(c) : "l"(a), "l"(b)); return c;
}
__device__ __forceinline__ unsigned smem_u32(const void* p) {
    return (unsigned)__cvta_generic_to_shared(p);
}
__device__ __forceinline__ void cpa16(unsigned s, const void* g) {
    asm volatile("cp.async.cg.shared.global [%0], [%1], 16;" :: "r"(s), "l"(g));
}
__device__ __forceinline__ void cpa_commit() {
    asm volatile("cp.async.commit_group;" ::: "memory");
}
template <int N> __device__ __forceinline__ void cpa_wait() {
    asm volatile("cp.async.wait_group %0;" :: "n"(N) : "memory");
}

__global__ __launch_bounds__(256) void k_init(const float* __restrict__ bq,
                                              const float* __restrict__ bv,
                                              const float* __restrict__ bo) {
    int i = blockIdx.x * 256 + threadIdx.x;
    int c = i & 1023;
    g_qh[i] = bq[c]; g_concat[i] = bv[c]; g_outpre[i] = bo[c];
}

// C[64,1024] += A[64,1024] @ W[1024,1024]; 16-way k-split over by, 64-col tiles over bx.
// mode 0: A=q -> g_qh | mode 1: A=sum of 16 vbar partials (head h=bx) -> g_concat
// mode 2: A=g_concat -> g_outpre
__global__ __launch_bounds__(256) void gemm_ksplit(const float* __restrict__ Ain,
                                                   const float* __restrict__ W, int mode) {
    __shared__ float As[64 * 68];
    __shared__ float Wsm[64 * 64];
    int bx = blockIdx.x, by = blockIdx.y, tid = threadIdx.x;
    int col0 = bx * 64, db = by * 64;

    if (mode == 1) {
        for (int idx = tid; idx < 4096; idx += 256) {
            int bb = idx >> 6, dd = idx & 63;
            size_t off = (size_t)bb * 16384 + (size_t)bx * 1024 + db + dd;
            float s = 0.f;
            #pragma unroll
            for (int p = 0; p < 16; p++) s += g_vbar_part[p][off];
            As[bb * 68 + dd] = s;
        }
    } else {
        const float* A = (mode == 0) ? Ain : g_concat;
        for (int idx = tid; idx < 4096; idx += 256) {
            int bb = idx >> 6, dd = idx & 63;
            As[bb * 68 + dd] = A[(size_t)bb * 1024 + db + dd];
        }
    }
    for (int idx = tid; idx < 4096; idx += 256) {
        int dd = idx >> 6, j = idx & 63;
        Wsm[dd * 64 + j] = W[(size_t)(db + dd) * 1024 + col0 + j];
    }
    __syncthreads();

    int tj = tid & 15, tb = tid >> 4;
    float acc[4][4] = {};
    const float4* Ws4 = (const float4*)Wsm;
    #pragma unroll 8
    for (int dd = 0; dd < 64; dd++) {
        float4 w = Ws4[dd * 16 + tj];
        #pragma unroll
        for (int bb = 0; bb < 4; bb++) {
            float a = As[(tb * 4 + bb) * 68 + dd];
            acc[bb][0] = fmaf(a, w.x, acc[bb][0]);
            acc[bb][1] = fmaf(a, w.y, acc[bb][1]);
            acc[bb][2] = fmaf(a, w.z, acc[bb][2]);
            acc[bb][3] = fmaf(a, w.w, acc[bb][3]);
        }
    }
    float* C = (mode == 0) ? g_qh : (mode == 1) ? g_concat : g_outpre;
    #pragma unroll
    for (int bb = 0; bb < 4; bb++)
        #pragma unroll
        for (int jj = 0; jj < 4; jj++)
            atomicAdd(&C[(size_t)(tb * 4 + bb) * 1024 + col0 + tj * 4 + jj], acc[bb][jj]);
}

// g_ws[b][d][h] = 0.125 * sum_j Wk[d, 64h+j] * g_qh[b, 64h+j]; grid (16 dt, 8 bt, 4 hz)
__global__ __launch_bounds__(256) void k_ws(const float* __restrict__ Wk) {
    __shared__ float Wks[64 * 68];
    __shared__ float qhs[8 * 64];
    int dt = blockIdx.x, bt = blockIdx.y, hz = blockIdx.z, tid = threadIdx.x;
    int td = tid & 63, tg = tid >> 6;
    for (int hi = 0; hi < 4; hi++) {
        int h = hz * 4 + hi;
        __syncthreads();
        for (int idx = tid; idx < 4096; idx += 256) {
            int dd = idx >> 6, j = idx & 63;
            Wks[dd * 68 + j] = Wk[(size_t)(dt * 64 + dd) * 1024 + h * 64 + j];
        }
        for (int idx = tid; idx < 512; idx += 256) {
            int bb = idx >> 6, j = idx & 63;
            qhs[bb * 64 + j] = g_qh[(size_t)(bt * 8 + bb) * 1024 + h * 64 + j];
        }
        __syncthreads();
        float a0 = 0.f, a1 = 0.f;
        #pragma unroll
        for (int j4 = 0; j4 < 16; j4++) {
            float4 w  = *(const float4*)&Wks[td * 68 + j4 * 4];
            float4 qa = *(const float4*)&qhs[(tg * 2 + 0) * 64 + j4 * 4];
            float4 qb = *(const float4*)&qhs[(tg * 2 + 1) * 64 + j4 * 4];
            a0 = fmaf(w.x, qa.x, fmaf(w.y, qa.y, fmaf(w.z, qa.z, fmaf(w.w, qa.w, a0))));
            a1 = fmaf(w.x, qb.x, fmaf(w.y, qb.y, fmaf(w.z, qb.z, fmaf(w.w, qb.w, a1))));
        }
        int d = dt * 64 + td;
        g_ws[((size_t)(bt * 8 + tg * 2 + 0) * 1024 + d) * 16 + h] = a0 * 0.125f;
        g_ws[((size_t)(bt * 8 + tg * 2 + 1) * 1024 + d) * 16 + h] = a1 * 0.125f;
    }
}

// ---------------- pass 1: stream k -> partial scores ----------------
// grid (64 b, 16 st, 4 dq). CTA tile: 128 s x 256 d, 16 chunks of 16 d.
// 5-stage cp.async ring, fully unrolled (all indices immediate).
// Thread (hg=tid>>7, dg=(tid>>5)&3, r=tid&31): 4 rows {r,r+32,r+64,r+96},
// 8 heads (hg half), 4 d per chunk (f4-col dg). 67584 B smem; 3 CTAs/SM.
__global__ __launch_bounds__(256, 3) void k_scores(const float* __restrict__ k) {
    extern __shared__ float sm[];
    float* ws_s = sm;                          // 4096 f: [256 d][16 h]
    float4* pipe = (float4*)(sm + 4096);       // 5 stages x 640 f4
    const int b = blockIdx.x, st = blockIdx.y, dq = blockIdx.z;
    const int tid = threadIdx.x;
    const int r = tid & 31;
    const int dg = (tid >> 5) & 3;
    const int hg = tid >> 7;

    {   // stage ws slice (coalesced)
        const float4* src = (const float4*)(g_ws + (size_t)b * 16384 + dq * 4096);
        float4* dst = (float4*)ws_s;
        #pragma unroll
        for (int i = 0; i < 4; i++) dst[tid + i * 256] = src[tid + i * 256];
    }

    const float4* k4 = (const float4*)k;
    const size_t gbase = ((size_t)b * 2048 + st * 128) * 256 + dq * 64;   // f4 units
    const int row0 = tid >> 2, colx = tid & 3;
    const int row1 = (tid + 256) >> 2;
    const float4* kg0 = k4 + gbase + (size_t)row0 * 256 + colx;
    const float4* kg1 = k4 + gbase + (size_t)row1 * 256 + colx;
    const unsigned sbase = smem_u32(pipe);
    const unsigned s0off = sbase + (unsigned)(row0 * 5 + colx) * 16u;
    const unsigned s1off = sbase + (unsigned)(row1 * 5 + colx) * 16u;

#define KS_ISSUE(c) do { \
    cpa16(s0off + (unsigned)(((c) % 5) * 640) * 16u, kg0 + (c) * 4); \
    cpa16(s1off + (unsigned)(((c) % 5) * 640) * 16u, kg1 + (c) * 4); \
} while (0)

    #pragma unroll
    for (int c = 0; c < 4; c++) { KS_ISSUE(c); cpa_commit(); }

    ull acc[4][4];   // [row i][h-pair p within hg]
    #pragma unroll
    for (int i = 0; i < 4; i++)
        #pragma unroll
        for (int p = 0; p < 4; p++) acc[i][p] = 0ull;

    const ulonglong2* wq = (const ulonglong2*)ws_s;   // [d][4 x ulonglong2]
    const int kidx0 = r * 5 + dg, kidx1 = (r + 32) * 5 + dg;
    const int kidx2 = (r + 64) * 5 + dg, kidx3 = (r + 96) * 5 + dg;
    const int wbase = hg * 2;

    #pragma unroll
    for (int c = 0; c < 16; c++) {
        cpa_wait<3>();
        __syncthreads();
        if (c + 4 < 16) KS_ISSUE(c + 4);
        cpa_commit();

        const float4* kb = pipe + (c % 5) * 640;       // constant under unroll
        float4 kv0 = kb[kidx0];
        float4 kv1 = kb[kidx1];
        float4 kv2 = kb[kidx2];
        float4 kv3 = kb[kidx3];
        #pragma unroll
        for (int dl = 0; dl < 4; dl++) {
            const int dd = c * 16 + dg * 4 + dl;       // constant offsets
            ulonglong2 w0 = wq[dd * 4 + wbase];
            ulonglong2 w1 = wq[dd * 4 + wbase + 1];
            float kf0 = ((const float*)&kv0)[dl];
            float kf1 = ((const float*)&kv1)[dl];
            float kf2 = ((const float*)&kv2)[dl];
            float kf3 = ((const float*)&kv3)[dl];
            ull kk0 = pk2(kf0, kf0), kk1 = pk2(kf1, kf1);
            ull kk2 = pk2(kf2, kf2), kk3 = pk2(kf3, kf3);
            acc[0][0] = fma2(kk0, w0.x, acc[0][0]); acc[0][1] = fma2(kk0, w0.y, acc[0][1]);
            acc[0][2] = fma2(kk0, w1.x, acc[0][2]); acc[0][3] = fma2(kk0, w1.y, acc[0][3]);
            acc[1][0] = fma2(kk1, w0.x, acc[1][0]); acc[1][1] = fma2(kk1, w0.y, acc[1][1]);
            acc[1][2] = fma2(kk1, w1.x, acc[1][2]); acc[1][3] = fma2(kk1, w1.y, acc[1][3]);
            acc[2][0] = fma2(kk2, w0.x, acc[2][0]); acc[2][1] = fma2(kk2, w0.y, acc[2][1]);
            acc[2][2] = fma2(kk2, w1.x, acc[2][2]); acc[2][3] = fma2(kk2, w1.y, acc[2][3]);
            acc[3][0] = fma2(kk3, w0.x, acc[3][0]); acc[3][1] = fma2(kk3, w0.y, acc[3][1]);
            acc[3][2] = fma2(kk3, w1.x, acc[3][2]); acc[3][3] = fma2(kk3, w1.y, acc[3][3]);
        }
    }
#undef KS_ISSUE

    // reduce the 4 dg partials via smem (reuse ring region; stride 9 pad)
    __syncthreads();
    ull* sred = (ull*)(sm + 4096);        // 4 * 1152 ull = 36864 B <= 50 KB
    #pragma unroll
    for (int i = 0; i < 4; i++)
        #pragma unroll
        for (int p = 0; p < 4; p++)
            sred[dg * 1152 + (r + 32 * i) * 9 + hg * 4 + p] = acc[i][p];
    __syncthreads();

    const int row = tid >> 1, pb = (tid & 1) * 4;
    const int s = st * 128 + row;
    float* outp = g_scores_part[dq];
    #pragma unroll
    for (int j = 0; j < 4; j++) {
        int p = pb + j;
        ull t = add2(add2(sred[row * 9 + p],        sred[1152 + row * 9 + p]),
                     add2(sred[2304 + row * 9 + p], sred[3456 + row * 9 + p]));
        float lo, hi; upk2(lo, hi, t);
        outp[(size_t)(b * 16 + 2 * p) * 2048 + s]     = lo;
        outp[(size_t)(b * 16 + 2 * p + 1) * 2048 + s] = hi;
    }
}

// softmax over s per (b,h); sums 4 d-partials; write attn[b][s][h]
__global__ __launch_bounds__(256) void k_softmax() {
    int b = blockIdx.x, h = blockIdx.y, tid = threadIdx.x;
    size_t off = (size_t)(b * 16 + h) * 2048;
    float x[8], m = -1e30f;
    #pragma unroll
    for (int i = 0; i < 8; i++) {
        int s = tid + i * 256;
        float v = g_scores_part[0][off + s] + g_scores_part[1][off + s]
                + g_scores_part[2][off + s] + g_scores_part[3][off + s];
        x[i] = v; m = fmaxf(m, v);
    }
    __shared__ float red[8];
    #pragma unroll
    for (int o = 16; o; o >>= 1) m = fmaxf(m, __shfl_xor_sync(0xffffffffu, m, o));
    if ((tid & 31) == 0) red[tid >> 5] = m;
    __syncthreads();
    float M = red[0];
    #pragma unroll
    for (int i = 1; i < 8; i++) M = fmaxf(M, red[i]);
    __syncthreads();
    float ssum = 0.f;
    #pragma unroll
    for (int i = 0; i < 8; i++) { x[i] = __expf(x[i] - M); ssum += x[i]; }
    #pragma unroll
    for (int o = 16; o; o >>= 1) ssum += __shfl_xor_sync(0xffffffffu, ssum, o);
    if ((tid & 31) == 0) red[tid >> 5] = ssum;
    __syncthreads();
    float T = 0.f;
    #pragma unroll
    for (int i = 0; i < 8; i++) T += red[i];
    float inv = 1.0f / T;
    #pragma unroll
    for (int i = 0; i < 8; i++)
        g_attn[((size_t)b * 2048 + tid + i * 256) * 16 + h] = x[i] * inv;
}

// ---------------- pass 2: stream v -> partial vbar ----------------
// grid (64 b, 2 dh, 16 sq). CTA: 128 s x 512 d x 16 h; 16 stages of 8 s via
// 4-stage cp.async ring (constants under x4 unroll). Thread (hg=tid>>7,
// dt=tid&127): 4 d x 8 heads x 8 s per stage. 67584 B smem, 3 CTAs/SM.
// sq=16 halves per-CTA work -> 2048 CTAs, 4.6 waves (was 2.3: tail fix).
__global__ __launch_bounds__(256, 3) void k_vbar(const float* __restrict__ v) {
    extern __shared__ float vsm[];             // 4 stages x 4224 floats
    const int b = blockIdx.x, dh = blockIdx.y, sq = blockIdx.z;
    const int tid = threadIdx.x;
    const int hg = tid >> 7, dt = tid & 127;
    const size_t sBase = (size_t)b * 2048 + sq * 128;
    const float4* vg = (const float4*)v;
    const float4* ag = (const float4*)g_attn;
    const unsigned smb = smem_u32(vsm);

    const int sl0 = tid >> 7;
    const float4* vg0 = vg + (sBase + sl0) * 256 + dh * 128 + (tid & 127);
    const float4* agp = ag + sBase * 4 + tid;
    const unsigned vs_off = (unsigned)tid * 16u;

#define VB_ISSUE(c, stg) do { \
    unsigned sb = smb + (unsigned)((stg) * 16896); \
    _Pragma("unroll") \
    for (int i2 = 0; i2 < 4; i2++) \
        cpa16(sb + vs_off + (unsigned)i2 * 4096u, \
              vg0 + ((size_t)(c) * 8 + i2 * 2) * 256); \
    if (tid < 32) cpa16(sb + 16384u + (unsigned)tid * 16u, agp + (c) * 32); \
} while (0)

    VB_ISSUE(0, 0); cpa_commit();
    VB_ISSUE(1, 1); cpa_commit();
    VB_ISSUE(2, 2); cpa_commit();

    ull acc[4][4];
    #pragma unroll
    for (int d = 0; d < 4; d++)
        #pragma unroll
        for (int hp = 0; hp < 4; hp++) acc[d][hp] = 0ull;

    const int abase = hg * 8;
    for (int cc = 0; cc < 4; cc++) {
        #pragma unroll
        for (int u = 0; u < 4; u++) {
            const int c = cc * 4 + u;
            cpa_wait<2>();
            __syncthreads();
            if (c + 3 < 16) VB_ISSUE(c + 3, (u + 3) & 3);
            cpa_commit();

            const float* stg = vsm + u * 4224;
            const float4* vb4 = (const float4*)stg + dt;
            const float* ab = stg + 4096 + abase;
            #pragma unroll
            for (int sl = 0; sl < 8; sl++) {
                float4 vv = vb4[sl * 128];
                ulonglong2 a01 = *(const ulonglong2*)(ab + sl * 16);
                ulonglong2 a23 = *(const ulonglong2*)(ab + sl * 16 + 4);
                ull v0 = pk2(vv.x, vv.x), v1 = pk2(vv.y, vv.y);
                ull v2 = pk2(vv.z, vv.z), v3 = pk2(vv.w, vv.w);
                acc[0][0] = fma2(a01.x, v0, acc[0][0]); acc[1][0] = fma2(a01.x, v1, acc[1][0]);
                acc[2][0] = fma2(a01.x, v2, acc[2][0]); acc[3][0] = fma2(a01.x, v3, acc[3][0]);
                acc[0][1] = fma2(a01.y, v0, acc[0][1]); acc[1][1] = fma2(a01.y, v1, acc[1][1]);
                acc[2][1] = fma2(a01.y, v2, acc[2][1]); acc[3][1] = fma2(a01.y, v3, acc[3][1]);
                acc[0][2] = fma2(a23.x, v0, acc[0][2]); acc[1][2] = fma2(a23.x, v1, acc[1][2]);
                acc[2][2] = fma2(a23.x, v2, acc[2][2]); acc[3][2] = fma2(a23.x, v3, acc[3][2]);
                acc[0][3] = fma2(a23.y, v0, acc[0][3]); acc[1][3] = fma2(a23.y, v1, acc[1][3]);
                acc[2][3] = fma2(a23.y, v2, acc[2][3]); acc[3][3] = fma2(a23.y, v3, acc[3][3]);
            }
        }
    }
#undef VB_ISSUE

    float* outp = g_vbar_part[sq] + (size_t)b * 16384;
    const int d0 = dh * 512 + dt * 4;
    #pragma unroll
    for (int hp = 0; hp < 4; hp++) {
        float lo0, hi0, lo1, hi1, lo2, hi2, lo3, hi3;
        upk2(lo0, hi0, acc[0][hp]); upk2(lo1, hi1, acc[1][hp]);
        upk2(lo2, hi2, acc[2][hp]); upk2(lo3, hi3, acc[3][hp]);
        float4 e; e.x = lo0; e.y = lo1; e.z = lo2; e.w = lo3;
        float4 o; o.x = hi0; o.y = hi1; o.z = hi2; o.w = hi3;
        int h0 = hg * 8 + 2 * hp;
        *(float4*)&outp[(size_t)h0 * 1024 + d0]       = e;
        *(float4*)&outp[(size_t)(h0 + 1) * 1024 + d0] = o;
    }
}

__global__ __launch_bounds__(256) void k_relu(float* __restrict__ out) {
    int i = blockIdx.x * 256 + threadIdx.x;
    out[i] = fmaxf(g_outpre[i], 0.0f);
}

extern "C" void kernel_launch(void* const* d_in, const int* in_sizes, int n_in,
                              void* d_out, int out_size) {
    const float* q  = (const float*)d_in[0];
    const float* k  = (const float*)d_in[1];
    const float* v  = (const float*)d_in[2];
    const float* Wq = (const float*)d_in[3];
    const float* bq = (const float*)d_in[4];
    const float* Wk = (const float*)d_in[5];
    // d_in[6] = bk — cancels in softmax
    const float* Wv = (const float*)d_in[7];
    const float* bv = (const float*)d_in[8];
    const float* Wo = (const float*)d_in[9];
    const float* bo = (const float*)d_in[10];

    const int smem_scores = 4096 * 4 + 5 * 640 * 16;   // 67584
    const int smem_vbar   = 4 * 16896;                 // 67584
    static bool attr_done = false;
    if (!attr_done) {
        cudaFuncSetAttribute(k_scores, cudaFuncAttributeMaxDynamicSharedMemorySize, smem_scores);
        cudaFuncSetAttribute(k_vbar,   cudaFuncAttributeMaxDynamicSharedMemorySize, smem_vbar);
        attr_done = true;
    }

    k_init<<<256, 256>>>(bq, bv, bo);
    gemm_ksplit<<<dim3(16, 16), 256>>>(q, Wq, 0);
    k_ws<<<dim3(16, 8, 4), 256>>>(Wk);
    k_scores<<<dim3(64, 16, 4), 256, smem_scores>>>(k);
    k_softmax<<<dim3(64, 16), 256>>>();
    k_vbar<<<dim3(64, 2, 16), 256, smem_vbar>>>(v);
    gemm_ksplit<<<dim3(16, 16), 256>>>(nullptr, Wv, 1);
    gemm_ksplit<<<dim3(16, 16), 256>>>(nullptr, Wo, 2);
    k_relu<<<256, 256>>>((float*)d_out);
}